// round 1
// baseline (speedup 1.0000x reference)
#include <cuda_runtime.h>
#include <math.h>

#define Bb 2
#define Nn 1024
#define FS 1024
#define FZ 64
#define Hh 16
#define Cc 64
#define HC (Hh*Cc)          // 1024
#define Mrows (Bb*Nn)       // 2048

// ---------------- scratch (static device globals; no allocations) ----------
__device__ float g_q[Bb*Nn*HC];                 // 2M floats
__device__ float g_k[Bb*Nn*HC];
__device__ float g_v[Bb*Nn*HC];
__device__ float g_bias[(size_t)Bb*Hh*Nn*Nn];   // 32M floats = 128MB

// ---------------- QKV projection: out = s @ W  (M=2048,K=1024,N=1024) ------
// blockIdx.z selects which of Wq/Wk/Wv -> g_q/g_k/g_v
#define BM 64
#define BN 64
#define BK 16
__global__ void qkv_gemm_kernel(const float* __restrict__ S,
                                const float* __restrict__ Wq,
                                const float* __restrict__ Wk,
                                const float* __restrict__ Wv)
{
    const float* W = (blockIdx.z == 0) ? Wq : (blockIdx.z == 1) ? Wk : Wv;
    float* O       = (blockIdx.z == 0) ? g_q : (blockIdx.z == 1) ? g_k : g_v;

    __shared__ float As[BK][BM];
    __shared__ float Bs[BK][BN];

    const int tid  = threadIdx.x;          // 0..255
    const int row0 = blockIdx.y * BM;
    const int col0 = blockIdx.x * BN;

    const int tr = tid >> 4;               // 0..15
    const int tc = tid & 15;               // 0..15

    // A tile load mapping: one float4 per thread
    const int arow = tid >> 2;             // 0..63
    const int acol = (tid & 3) * 4;        // 0,4,8,12
    // B tile load mapping: one float4 per thread
    const int brow = tid >> 4;             // 0..15
    const int bcol = (tid & 15) * 4;       // 0..60

    float acc[4][4];
#pragma unroll
    for (int i = 0; i < 4; i++)
#pragma unroll
        for (int j = 0; j < 4; j++) acc[i][j] = 0.f;

    for (int k0 = 0; k0 < FS; k0 += BK) {
        float4 a = *(const float4*)&S[(size_t)(row0 + arow) * FS + k0 + acol];
        As[acol + 0][arow] = a.x;
        As[acol + 1][arow] = a.y;
        As[acol + 2][arow] = a.z;
        As[acol + 3][arow] = a.w;
        float4 b = *(const float4*)&W[(size_t)(k0 + brow) * HC + col0 + bcol];
        *(float4*)&Bs[brow][bcol] = b;
        __syncthreads();

#pragma unroll
        for (int k = 0; k < BK; k++) {
            float ar[4], br[4];
#pragma unroll
            for (int i = 0; i < 4; i++) ar[i] = As[k][tr * 4 + i];
#pragma unroll
            for (int j = 0; j < 4; j++) br[j] = Bs[k][tc * 4 + j];
#pragma unroll
            for (int i = 0; i < 4; i++)
#pragma unroll
                for (int j = 0; j < 4; j++) acc[i][j] += ar[i] * br[j];
        }
        __syncthreads();
    }

#pragma unroll
    for (int i = 0; i < 4; i++) {
        float4 o4 = make_float4(acc[i][0], acc[i][1], acc[i][2], acc[i][3]);
        *(float4*)&O[(size_t)(row0 + tr * 4 + i) * HC + col0 + tc * 4] = o4;
    }
}

// ---------------- RoPE on g_q and g_k, in place ----------------------------
__global__ void rope_kernel(const int* __restrict__ positions)
{
    int idx = blockIdx.x * blockDim.x + threadIdx.x;   // B*N*H*32 = 1,048,576
    int i = idx & 31;
    int h = (idx >> 5) & 15;
    int n = (idx >> 9) & 1023;
    int b = idx >> 19;

    int pos = positions[b * Nn + n];
    // timescale = 10000^(i/32); computed in double for safety, cost negligible
    double ts  = exp((double)i * (9.210340371976184 / 32.0)); // ln(10000)
    float ang  = (float)((double)pos / ts);
    float sn, cs;
    sincosf(ang, &sn, &cs);

    size_t base = (size_t)(b * Nn + n) * HC + h * Cc;
    float q1 = g_q[base + i], q2 = g_q[base + 32 + i];
    g_q[base + i]      = q1 * cs - q2 * sn;
    g_q[base + 32 + i] = q2 * cs + q1 * sn;
    float k1 = g_k[base + i], k2 = g_k[base + 32 + i];
    g_k[base + i]      = k1 * cs - k2 * sn;
    g_k[base + 32 + i] = k2 * cs + k1 * sn;
}

// ---------------- bias[b,h,q,k] = sum_f pair[b,q,k,f] * Wb[f,h] ------------
// grid: (N/256, N, B), block 256. One thread per (b,q,k).
__global__ void bias_kernel(const float* __restrict__ pair,
                            const float* __restrict__ Wb)
{
    __shared__ float Wb_s[FZ][Hh];   // 64 x 16
    for (int i = threadIdx.x; i < FZ * Hh; i += 256)
        Wb_s[i >> 4][i & 15] = Wb[i];
    __syncthreads();

    const int k = blockIdx.x * 256 + threadIdx.x;
    const int q = blockIdx.y;
    const int b = blockIdx.z;

    const float4* pp = (const float4*)&pair[((size_t)(b * Nn + q) * Nn + k) * FZ];

    float acc[Hh];
#pragma unroll
    for (int h = 0; h < Hh; h++) acc[h] = 0.f;

#pragma unroll
    for (int f4 = 0; f4 < FZ / 4; f4++) {
        float4 p = pp[f4];
#pragma unroll
        for (int h = 0; h < Hh; h++) {
            acc[h] += p.x * Wb_s[4 * f4 + 0][h];
            acc[h] += p.y * Wb_s[4 * f4 + 1][h];
            acc[h] += p.z * Wb_s[4 * f4 + 2][h];
            acc[h] += p.w * Wb_s[4 * f4 + 3][h];
        }
    }
#pragma unroll
    for (int h = 0; h < Hh; h++)
        g_bias[((size_t)(b * Hh + h) * Nn + q) * Nn + k] = acc[h];
}

// ---------------- flash attention ------------------------------------------
// grid: (N/64 q-tiles, H, B), block 64 threads (one thread per q row).
// K and V share one smem buffer (loaded sequentially) to stay under 48KB.
__global__ void attn_kernel(const int* __restrict__ seg, float* __restrict__ out)
{
    __shared__ float kv_s[64][64];   // K tile, then V tile
    __shared__ float s_s[64][64];    // s_s[j][tid]: logits, bank-conflict free
    __shared__ int   seg_s[64];

    const int tid = threadIdx.x;     // 0..63
    const int qt  = blockIdx.x;
    const int h   = blockIdx.y;
    const int b   = blockIdx.z;
    const int row = qt * 64 + tid;

    const float sm_scale = 0.125f;   // 1/sqrt(64)

    // load my q row into registers
    float q_reg[64];
    {
        const float4* qp = (const float4*)&g_q[(size_t)(b * Nn + row) * HC + h * Cc];
#pragma unroll
        for (int i = 0; i < 16; i++) {
            float4 t = qp[i];
            q_reg[4 * i + 0] = t.x; q_reg[4 * i + 1] = t.y;
            q_reg[4 * i + 2] = t.z; q_reg[4 * i + 3] = t.w;
        }
    }
    const int my_seg = seg[b * Nn + row];

    float o_acc[64];
#pragma unroll
    for (int c = 0; c < 64; c++) o_acc[c] = 0.f;
    float m_run = -INFINITY;
    float l_run = 0.f;

    const float* bias_base = &g_bias[((size_t)(b * Hh + h) * Nn + row) * Nn];

    for (int kt = 0; kt <= qt; kt++) {
        // ---- load K tile (+ segment ids) ----
        __syncthreads();   // previous iteration done with kv_s
        {
            const float* kbase = &g_k[(size_t)(b * Nn + kt * 64) * HC + h * Cc];
#pragma unroll
            for (int t = tid; t < 64 * 16; t += 64) {
                int r  = t >> 4;
                int c4 = (t & 15) * 4;
                *(float4*)&kv_s[r][c4] = *(const float4*)&kbase[(size_t)r * HC + c4];
            }
            if (tid < 64) seg_s[tid] = seg[b * Nn + kt * 64 + tid];
        }
        __syncthreads();

        // ---- S = q . k^T * scale + bias, masked ----
        float m_t = -INFINITY;
        const float* bias_row = bias_base + kt * 64;
        for (int j4 = 0; j4 < 64; j4 += 4) {
            float4 bs4 = *(const float4*)(bias_row + j4);
            float bb[4] = { bs4.x, bs4.y, bs4.z, bs4.w };
#pragma unroll
            for (int jj = 0; jj < 4; jj++) {
                int j = j4 + jj;
                const float4* kr = (const float4*)kv_s[j];
                float a0 = 0.f, a1 = 0.f, a2 = 0.f, a3 = 0.f;
#pragma unroll
                for (int c4 = 0; c4 < 16; c4++) {
                    float4 kk4 = kr[c4];
                    a0 += q_reg[4 * c4 + 0] * kk4.x;
                    a1 += q_reg[4 * c4 + 1] * kk4.y;
                    a2 += q_reg[4 * c4 + 2] * kk4.z;
                    a3 += q_reg[4 * c4 + 3] * kk4.w;
                }
                float dot = (a0 + a1) + (a2 + a3);
                int kk = kt * 64 + j;
                bool ok = (kk <= row) && (seg_s[j] == my_seg);
                float sv = ok ? fmaf(dot, sm_scale, bb[jj]) : -INFINITY;
                s_s[j][tid] = sv;
                m_t = fmaxf(m_t, sv);
            }
        }

        // ---- load V tile into the same buffer ----
        __syncthreads();   // all threads done reading K
        {
            const float* vbase = &g_v[(size_t)(b * Nn + kt * 64) * HC + h * Cc];
#pragma unroll
            for (int t = tid; t < 64 * 16; t += 64) {
                int r  = t >> 4;
                int c4 = (t & 15) * 4;
                *(float4*)&kv_s[r][c4] = *(const float4*)&vbase[(size_t)r * HC + c4];
            }
        }
        __syncthreads();

        // ---- online softmax + P.V (per-thread, may skip if tile fully masked)
        if (m_t > -INFINITY) {
            float m_new = fmaxf(m_run, m_t);
            float alpha = __expf(m_run - m_new);   // 0 when m_run == -inf
            l_run *= alpha;
#pragma unroll
            for (int c = 0; c < 64; c++) o_acc[c] *= alpha;

            for (int j4 = 0; j4 < 64; j4 += 4) {
#pragma unroll
                for (int jj = 0; jj < 4; jj++) {
                    int j = j4 + jj;
                    float p = __expf(s_s[j][tid] - m_new);
                    l_run += p;
                    const float4* vr = (const float4*)kv_s[j];
#pragma unroll
                    for (int c4 = 0; c4 < 16; c4++) {
                        float4 v4 = vr[c4];
                        o_acc[4 * c4 + 0] += p * v4.x;
                        o_acc[4 * c4 + 1] += p * v4.y;
                        o_acc[4 * c4 + 2] += p * v4.z;
                        o_acc[4 * c4 + 3] += p * v4.w;
                    }
                }
            }
            m_run = m_new;
        }
    }

    // ---- write out[b, q, h, c] ----
    float inv = 1.f / l_run;
    float* op = &out[(size_t)(b * Nn + row) * HC + h * Cc];
#pragma unroll
    for (int c4 = 0; c4 < 16; c4++) {
        float4 o4 = make_float4(o_acc[4 * c4 + 0] * inv, o_acc[4 * c4 + 1] * inv,
                                o_acc[4 * c4 + 2] * inv, o_acc[4 * c4 + 3] * inv);
        *(float4*)&op[4 * c4] = o4;
    }
}

// ---------------------------------------------------------------------------
extern "C" void kernel_launch(void* const* d_in, const int* in_sizes, int n_in,
                              void* d_out, int out_size)
{
    const float* s    = (const float*)d_in[0];
    const float* pair = (const float*)d_in[1];
    const int*   seg  = (const int*)d_in[2];
    const int*   pos  = (const int*)d_in[3];
    const float* Wq   = (const float*)d_in[4];
    const float* Wk   = (const float*)d_in[5];
    const float* Wv   = (const float*)d_in[6];
    const float* Wb   = (const float*)d_in[7];
    float* out = (float*)d_out;

    // QKV projections (z selects q/k/v)
    qkv_gemm_kernel<<<dim3(HC / BN, Mrows / BM, 3), 256>>>(s, Wq, Wk, Wv);
    // RoPE in place on q,k
    rope_kernel<<<(Bb * Nn * Hh * 32) / 256, 256>>>(pos);
    // pair bias precompute (independent of qkv, same stream is fine)
    bias_kernel<<<dim3(Nn / 256, Nn, Bb), 256>>>(pair, Wb);
    // flash attention
    attn_kernel<<<dim3(Nn / 64, Hh, Bb), 64>>>(seg, out);
}

// round 3
// speedup vs baseline: 1.3684x; 1.3684x over previous
#include <cuda_runtime.h>
#include <math.h>

#define Bb 2
#define Nn 1024
#define FS 1024
#define FZ 64
#define Hh 16
#define Cc 64
#define HC (Hh*Cc)          // 1024
#define Mrows (Bb*Nn)       // 2048

// ---------------- scratch (static device globals; no allocations) ----------
__device__ float g_q[Bb*Nn*HC];
__device__ float g_k[Bb*Nn*HC];
__device__ float g_v[Bb*Nn*HC];
__device__ float g_bias[(size_t)Bb*Hh*Nn*Nn];   // 128MB

// ---------------- QKV projection: out = s @ W  (M=2048,K=1024,N=1024 x3) ---
// BM=128, BN=64, BK=8, 256 threads, 8x4 micro-tile.
__global__ __launch_bounds__(256) void qkv_gemm_kernel(
    const float* __restrict__ S,
    const float* __restrict__ Wq,
    const float* __restrict__ Wk,
    const float* __restrict__ Wv)
{
    const float* W = (blockIdx.z == 0) ? Wq : (blockIdx.z == 1) ? Wk : Wv;
    float* O       = (blockIdx.z == 0) ? g_q : (blockIdx.z == 1) ? g_k : g_v;

    __shared__ float As[8][132];   // [k][m], transposed
    __shared__ float Bs[8][68];    // [k][n]

    const int tid  = threadIdx.x;
    const int row0 = blockIdx.y * 128;
    const int col0 = blockIdx.x * 64;

    const int tr = tid >> 4;       // 0..15
    const int tc = tid & 15;       // 0..15

    const int arow = tid >> 1;           // 0..127
    const int acol = (tid & 1) * 4;      // 0 or 4

    float acc[2][4][4];
#pragma unroll
    for (int h = 0; h < 2; h++)
#pragma unroll
        for (int i = 0; i < 4; i++)
#pragma unroll
            for (int j = 0; j < 4; j++) acc[h][i][j] = 0.f;

    for (int k0 = 0; k0 < FS; k0 += 8) {
        // load A tile (transpose)
        float4 a = *(const float4*)&S[(size_t)(row0 + arow) * FS + k0 + acol];
        As[acol + 0][arow] = a.x;
        As[acol + 1][arow] = a.y;
        As[acol + 2][arow] = a.z;
        As[acol + 3][arow] = a.w;
        // load B tile (threads 0..127)
        if (tid < 128) {
            int brow = tid >> 4;
            int bcol = (tid & 15) * 4;
            *(float4*)&Bs[brow][bcol] =
                *(const float4*)&W[(size_t)(k0 + brow) * HC + col0 + bcol];
        }
        __syncthreads();

#pragma unroll
        for (int k = 0; k < 8; k++) {
            float4 a0 = *(const float4*)&As[k][tr * 4];
            float4 a1 = *(const float4*)&As[k][64 + tr * 4];
            float4 b0 = *(const float4*)&Bs[k][tc * 4];
            float ar0[4] = { a0.x, a0.y, a0.z, a0.w };
            float ar1[4] = { a1.x, a1.y, a1.z, a1.w };
            float br[4]  = { b0.x, b0.y, b0.z, b0.w };
#pragma unroll
            for (int i = 0; i < 4; i++)
#pragma unroll
                for (int j = 0; j < 4; j++) {
                    acc[0][i][j] = fmaf(ar0[i], br[j], acc[0][i][j]);
                    acc[1][i][j] = fmaf(ar1[i], br[j], acc[1][i][j]);
                }
        }
        __syncthreads();
    }

#pragma unroll
    for (int h = 0; h < 2; h++)
#pragma unroll
        for (int i = 0; i < 4; i++) {
            int row = row0 + h * 64 + tr * 4 + i;
            float4 o4 = make_float4(acc[h][i][0], acc[h][i][1],
                                    acc[h][i][2], acc[h][i][3]);
            *(float4*)&O[(size_t)row * HC + col0 + tc * 4] = o4;
        }
}

// ---------------- RoPE on g_q and g_k, in place ----------------------------
__global__ void rope_kernel(const int* __restrict__ positions)
{
    int idx = blockIdx.x * blockDim.x + threadIdx.x;
    int i = idx & 31;
    int h = (idx >> 5) & 15;
    int n = (idx >> 9) & 1023;
    int b = idx >> 19;

    int pos = positions[b * Nn + n];
    double ts  = exp((double)i * (9.210340371976184 / 32.0));
    float ang  = (float)((double)pos / ts);
    float sn, cs;
    sincosf(ang, &sn, &cs);

    size_t base = (size_t)(b * Nn + n) * HC + h * Cc;
    float q1 = g_q[base + i], q2 = g_q[base + 32 + i];
    g_q[base + i]      = q1 * cs - q2 * sn;
    g_q[base + 32 + i] = q2 * cs + q1 * sn;
    float k1 = g_k[base + i], k2 = g_k[base + 32 + i];
    g_k[base + i]      = k1 * cs - k2 * sn;
    g_k[base + 32 + i] = k2 * cs + k1 * sn;
}

// ---------------- bias[b,h,q,k] = sum_f pair[b,q,k,f] * Wb[f,h] ------------
__global__ void bias_kernel(const float* __restrict__ pair,
                            const float* __restrict__ Wb)
{
    __shared__ float Wb_s[FZ][Hh];
    for (int i = threadIdx.x; i < FZ * Hh; i += 256)
        Wb_s[i >> 4][i & 15] = Wb[i];
    __syncthreads();

    const int k = blockIdx.x * 256 + threadIdx.x;
    const int q = blockIdx.y;
    const int b = blockIdx.z;

    const float4* pp = (const float4*)&pair[((size_t)(b * Nn + q) * Nn + k) * FZ];

    float acc[Hh];
#pragma unroll
    for (int h = 0; h < Hh; h++) acc[h] = 0.f;

#pragma unroll
    for (int f4 = 0; f4 < FZ / 4; f4++) {
        float4 p = pp[f4];
#pragma unroll
        for (int h = 0; h < Hh; h++) {
            acc[h] += p.x * Wb_s[4 * f4 + 0][h];
            acc[h] += p.y * Wb_s[4 * f4 + 1][h];
            acc[h] += p.z * Wb_s[4 * f4 + 2][h];
            acc[h] += p.w * Wb_s[4 * f4 + 3][h];
        }
    }
#pragma unroll
    for (int h = 0; h < Hh; h++)
        g_bias[((size_t)(b * Hh + h) * Nn + q) * Nn + k] = acc[h];
}

// ---------------- flash attention (256 threads, 4x4 register tiles) --------
// Thread (tr,tc): q rows qt*64 + tr*4 + i, k cols (within tile) tc*4 + j.
__global__ __launch_bounds__(256) void attn_kernel(const int* __restrict__ seg,
                                                   float* __restrict__ out)
{
    __shared__ float Qs[64][68];    // q tile [row][c]
    __shared__ float Ps[64][68];    // probs  [row][j]
    __shared__ float KVc[16][68];   // K chunk [c][key] / V chunk [j][c]
    __shared__ int   seg_s[64];

    const int tid = threadIdx.x;
    const int tr  = tid >> 4;
    const int tc  = tid & 15;
    const int qt  = gridDim.x - 1 - blockIdx.x;   // big tiles first
    const int h   = blockIdx.y;
    const int b   = blockIdx.z;

    const float sm_scale = 0.125f;

    // load Q tile
    {
        int r  = tid >> 2;
        int c0 = (tid & 3) * 16;
        const float* qp = &g_q[(size_t)(b * Nn + qt * 64 + r) * HC + h * Cc + c0];
#pragma unroll
        for (int u = 0; u < 4; u++)
            *(float4*)&Qs[r][c0 + u * 4] = *(const float4*)&qp[u * 4];
    }

    int   my_seg[4];
    float m_run[4], l_run[4];
    float O[4][4];
#pragma unroll
    for (int i = 0; i < 4; i++) {
        my_seg[i] = seg[b * Nn + qt * 64 + tr * 4 + i];
        m_run[i] = -INFINITY;
        l_run[i] = 0.f;
#pragma unroll
        for (int j = 0; j < 4; j++) O[i][j] = 0.f;
    }
    __syncthreads();   // Qs ready

    for (int kt = 0; kt <= qt; kt++) {
        if (tid < 64) seg_s[tid] = seg[b * Nn + kt * 64 + tid];

        float S[4][4];
#pragma unroll
        for (int i = 0; i < 4; i++)
#pragma unroll
            for (int j = 0; j < 4; j++) S[i][j] = 0.f;

        const float* kbase = &g_k[(size_t)(b * Nn + kt * 64) * HC + h * Cc];

        // ---- S = Q . K^T over 4 chunks of 16 dims ----
        for (int c0 = 0; c0 < 64; c0 += 16) {
            {   // load K chunk transposed: KVc[c][key]
                int jj = tid >> 2;
                int cc = (tid & 3) * 4;
                float4 kk = *(const float4*)&kbase[(size_t)jj * HC + c0 + cc];
                KVc[cc + 0][jj] = kk.x;
                KVc[cc + 1][jj] = kk.y;
                KVc[cc + 2][jj] = kk.z;
                KVc[cc + 3][jj] = kk.w;
            }
            __syncthreads();
#pragma unroll
            for (int cc = 0; cc < 16; cc++) {
                float qf[4];
#pragma unroll
                for (int i = 0; i < 4; i++) qf[i] = Qs[tr * 4 + i][c0 + cc];
                float4 kf4 = *(const float4*)&KVc[cc][tc * 4];
                float kf[4] = { kf4.x, kf4.y, kf4.z, kf4.w };
#pragma unroll
                for (int i = 0; i < 4; i++)
#pragma unroll
                    for (int j = 0; j < 4; j++)
                        S[i][j] = fmaf(qf[i], kf[j], S[i][j]);
            }
            __syncthreads();
        }

        // ---- bias + mask + online softmax (branch-free across lanes) ----
        float mx[4];
#pragma unroll
        for (int i = 0; i < 4; i++) {
            int row = qt * 64 + tr * 4 + i;
            float4 bb4 = *(const float4*)&g_bias[
                ((size_t)(b * Hh + h) * Nn + row) * Nn + kt * 64 + tc * 4];
            float bb[4] = { bb4.x, bb4.y, bb4.z, bb4.w };
            mx[i] = -INFINITY;
#pragma unroll
            for (int j = 0; j < 4; j++) {
                int key = kt * 64 + tc * 4 + j;
                bool ok = (key <= row) && (seg_s[tc * 4 + j] == my_seg[i]);
                S[i][j] = ok ? fmaf(S[i][j], sm_scale, bb[j]) : -INFINITY;
                mx[i] = fmaxf(mx[i], S[i][j]);
            }
        }
        // reduce row max over the 16 lanes sharing each row
#pragma unroll
        for (int s = 8; s >= 1; s >>= 1)
#pragma unroll
            for (int i = 0; i < 4; i++)
                mx[i] = fmaxf(mx[i], __shfl_xor_sync(0xffffffffu, mx[i], s, 16));

#pragma unroll
        for (int i = 0; i < 4; i++) {
            float m_new = fmaxf(m_run[i], mx[i]);
            bool  dead  = (m_new == -INFINITY);
            float m_use = dead ? 0.f : m_new;
            float alpha = __expf(m_run[i] - m_use);  // 0 when m_run=-inf or dead
            float ps = 0.f;
            float p[4];
#pragma unroll
            for (int j = 0; j < 4; j++) {
                p[j] = __expf(S[i][j] - m_use);      // 0 when S=-inf
                ps += p[j];
            }
            // reduce row sum over 16 lanes
#pragma unroll
            for (int s = 8; s >= 1; s >>= 1)
                ps += __shfl_xor_sync(0xffffffffu, ps, s, 16);
            l_run[i] = l_run[i] * alpha + ps;
            m_run[i] = m_new;
#pragma unroll
            for (int j = 0; j < 4; j++) {
                O[i][j] *= alpha;
                Ps[tr * 4 + i][tc * 4 + j] = p[j];
            }
        }

        // ---- O += P . V over 4 chunks of 16 keys ----
        const float* vbase = &g_v[(size_t)(b * Nn + kt * 64) * HC + h * Cc];
        for (int j0 = 0; j0 < 64; j0 += 16) {
            __syncthreads();   // KVc free (and first iter: Ps visible after this)
            {
                int jj = tid >> 4;
                int c  = (tid & 15) * 4;
                *(float4*)&KVc[jj][c] =
                    *(const float4*)&vbase[(size_t)(j0 + jj) * HC + c];
            }
            __syncthreads();
#pragma unroll
            for (int jj = 0; jj < 16; jj++) {
                float pf[4];
#pragma unroll
                for (int i = 0; i < 4; i++) pf[i] = Ps[tr * 4 + i][j0 + jj];
                float4 vf4 = *(const float4*)&KVc[jj][tc * 4];
                float vf[4] = { vf4.x, vf4.y, vf4.z, vf4.w };
#pragma unroll
                for (int i = 0; i < 4; i++)
#pragma unroll
                    for (int j = 0; j < 4; j++)
                        O[i][j] = fmaf(pf[i], vf[j], O[i][j]);
            }
        }
        __syncthreads();   // KVc + Ps free before next kt
    }

    // ---- write out[b, row, h, c] ----
#pragma unroll
    for (int i = 0; i < 4; i++) {
        int row = qt * 64 + tr * 4 + i;
        float inv = 1.f / l_run[i];
        float4 o4 = make_float4(O[i][0] * inv, O[i][1] * inv,
                                O[i][2] * inv, O[i][3] * inv);
        *(float4*)&out[(size_t)(b * Nn + row) * HC + h * Cc + tc * 4] = o4;
    }
}

// ---------------------------------------------------------------------------
extern "C" void kernel_launch(void* const* d_in, const int* in_sizes, int n_in,
                              void* d_out, int out_size)
{
    const float* s    = (const float*)d_in[0];
    const float* pair = (const float*)d_in[1];
    const int*   seg  = (const int*)d_in[2];
    const int*   pos  = (const int*)d_in[3];
    const float* Wq   = (const float*)d_in[4];
    const float* Wk   = (const float*)d_in[5];
    const float* Wv   = (const float*)d_in[6];
    const float* Wb   = (const float*)d_in[7];
    float* out = (float*)d_out;

    qkv_gemm_kernel<<<dim3(HC / 64, Mrows / 128, 3), 256>>>(s, Wq, Wk, Wv);
    rope_kernel<<<(Bb * Nn * Hh * 32) / 256, 256>>>(pos);
    bias_kernel<<<dim3(Nn / 256, Nn, Bb), 256>>>(pair, Wb);
    attn_kernel<<<dim3(Nn / 64, Hh, Bb), 256>>>(seg, out);
}

// round 6
// speedup vs baseline: 2.0039x; 1.4644x over previous
#include <cuda_runtime.h>
#include <cuda_fp16.h>
#include <math.h>
#include <stdint.h>

#define Bb 2
#define Nn 1024
#define FS 1024
#define FZ 64
#define Hh 16
#define Cc 64
#define HC (Hh*Cc)          // 1024
#define Mrows (Bb*Nn)       // 2048

// ---------------- scratch (static device globals; no allocations) ----------
__device__ float g_q[Bb*Nn*HC];
__device__ float g_k[Bb*Nn*HC];
__device__ float g_v[Bb*Nn*HC];
__device__ float g_bias[(size_t)Bb*Hh*Nn*Nn];   // 128MB

// fp16 copies for tensor-core GEMM
__device__ __half g_sh[(size_t)Mrows*FS];        // [m][k]
__device__ __half g_wh[(size_t)3*HC*FS];         // [mat][n][k]  (W transposed)

// ======================= helpers ===========================================
static __device__ __forceinline__ uint32_t smem_u32(const void* p) {
    uint32_t a;
    asm("{ .reg .u64 t; cvta.to.shared.u64 t, %1; cvt.u32.u64 %0, t; }"
        : "=r"(a) : "l"(p));
    return a;
}
static __device__ __forceinline__ void cp16(uint32_t dst, const void* src) {
    asm volatile("cp.async.cg.shared.global [%0], [%1], 16;"
                 :: "r"(dst), "l"(src) : "memory");
}
static __device__ __forceinline__ void cp_commit() {
    asm volatile("cp.async.commit_group;" ::: "memory");
}

#define MMA16816(d, a, b0v, b1v)                                              \
    asm volatile("mma.sync.aligned.m16n8k16.row.col.f32.f16.f16.f32 "         \
                 "{%0,%1,%2,%3}, {%4,%5,%6,%7}, {%8,%9}, {%0,%1,%2,%3};"      \
                 : "+f"((d)[0]), "+f"((d)[1]), "+f"((d)[2]), "+f"((d)[3])     \
                 : "r"((a)[0]), "r"((a)[1]), "r"((a)[2]), "r"((a)[3]),        \
                   "r"(b0v), "r"(b1v))

// ---------------- conversion kernels ---------------------------------------
__global__ void conv_s_kernel(const float* __restrict__ s) {
    int i = blockIdx.x * 256 + threadIdx.x;
    g_sh[i] = __float2half(s[i]);
}

// transpose + convert: g_wh[mat][n][k] = W_mat[k][n]
__global__ void conv_w_kernel(const float* __restrict__ Wq,
                              const float* __restrict__ Wk,
                              const float* __restrict__ Wv) {
    __shared__ float t[32][33];
    const float* W = (blockIdx.z == 0) ? Wq : (blockIdx.z == 1) ? Wk : Wv;
    int n0 = blockIdx.x * 32;
    int k0 = blockIdx.y * 32;
    int tx = threadIdx.x, ty = threadIdx.y;
#pragma unroll
    for (int i = 0; i < 32; i += 8)
        t[ty + i][tx] = W[(size_t)(k0 + ty + i) * HC + n0 + tx];
    __syncthreads();
#pragma unroll
    for (int i = 0; i < 32; i += 8) {
        size_t idx = ((size_t)(blockIdx.z * HC + n0 + ty + i)) * FS + k0 + tx;
        g_wh[idx] = __float2half(t[tx][ty + i]);
    }
}

// ---------------- QKV projection via mma.sync (HMMA) ------------------------
// Block: 128x128 tile, K in 32 chunks of 32, cp.async double buffer.
// 8 warps in 4(m) x 2(n); warp tile 32x64 = 2x8 m16n8k16 fragments.
#define PAD 40   // 32 k elems + 8 pad (conflict-free fragment LDS)

__global__ __launch_bounds__(256) void qkv_mma_kernel()
{
    __shared__ __half As[2][128 * PAD];
    __shared__ __half Bs[2][128 * PAD];

    const int tid  = threadIdx.x;
    const int col0 = blockIdx.x * 128;
    const int row0 = blockIdx.y * 128;
    const int mat  = blockIdx.z;

    float* O = (mat == 0) ? g_q : (mat == 1) ? g_k : g_v;
    const __half* Ag = g_sh + (size_t)row0 * FS;
    const __half* Bg = g_wh + (size_t)(mat * HC + col0) * FS;

    const uint32_t aS = smem_u32(As);
    const uint32_t bS = smem_u32(Bs);

    const int r  = tid >> 1;           // 0..127
    const int pp = (tid & 1) * 16;     // 0 or 16 (elems)

    const int w    = tid >> 5;
    const int lane = tid & 31;
    const int gid  = lane >> 2;
    const int tig  = lane & 3;
    const int wm   = w & 3;            // 0..3  -> rows wm*32
    const int wn   = w >> 2;           // 0..1  -> cols wn*64

    float acc[2][8][4];
#pragma unroll
    for (int mf = 0; mf < 2; mf++)
#pragma unroll
        for (int nf = 0; nf < 8; nf++)
#pragma unroll
            for (int i = 0; i < 4; i++) acc[mf][nf][i] = 0.f;

    // issue cp.async for chunk c into buffer buf
    auto issue = [&](int c, int buf) {
        const __half* as = Ag + (size_t)r * FS + c * 32 + pp;
        const __half* bs = Bg + (size_t)r * FS + c * 32 + pp;
        uint32_t ad = aS + (uint32_t)(buf * 128 * PAD + r * PAD + pp) * 2;
        uint32_t bd = bS + (uint32_t)(buf * 128 * PAD + r * PAD + pp) * 2;
        cp16(ad,      as);
        cp16(ad + 16, as + 8);
        cp16(bd,      bs);
        cp16(bd + 16, bs + 8);
    };

    issue(0, 0);
    cp_commit();

#pragma unroll 1
    for (int c = 0; c < 32; ++c) {
        if (c + 1 < 32) {
            issue(c + 1, (c + 1) & 1);
            cp_commit();
            asm volatile("cp.async.wait_group 1;" ::: "memory");
        } else {
            asm volatile("cp.async.wait_group 0;" ::: "memory");
        }
        __syncthreads();

        const __half* Abuf = As[c & 1];
        const __half* Bbuf = Bs[c & 1];

#pragma unroll
        for (int kk = 0; kk < 32; kk += 16) {
            uint32_t a[2][4];
#pragma unroll
            for (int mf = 0; mf < 2; ++mf) {
                const __half* p0 = Abuf + (wm * 32 + mf * 16 + gid) * PAD + kk + 2 * tig;
                a[mf][0] = *(const uint32_t*)p0;
                a[mf][1] = *(const uint32_t*)(p0 + 8 * PAD);
                a[mf][2] = *(const uint32_t*)(p0 + 8);
                a[mf][3] = *(const uint32_t*)(p0 + 8 * PAD + 8);
            }
#pragma unroll
            for (int nf = 0; nf < 8; ++nf) {
                const __half* q0 = Bbuf + (wn * 64 + nf * 8 + gid) * PAD + kk + 2 * tig;
                uint32_t b0 = *(const uint32_t*)q0;
                uint32_t b1 = *(const uint32_t*)(q0 + 8);
                MMA16816(acc[0][nf], a[0], b0, b1);
                MMA16816(acc[1][nf], a[1], b0, b1);
            }
        }
        __syncthreads();
    }

    // epilogue
#pragma unroll
    for (int mf = 0; mf < 2; ++mf)
#pragma unroll
        for (int nf = 0; nf < 8; ++nf) {
            int row = row0 + wm * 32 + mf * 16 + gid;
            int col = col0 + wn * 64 + nf * 8 + 2 * tig;
            float* d0 = O + (size_t)row * HC + col;
            *(float2*)d0            = make_float2(acc[mf][nf][0], acc[mf][nf][1]);
            *(float2*)(d0 + 8 * HC) = make_float2(acc[mf][nf][2], acc[mf][nf][3]);
        }
}

// ---------------- RoPE on g_q and g_k, in place ----------------------------
__global__ void rope_kernel(const int* __restrict__ positions)
{
    int idx = blockIdx.x * blockDim.x + threadIdx.x;
    int i = idx & 31;
    int h = (idx >> 5) & 15;
    int n = (idx >> 9) & 1023;
    int b = idx >> 19;

    int pos = positions[b * Nn + n];
    double ts  = exp((double)i * (9.210340371976184 / 32.0));
    float ang  = (float)((double)pos / ts);
    float sn, cs;
    sincosf(ang, &sn, &cs);

    size_t base = (size_t)(b * Nn + n) * HC + h * Cc;
    float q1 = g_q[base + i], q2 = g_q[base + 32 + i];
    g_q[base + i]      = q1 * cs - q2 * sn;
    g_q[base + 32 + i] = q2 * cs + q1 * sn;
    float k1 = g_k[base + i], k2 = g_k[base + 32 + i];
    g_k[base + i]      = k1 * cs - k2 * sn;
    g_k[base + 32 + i] = k2 * cs + k1 * sn;
}

// ---------------- bias[b,h,q,k] = sum_f pair[b,q,k,f] * Wb[f,h] ------------
__global__ void bias_kernel(const float* __restrict__ pair,
                            const float* __restrict__ Wb)
{
    __shared__ float Wb_s[FZ][Hh];
    for (int i = threadIdx.x; i < FZ * Hh; i += 256)
        Wb_s[i >> 4][i & 15] = Wb[i];
    __syncthreads();

    const int k = blockIdx.x * 256 + threadIdx.x;
    const int q = blockIdx.y;
    const int b = blockIdx.z;

    const float4* pp = (const float4*)&pair[((size_t)(b * Nn + q) * Nn + k) * FZ];

    float acc[Hh];
#pragma unroll
    for (int h = 0; h < Hh; h++) acc[h] = 0.f;

#pragma unroll
    for (int f4 = 0; f4 < FZ / 4; f4++) {
        float4 p = pp[f4];
#pragma unroll
        for (int h = 0; h < Hh; h++) {
            acc[h] += p.x * Wb_s[4 * f4 + 0][h];
            acc[h] += p.y * Wb_s[4 * f4 + 1][h];
            acc[h] += p.z * Wb_s[4 * f4 + 2][h];
            acc[h] += p.w * Wb_s[4 * f4 + 3][h];
        }
    }
#pragma unroll
    for (int h = 0; h < Hh; h++)
        g_bias[((size_t)(b * Hh + h) * Nn + q) * Nn + k] = acc[h];
}

// ---------------- flash attention (256 threads, 4x4 register tiles) --------
__global__ __launch_bounds__(256) void attn_kernel(const int* __restrict__ seg,
                                                   float* __restrict__ out)
{
    __shared__ float Qs[64][68];
    __shared__ float Ps[64][68];
    __shared__ float KVc[16][68];
    __shared__ int   seg_s[64];

    const int tid = threadIdx.x;
    const int tr  = tid >> 4;
    const int tc  = tid & 15;
    const int qt  = gridDim.x - 1 - blockIdx.x;
    const int h   = blockIdx.y;
    const int b   = blockIdx.z;

    const float sm_scale = 0.125f;

    {
        int r  = tid >> 2;
        int c0 = (tid & 3) * 16;
        const float* qp = &g_q[(size_t)(b * Nn + qt * 64 + r) * HC + h * Cc + c0];
#pragma unroll
        for (int u = 0; u < 4; u++)
            *(float4*)&Qs[r][c0 + u * 4] = *(const float4*)&qp[u * 4];
    }

    int   my_seg[4];
    float m_run[4], l_run[4];
    float O[4][4];
#pragma unroll
    for (int i = 0; i < 4; i++) {
        my_seg[i] = seg[b * Nn + qt * 64 + tr * 4 + i];
        m_run[i] = -INFINITY;
        l_run[i] = 0.f;
#pragma unroll
        for (int j = 0; j < 4; j++) O[i][j] = 0.f;
    }
    __syncthreads();

    for (int kt = 0; kt <= qt; kt++) {
        if (tid < 64) seg_s[tid] = seg[b * Nn + kt * 64 + tid];

        float S[4][4];
#pragma unroll
        for (int i = 0; i < 4; i++)
#pragma unroll
            for (int j = 0; j < 4; j++) S[i][j] = 0.f;

        const float* kbase = &g_k[(size_t)(b * Nn + kt * 64) * HC + h * Cc];

        for (int c0 = 0; c0 < 64; c0 += 16) {
            {
                int jj = tid >> 2;
                int cc = (tid & 3) * 4;
                float4 kk = *(const float4*)&kbase[(size_t)jj * HC + c0 + cc];
                KVc[cc + 0][jj] = kk.x;
                KVc[cc + 1][jj] = kk.y;
                KVc[cc + 2][jj] = kk.z;
                KVc[cc + 3][jj] = kk.w;
            }
            __syncthreads();
#pragma unroll
            for (int cc = 0; cc < 16; cc++) {
                float qf[4];
#pragma unroll
                for (int i = 0; i < 4; i++) qf[i] = Qs[tr * 4 + i][c0 + cc];
                float4 kf4 = *(const float4*)&KVc[cc][tc * 4];
                float kf[4] = { kf4.x, kf4.y, kf4.z, kf4.w };
#pragma unroll
                for (int i = 0; i < 4; i++)
#pragma unroll
                    for (int j = 0; j < 4; j++)
                        S[i][j] = fmaf(qf[i], kf[j], S[i][j]);
            }
            __syncthreads();
        }

        float mx[4];
#pragma unroll
        for (int i = 0; i < 4; i++) {
            int row = qt * 64 + tr * 4 + i;
            float4 bb4 = *(const float4*)&g_bias[
                ((size_t)(b * Hh + h) * Nn + row) * Nn + kt * 64 + tc * 4];
            float bb[4] = { bb4.x, bb4.y, bb4.z, bb4.w };
            mx[i] = -INFINITY;
#pragma unroll
            for (int j = 0; j < 4; j++) {
                int key = kt * 64 + tc * 4 + j;
                bool ok = (key <= row) && (seg_s[tc * 4 + j] == my_seg[i]);
                S[i][j] = ok ? fmaf(S[i][j], sm_scale, bb[j]) : -INFINITY;
                mx[i] = fmaxf(mx[i], S[i][j]);
            }
        }
#pragma unroll
        for (int s = 8; s >= 1; s >>= 1)
#pragma unroll
            for (int i = 0; i < 4; i++)
                mx[i] = fmaxf(mx[i], __shfl_xor_sync(0xffffffffu, mx[i], s, 16));

#pragma unroll
        for (int i = 0; i < 4; i++) {
            float m_new = fmaxf(m_run[i], mx[i]);
            bool  dead  = (m_new == -INFINITY);
            float m_use = dead ? 0.f : m_new;
            float alpha = __expf(m_run[i] - m_use);
            float ps = 0.f;
            float p[4];
#pragma unroll
            for (int j = 0; j < 4; j++) {
                p[j] = __expf(S[i][j] - m_use);
                ps += p[j];
            }
#pragma unroll
            for (int s = 8; s >= 1; s >>= 1)
                ps += __shfl_xor_sync(0xffffffffu, ps, s, 16);
            l_run[i] = l_run[i] * alpha + ps;
            m_run[i] = m_new;
#pragma unroll
            for (int j = 0; j < 4; j++) {
                O[i][j] *= alpha;
                Ps[tr * 4 + i][tc * 4 + j] = p[j];
            }
        }

        const float* vbase = &g_v[(size_t)(b * Nn + kt * 64) * HC + h * Cc];
        for (int j0 = 0; j0 < 64; j0 += 16) {
            __syncthreads();
            {
                int jj = tid >> 4;
                int c  = (tid & 15) * 4;
                *(float4*)&KVc[jj][c] =
                    *(const float4*)&vbase[(size_t)(j0 + jj) * HC + c];
            }
            __syncthreads();
#pragma unroll
            for (int jj = 0; jj < 16; jj++) {
                float pf[4];
#pragma unroll
                for (int i = 0; i < 4; i++) pf[i] = Ps[tr * 4 + i][j0 + jj];
                float4 vf4 = *(const float4*)&KVc[jj][tc * 4];
                float vf[4] = { vf4.x, vf4.y, vf4.z, vf4.w };
#pragma unroll
                for (int i = 0; i < 4; i++)
#pragma unroll
                    for (int j = 0; j < 4; j++)
                        O[i][j] = fmaf(pf[i], vf[j], O[i][j]);
            }
        }
        __syncthreads();
    }

#pragma unroll
    for (int i = 0; i < 4; i++) {
        int row = qt * 64 + tr * 4 + i;
        float inv = 1.f / l_run[i];
        float4 o4 = make_float4(O[i][0] * inv, O[i][1] * inv,
                                O[i][2] * inv, O[i][3] * inv);
        *(float4*)&out[(size_t)(b * Nn + row) * HC + h * Cc + tc * 4] = o4;
    }
}

// ---------------------------------------------------------------------------
extern "C" void kernel_launch(void* const* d_in, const int* in_sizes, int n_in,
                              void* d_out, int out_size)
{
    const float* s    = (const float*)d_in[0];
    const float* pair = (const float*)d_in[1];
    const int*   seg  = (const int*)d_in[2];
    const int*   pos  = (const int*)d_in[3];
    const float* Wq   = (const float*)d_in[4];
    const float* Wk   = (const float*)d_in[5];
    const float* Wv   = (const float*)d_in[6];
    const float* Wb   = (const float*)d_in[7];
    float* out = (float*)d_out;

    // fp16 conversion (+ transpose for W)
    conv_s_kernel<<<(Mrows * FS) / 256, 256>>>(s);
    conv_w_kernel<<<dim3(HC / 32, FS / 32, 3), dim3(32, 8)>>>(Wq, Wk, Wv);
    // tensor-core QKV projection
    qkv_mma_kernel<<<dim3(HC / 128, Mrows / 128, 3), 256>>>();
    // RoPE in place on q,k
    rope_kernel<<<(Bb * Nn * Hh * 32) / 256, 256>>>(pos);
    // pair bias precompute
    bias_kernel<<<dim3(Nn / 256, Nn, Bb), 256>>>(pair, Wb);
    // flash attention
    attn_kernel<<<dim3(Nn / 64, Hh, Bb), 256>>>(seg, out);
}

// round 9
// speedup vs baseline: 2.2647x; 1.1302x over previous
#include <cuda_runtime.h>
#include <cuda_fp16.h>
#include <math.h>
#include <stdint.h>

#define Bb 2
#define Nn 1024
#define FS 1024
#define FZ 64
#define Hh 16
#define Cc 64
#define HC (Hh*Cc)          // 1024
#define Mrows (Bb*Nn)       // 2048

// ---------------- scratch (static device globals; no allocations) ----------
__device__ float g_q[Bb*Nn*HC];
__device__ float g_k[Bb*Nn*HC];
__device__ float g_v[Bb*Nn*HC];
__device__ __half g_biash[(size_t)Bb*Hh*Nn*Nn];  // 64MB fp16 bias

// fp16 copies for tensor-core GEMM
__device__ __half g_sh[(size_t)Mrows*FS];        // [m][k]
__device__ __half g_wh[(size_t)3*HC*FS];         // [mat][n][k]  (W transposed)

// ======================= helpers ===========================================
static __device__ __forceinline__ uint32_t smem_u32(const void* p) {
    uint32_t a;
    asm("{ .reg .u64 t; cvta.to.shared.u64 t, %1; cvt.u32.u64 %0, t; }"
        : "=r"(a) : "l"(p));
    return a;
}
static __device__ __forceinline__ void cp16(uint32_t dst, const void* src) {
    asm volatile("cp.async.cg.shared.global [%0], [%1], 16;"
                 :: "r"(dst), "l"(src) : "memory");
}
static __device__ __forceinline__ void cp_commit() {
    asm volatile("cp.async.commit_group;" ::: "memory");
}

#define MMA16816(d, a, b0v, b1v)                                              \
    asm volatile("mma.sync.aligned.m16n8k16.row.col.f32.f16.f16.f32 "         \
                 "{%0,%1,%2,%3}, {%4,%5,%6,%7}, {%8,%9}, {%0,%1,%2,%3};"      \
                 : "+f"((d)[0]), "+f"((d)[1]), "+f"((d)[2]), "+f"((d)[3])     \
                 : "r"((a)[0]), "r"((a)[1]), "r"((a)[2]), "r"((a)[3]),        \
                   "r"(b0v), "r"(b1v))

// ---------------- conversion kernels ---------------------------------------
__global__ void conv_s_kernel(const float* __restrict__ s) {
    int i = blockIdx.x * 256 + threadIdx.x;
    g_sh[i] = __float2half(s[i]);
}

// transpose + convert: g_wh[mat][n][k] = W_mat[k][n]
__global__ void conv_w_kernel(const float* __restrict__ Wq,
                              const float* __restrict__ Wk,
                              const float* __restrict__ Wv) {
    __shared__ float t[32][33];
    const float* W = (blockIdx.z == 0) ? Wq : (blockIdx.z == 1) ? Wk : Wv;
    int n0 = blockIdx.x * 32;
    int k0 = blockIdx.y * 32;
    int tx = threadIdx.x, ty = threadIdx.y;
#pragma unroll
    for (int i = 0; i < 32; i += 8)
        t[ty + i][tx] = W[(size_t)(k0 + ty + i) * HC + n0 + tx];
    __syncthreads();
#pragma unroll
    for (int i = 0; i < 32; i += 8) {
        size_t idx = ((size_t)(blockIdx.z * HC + n0 + ty + i)) * FS + k0 + tx;
        g_wh[idx] = __float2half(t[tx][ty + i]);
    }
}

// ---------------- QKV projection via mma.sync (HMMA) ------------------------
#define PAD 40

__global__ __launch_bounds__(256) void qkv_mma_kernel()
{
    __shared__ __half As[2][128 * PAD];
    __shared__ __half Bs[2][128 * PAD];

    const int tid  = threadIdx.x;
    const int col0 = blockIdx.x * 128;
    const int row0 = blockIdx.y * 128;
    const int mat  = blockIdx.z;

    float* O = (mat == 0) ? g_q : (mat == 1) ? g_k : g_v;
    const __half* Ag = g_sh + (size_t)row0 * FS;
    const __half* Bg = g_wh + (size_t)(mat * HC + col0) * FS;

    const uint32_t aS = smem_u32(As);
    const uint32_t bS = smem_u32(Bs);

    const int r  = tid >> 1;
    const int pp = (tid & 1) * 16;

    const int w    = tid >> 5;
    const int lane = tid & 31;
    const int gid  = lane >> 2;
    const int tig  = lane & 3;
    const int wm   = w & 3;
    const int wn   = w >> 2;

    float acc[2][8][4];
#pragma unroll
    for (int mf = 0; mf < 2; mf++)
#pragma unroll
        for (int nf = 0; nf < 8; nf++)
#pragma unroll
            for (int i = 0; i < 4; i++) acc[mf][nf][i] = 0.f;

    auto issue = [&](int c, int buf) {
        const __half* as = Ag + (size_t)r * FS + c * 32 + pp;
        const __half* bs = Bg + (size_t)r * FS + c * 32 + pp;
        uint32_t ad = aS + (uint32_t)(buf * 128 * PAD + r * PAD + pp) * 2;
        uint32_t bd = bS + (uint32_t)(buf * 128 * PAD + r * PAD + pp) * 2;
        cp16(ad,      as);
        cp16(ad + 16, as + 8);
        cp16(bd,      bs);
        cp16(bd + 16, bs + 8);
    };

    issue(0, 0);
    cp_commit();

#pragma unroll 1
    for (int c = 0; c < 32; ++c) {
        if (c + 1 < 32) {
            issue(c + 1, (c + 1) & 1);
            cp_commit();
            asm volatile("cp.async.wait_group 1;" ::: "memory");
        } else {
            asm volatile("cp.async.wait_group 0;" ::: "memory");
        }
        __syncthreads();

        const __half* Abuf = As[c & 1];
        const __half* Bbuf = Bs[c & 1];

#pragma unroll
        for (int kk = 0; kk < 32; kk += 16) {
            uint32_t a[2][4];
#pragma unroll
            for (int mf = 0; mf < 2; ++mf) {
                const __half* p0 = Abuf + (wm * 32 + mf * 16 + gid) * PAD + kk + 2 * tig;
                a[mf][0] = *(const uint32_t*)p0;
                a[mf][1] = *(const uint32_t*)(p0 + 8 * PAD);
                a[mf][2] = *(const uint32_t*)(p0 + 8);
                a[mf][3] = *(const uint32_t*)(p0 + 8 * PAD + 8);
            }
#pragma unroll
            for (int nf = 0; nf < 8; ++nf) {
                const __half* q0 = Bbuf + (wn * 64 + nf * 8 + gid) * PAD + kk + 2 * tig;
                uint32_t b0 = *(const uint32_t*)q0;
                uint32_t b1 = *(const uint32_t*)(q0 + 8);
                MMA16816(acc[0][nf], a[0], b0, b1);
                MMA16816(acc[1][nf], a[1], b0, b1);
            }
        }
        __syncthreads();
    }

#pragma unroll
    for (int mf = 0; mf < 2; ++mf)
#pragma unroll
        for (int nf = 0; nf < 8; ++nf) {
            int row = row0 + wm * 32 + mf * 16 + gid;
            int col = col0 + wn * 64 + nf * 8 + 2 * tig;
            float* d0 = O + (size_t)row * HC + col;
            *(float2*)d0            = make_float2(acc[mf][nf][0], acc[mf][nf][1]);
            *(float2*)(d0 + 8 * HC) = make_float2(acc[mf][nf][2], acc[mf][nf][3]);
        }
}

// ---------------- RoPE on g_q and g_k, in place (fp32 only) -----------------
__global__ void rope_kernel(const int* __restrict__ positions)
{
    int idx = blockIdx.x * blockDim.x + threadIdx.x;
    int i = idx & 31;
    int h = (idx >> 5) & 15;
    int n = (idx >> 9) & 1023;
    int b = idx >> 19;

    int pos = positions[b * Nn + n];
    // 1/timescale = 10000^(-i/32) = 2^(-i*log2(10000)/32)
    float inv_ts = exp2f(-0.41524101186092029f * (float)i);
    float ang = (float)pos * inv_ts;
    float sn, cs;
    __sincosf(ang, &sn, &cs);
    // __sincosf has ~2^-22 abs error on reduced range; ang can be up to 1023
    // -> use accurate sincosf instead for large args
    sincosf(ang, &sn, &cs);

    size_t base = (size_t)(b * Nn + n) * HC + h * Cc;
    float q1 = g_q[base + i], q2 = g_q[base + 32 + i];
    g_q[base + i]      = q1 * cs - q2 * sn;
    g_q[base + 32 + i] = q2 * cs + q1 * sn;
    float k1 = g_k[base + i], k2 = g_k[base + 32 + i];
    g_k[base + i]      = k1 * cs - k2 * sn;
    g_k[base + 32 + i] = k2 * cs + k1 * sn;
}

// ---------------- bias[b,h,q,k] = sum_f pair[b,q,k,f] * Wb[f,h] (fp16 out) --
__global__ void bias_kernel(const float* __restrict__ pair,
                            const float* __restrict__ Wb)
{
    __shared__ float Wb_s[FZ][Hh];
    for (int i = threadIdx.x; i < FZ * Hh; i += 256)
        Wb_s[i >> 4][i & 15] = Wb[i];
    __syncthreads();

    const int k = blockIdx.x * 256 + threadIdx.x;
    const int q = blockIdx.y;
    const int b = blockIdx.z;

    const float4* pp = (const float4*)&pair[((size_t)(b * Nn + q) * Nn + k) * FZ];

    float acc[Hh];
#pragma unroll
    for (int h = 0; h < Hh; h++) acc[h] = 0.f;

#pragma unroll
    for (int f4 = 0; f4 < FZ / 4; f4++) {
        float4 p = pp[f4];
#pragma unroll
        for (int h = 0; h < Hh; h++) {
            acc[h] += p.x * Wb_s[4 * f4 + 0][h];
            acc[h] += p.y * Wb_s[4 * f4 + 1][h];
            acc[h] += p.z * Wb_s[4 * f4 + 2][h];
            acc[h] += p.w * Wb_s[4 * f4 + 3][h];
        }
    }
#pragma unroll
    for (int h = 0; h < Hh; h++)
        g_biash[((size_t)(b * Hh + h) * Nn + q) * Nn + k] = __float2half(acc[h]);
}

// ---------------- flash attention ------------------------------------------
// 256 threads, 4x4 register tiles, full 64x64 K(transposed)+V tiles in
// dynamic smem -> 3 syncthreads per kt iteration.
#define TW 68
#define ATTN_SMEM (4 * 64 * TW * 4)   // Qs, Ps, Ks, Vs

__global__ __launch_bounds__(256) void attn_kernel(const int* __restrict__ seg,
                                                   float* __restrict__ out)
{
    extern __shared__ float dynsm[];
    float* Qs = dynsm;                 // [row][c]
    float* Ps = dynsm + 64 * TW;       // [row][j]
    float* Ks = dynsm + 2 * 64 * TW;   // [c][key]   (transposed)
    float* Vs = dynsm + 3 * 64 * TW;   // [key][c]
    __shared__ int seg_s[64];

    const int tid = threadIdx.x;
    const int tr  = tid >> 4;
    const int tc  = tid & 15;
    const int qt  = gridDim.x - 1 - blockIdx.x;
    const int h   = blockIdx.y;
    const int b   = blockIdx.z;

    const float sm_scale = 0.125f;

    {
        int r  = tid >> 2;
        int c0 = (tid & 3) * 16;
        const float* qp = &g_q[(size_t)(b * Nn + qt * 64 + r) * HC + h * Cc + c0];
#pragma unroll
        for (int u = 0; u < 4; u++)
            *(float4*)&Qs[r * TW + c0 + u * 4] = *(const float4*)&qp[u * 4];
    }

    int   my_seg[4];
    float m_run[4], l_run[4];
    float O[4][4];
#pragma unroll
    for (int i = 0; i < 4; i++) {
        my_seg[i] = seg[b * Nn + qt * 64 + tr * 4 + i];
        m_run[i] = -INFINITY;
        l_run[i] = 0.f;
#pragma unroll
        for (int j = 0; j < 4; j++) O[i][j] = 0.f;
    }
    __syncthreads();   // Qs ready

    for (int kt = 0; kt <= qt; kt++) {
        // ---- load K (transposed) + V (direct) tiles ----
        const float* kbase = &g_k[(size_t)(b * Nn + kt * 64) * HC + h * Cc];
        const float* vbase = &g_v[(size_t)(b * Nn + kt * 64) * HC + h * Cc];
#pragma unroll
        for (int t = tid; t < 1024; t += 256) {
            int r  = t >> 4;
            int c4 = (t & 15) * 4;
            float4 kk = *(const float4*)&kbase[(size_t)r * HC + c4];
            Ks[(c4 + 0) * TW + r] = kk.x;
            Ks[(c4 + 1) * TW + r] = kk.y;
            Ks[(c4 + 2) * TW + r] = kk.z;
            Ks[(c4 + 3) * TW + r] = kk.w;
            *(float4*)&Vs[r * TW + c4] = *(const float4*)&vbase[(size_t)r * HC + c4];
        }
        if (tid < 64) seg_s[tid] = seg[b * Nn + kt * 64 + tid];
        __syncthreads();

        // ---- S = Q . K^T (full 64 dims, no syncs) ----
        float S[4][4];
#pragma unroll
        for (int i = 0; i < 4; i++)
#pragma unroll
            for (int j = 0; j < 4; j++) S[i][j] = 0.f;

#pragma unroll 8
        for (int cc = 0; cc < 64; cc++) {
            float qf[4];
#pragma unroll
            for (int i = 0; i < 4; i++) qf[i] = Qs[(tr * 4 + i) * TW + cc];
            float4 kf4 = *(const float4*)&Ks[cc * TW + tc * 4];
            float kf[4] = { kf4.x, kf4.y, kf4.z, kf4.w };
#pragma unroll
            for (int i = 0; i < 4; i++)
#pragma unroll
                for (int j = 0; j < 4; j++)
                    S[i][j] = fmaf(qf[i], kf[j], S[i][j]);
        }

        // ---- bias (fp16) + mask + online softmax ----
        float mx[4];
#pragma unroll
        for (int i = 0; i < 4; i++) {
            int row = qt * 64 + tr * 4 + i;
            const __half2* bp = (const __half2*)&g_biash[
                ((size_t)(b * Hh + h) * Nn + row) * Nn + kt * 64 + tc * 4];
            float2 b01 = __half22float2(bp[0]);
            float2 b23 = __half22float2(bp[1]);
            float bb[4] = { b01.x, b01.y, b23.x, b23.y };
            mx[i] = -INFINITY;
#pragma unroll
            for (int j = 0; j < 4; j++) {
                int key = kt * 64 + tc * 4 + j;
                bool ok = (key <= row) && (seg_s[tc * 4 + j] == my_seg[i]);
                S[i][j] = ok ? fmaf(S[i][j], sm_scale, bb[j]) : -INFINITY;
                mx[i] = fmaxf(mx[i], S[i][j]);
            }
        }
#pragma unroll
        for (int s = 8; s >= 1; s >>= 1)
#pragma unroll
            for (int i = 0; i < 4; i++)
                mx[i] = fmaxf(mx[i], __shfl_xor_sync(0xffffffffu, mx[i], s, 16));

#pragma unroll
        for (int i = 0; i < 4; i++) {
            float m_new = fmaxf(m_run[i], mx[i]);
            bool  dead  = (m_new == -INFINITY);
            float m_use = dead ? 0.f : m_new;
            float alpha = __expf(m_run[i] - m_use);
            float ps = 0.f;
            float p[4];
#pragma unroll
            for (int j = 0; j < 4; j++) {
                p[j] = __expf(S[i][j] - m_use);
                ps += p[j];
            }
#pragma unroll
            for (int s = 8; s >= 1; s >>= 1)
                ps += __shfl_xor_sync(0xffffffffu, ps, s, 16);
            l_run[i] = l_run[i] * alpha + ps;
            m_run[i] = m_new;
#pragma unroll
            for (int j = 0; j < 4; j++) {
                O[i][j] *= alpha;
                Ps[(tr * 4 + i) * TW + tc * 4 + j] = p[j];
            }
        }
        __syncthreads();   // Ps visible

        // ---- O += P . V (full 64 keys, no syncs) ----
#pragma unroll 8
        for (int jj = 0; jj < 64; jj++) {
            float pf[4];
#pragma unroll
            for (int i = 0; i < 4; i++) pf[i] = Ps[(tr * 4 + i) * TW + jj];
            float4 vf4 = *(const float4*)&Vs[jj * TW + tc * 4];
            float vf[4] = { vf4.x, vf4.y, vf4.z, vf4.w };
#pragma unroll
            for (int i = 0; i < 4; i++)
#pragma unroll
                for (int j = 0; j < 4; j++)
                    O[i][j] = fmaf(pf[i], vf[j], O[i][j]);
        }
        __syncthreads();   // tiles free for next kt
    }

#pragma unroll
    for (int i = 0; i < 4; i++) {
        int row = qt * 64 + tr * 4 + i;
        float inv = 1.f / l_run[i];
        float4 o4 = make_float4(O[i][0] * inv, O[i][1] * inv,
                                O[i][2] * inv, O[i][3] * inv);
        *(float4*)&out[(size_t)(b * Nn + row) * HC + h * Cc + tc * 4] = o4;
    }
}

// ---------------------------------------------------------------------------
extern "C" void kernel_launch(void* const* d_in, const int* in_sizes, int n_in,
                              void* d_out, int out_size)
{
    const float* s    = (const float*)d_in[0];
    const float* pair = (const float*)d_in[1];
    const int*   seg  = (const int*)d_in[2];
    const int*   pos  = (const int*)d_in[3];
    const float* Wq   = (const float*)d_in[4];
    const float* Wk   = (const float*)d_in[5];
    const float* Wv   = (const float*)d_in[6];
    const float* Wb   = (const float*)d_in[7];
    float* out = (float*)d_out;

    cudaFuncSetAttribute(attn_kernel,
                         cudaFuncAttributeMaxDynamicSharedMemorySize, ATTN_SMEM);

    conv_s_kernel<<<(Mrows * FS) / 256, 256>>>(s);
    conv_w_kernel<<<dim3(HC / 32, FS / 32, 3), dim3(32, 8)>>>(Wq, Wk, Wv);
    qkv_mma_kernel<<<dim3(HC / 128, Mrows / 128, 3), 256>>>();
    rope_kernel<<<(Bb * Nn * Hh * 32) / 256, 256>>>(pos);
    bias_kernel<<<dim3(Nn / 256, Nn, Bb), 256>>>(pair, Wb);
    attn_kernel<<<dim3(Nn / 64, Hh, Bb), 256, ATTN_SMEM>>>(seg, out);
}

// round 11
// speedup vs baseline: 5.2396x; 2.3136x over previous
#include <cuda_runtime.h>
#include <cuda_fp16.h>
#include <math.h>
#include <stdint.h>

#define Bb 2
#define Nn 1024
#define FS 1024
#define FZ 64
#define Hh 16
#define Cc 64
#define HC (Hh*Cc)          // 1024
#define Mrows (Bb*Nn)       // 2048

// ---------------- scratch (static device globals; no allocations) ----------
__device__ float g_q[Bb*Nn*HC];
__device__ float g_k[Bb*Nn*HC];
__device__ float g_v[Bb*Nn*HC];
__device__ __half g_biash[(size_t)Bb*Hh*Nn*Nn];  // 64MB fp16 bias

// fp16 copies for tensor-core GEMM
__device__ __half g_sh[(size_t)Mrows*FS];        // [m][k]
__device__ __half g_wh[(size_t)3*HC*FS];         // [mat][n][k]  (W transposed)

// ======================= helpers ===========================================
static __device__ __forceinline__ uint32_t smem_u32(const void* p) {
    uint32_t a;
    asm("{ .reg .u64 t; cvta.to.shared.u64 t, %1; cvt.u32.u64 %0, t; }"
        : "=r"(a) : "l"(p));
    return a;
}
static __device__ __forceinline__ void cp16(uint32_t dst, const void* src) {
    asm volatile("cp.async.cg.shared.global [%0], [%1], 16;"
                 :: "r"(dst), "l"(src) : "memory");
}
static __device__ __forceinline__ void cp_commit() {
    asm volatile("cp.async.commit_group;" ::: "memory");
}

#define MMA16816(d, a, b0v, b1v)                                              \
    asm volatile("mma.sync.aligned.m16n8k16.row.col.f32.f16.f16.f32 "         \
                 "{%0,%1,%2,%3}, {%4,%5,%6,%7}, {%8,%9}, {%0,%1,%2,%3};"      \
                 : "+f"((d)[0]), "+f"((d)[1]), "+f"((d)[2]), "+f"((d)[3])     \
                 : "r"((a)[0]), "r"((a)[1]), "r"((a)[2]), "r"((a)[3]),        \
                   "r"(b0v), "r"(b1v))

// ---------------- conversion kernels ---------------------------------------
__global__ void conv_s_kernel(const float* __restrict__ s) {
    int i = blockIdx.x * 256 + threadIdx.x;
    g_sh[i] = __float2half(s[i]);
}

// transpose + convert: g_wh[mat][n][k] = W_mat[k][n]
__global__ void conv_w_kernel(const float* __restrict__ Wq,
                              const float* __restrict__ Wk,
                              const float* __restrict__ Wv) {
    __shared__ float t[32][33];
    const float* W = (blockIdx.z == 0) ? Wq : (blockIdx.z == 1) ? Wk : Wv;
    int n0 = blockIdx.x * 32;
    int k0 = blockIdx.y * 32;
    int tx = threadIdx.x, ty = threadIdx.y;
#pragma unroll
    for (int i = 0; i < 32; i += 8)
        t[ty + i][tx] = W[(size_t)(k0 + ty + i) * HC + n0 + tx];
    __syncthreads();
#pragma unroll
    for (int i = 0; i < 32; i += 8) {
        size_t idx = ((size_t)(blockIdx.z * HC + n0 + ty + i)) * FS + k0 + tx;
        g_wh[idx] = __float2half(t[tx][ty + i]);
    }
}

// ---------------- QKV projection via mma.sync (HMMA) ------------------------
#define PAD 40

__global__ __launch_bounds__(256) void qkv_mma_kernel()
{
    __shared__ __half As[2][128 * PAD];
    __shared__ __half Bs[2][128 * PAD];

    const int tid  = threadIdx.x;
    const int col0 = blockIdx.x * 128;
    const int row0 = blockIdx.y * 128;
    const int mat  = blockIdx.z;

    float* O = (mat == 0) ? g_q : (mat == 1) ? g_k : g_v;
    const __half* Ag = g_sh + (size_t)row0 * FS;
    const __half* Bg = g_wh + (size_t)(mat * HC + col0) * FS;

    const uint32_t aS = smem_u32(As);
    const uint32_t bS = smem_u32(Bs);

    const int r  = tid >> 1;
    const int pp = (tid & 1) * 16;

    const int w    = tid >> 5;
    const int lane = tid & 31;
    const int gid  = lane >> 2;
    const int tig  = lane & 3;
    const int wm   = w & 3;
    const int wn   = w >> 2;

    float acc[2][8][4];
#pragma unroll
    for (int mf = 0; mf < 2; mf++)
#pragma unroll
        for (int nf = 0; nf < 8; nf++)
#pragma unroll
            for (int i = 0; i < 4; i++) acc[mf][nf][i] = 0.f;

    auto issue = [&](int c, int buf) {
        const __half* as = Ag + (size_t)r * FS + c * 32 + pp;
        const __half* bs = Bg + (size_t)r * FS + c * 32 + pp;
        uint32_t ad = aS + (uint32_t)(buf * 128 * PAD + r * PAD + pp) * 2;
        uint32_t bd = bS + (uint32_t)(buf * 128 * PAD + r * PAD + pp) * 2;
        cp16(ad,      as);
        cp16(ad + 16, as + 8);
        cp16(bd,      bs);
        cp16(bd + 16, bs + 8);
    };

    issue(0, 0);
    cp_commit();

#pragma unroll 1
    for (int c = 0; c < 32; ++c) {
        if (c + 1 < 32) {
            issue(c + 1, (c + 1) & 1);
            cp_commit();
            asm volatile("cp.async.wait_group 1;" ::: "memory");
        } else {
            asm volatile("cp.async.wait_group 0;" ::: "memory");
        }
        __syncthreads();

        const __half* Abuf = As[c & 1];
        const __half* Bbuf = Bs[c & 1];

#pragma unroll
        for (int kk = 0; kk < 32; kk += 16) {
            uint32_t a[2][4];
#pragma unroll
            for (int mf = 0; mf < 2; ++mf) {
                const __half* p0 = Abuf + (wm * 32 + mf * 16 + gid) * PAD + kk + 2 * tig;
                a[mf][0] = *(const uint32_t*)p0;
                a[mf][1] = *(const uint32_t*)(p0 + 8 * PAD);
                a[mf][2] = *(const uint32_t*)(p0 + 8);
                a[mf][3] = *(const uint32_t*)(p0 + 8 * PAD + 8);
            }
#pragma unroll
            for (int nf = 0; nf < 8; ++nf) {
                const __half* q0 = Bbuf + (wn * 64 + nf * 8 + gid) * PAD + kk + 2 * tig;
                uint32_t b0 = *(const uint32_t*)q0;
                uint32_t b1 = *(const uint32_t*)(q0 + 8);
                MMA16816(acc[0][nf], a[0], b0, b1);
                MMA16816(acc[1][nf], a[1], b0, b1);
            }
        }
        __syncthreads();
    }

#pragma unroll
    for (int mf = 0; mf < 2; ++mf)
#pragma unroll
        for (int nf = 0; nf < 8; ++nf) {
            int row = row0 + wm * 32 + mf * 16 + gid;
            int col = col0 + wn * 64 + nf * 8 + 2 * tig;
            float* d0 = O + (size_t)row * HC + col;
            *(float2*)d0            = make_float2(acc[mf][nf][0], acc[mf][nf][1]);
            *(float2*)(d0 + 8 * HC) = make_float2(acc[mf][nf][2], acc[mf][nf][3]);
        }
}

// ---------------- RoPE on g_q and g_k, in place (fp32) ----------------------
__global__ void rope_kernel(const int* __restrict__ positions)
{
    int idx = blockIdx.x * blockDim.x + threadIdx.x;
    int i = idx & 31;
    int h = (idx >> 5) & 15;
    int n = (idx >> 9) & 1023;
    int b = idx >> 19;

    int pos = positions[b * Nn + n];
    float inv_ts = exp2f(-0.41524101186092029f * (float)i);
    float ang = (float)pos * inv_ts;
    float sn, cs;
    sincosf(ang, &sn, &cs);

    size_t base = (size_t)(b * Nn + n) * HC + h * Cc;
    float q1 = g_q[base + i], q2 = g_q[base + 32 + i];
    g_q[base + i]      = q1 * cs - q2 * sn;
    g_q[base + 32 + i] = q2 * cs + q1 * sn;
    float k1 = g_k[base + i], k2 = g_k[base + 32 + i];
    g_k[base + i]      = k1 * cs - k2 * sn;
    g_k[base + 32 + i] = k2 * cs + k1 * sn;
}

// ---------------- bias (fp16 out), masked-region skip -----------------------
// grid: (Nn/64 k-tiles, Nn/4 q-groups, Bb); block 256 = 4 q-rows x 64 k.
// Only compute tiles that the attention kernel can actually consume:
// kt <= qt (causal at tile granularity) and segment range overlap.
__global__ __launch_bounds__(256) void bias_kernel(const float* __restrict__ pair,
                                                   const float* __restrict__ Wb,
                                                   const int* __restrict__ seg)
{
    const int kt = blockIdx.x;
    const int q0 = blockIdx.y * 4;
    const int b  = blockIdx.z;

    // causal skip: attn reads bias tiles only for kt <= qt
    if (kt > (q0 >> 6)) return;
    // segment skip: sorted segs -> overlap iff ranges intersect
    const int* sb = seg + b * Nn;
    if (sb[kt * 64 + 63] < sb[q0] || sb[kt * 64] > sb[q0 + 3]) return;

    __shared__ float Wb_s[FZ][Hh];
    for (int i = threadIdx.x; i < FZ * Hh; i += 256)
        Wb_s[i >> 4][i & 15] = Wb[i];
    __syncthreads();

    const int q = q0 + (threadIdx.x >> 6);
    const int k = kt * 64 + (threadIdx.x & 63);

    const float4* pp = (const float4*)&pair[((size_t)(b * Nn + q) * Nn + k) * FZ];

    float acc[Hh];
#pragma unroll
    for (int h = 0; h < Hh; h++) acc[h] = 0.f;

#pragma unroll
    for (int f4 = 0; f4 < FZ / 4; f4++) {
        float4 p = pp[f4];
#pragma unroll
        for (int h = 0; h < Hh; h++) {
            acc[h] += p.x * Wb_s[4 * f4 + 0][h];
            acc[h] += p.y * Wb_s[4 * f4 + 1][h];
            acc[h] += p.z * Wb_s[4 * f4 + 2][h];
            acc[h] += p.w * Wb_s[4 * f4 + 3][h];
        }
    }
#pragma unroll
    for (int h = 0; h < Hh; h++)
        g_biash[((size_t)(b * Hh + h) * Nn + q) * Nn + k] = __float2half(acc[h]);
}

// ---------------- flash attention ------------------------------------------
// 256 threads, 4x4 register tiles, full 64x64 K(transposed)+V tiles in
// dynamic smem; kt loop starts at first segment-overlapping tile.
#define TW 68
#define ATTN_SMEM (4 * 64 * TW * 4)   // Qs, Ps, Ks, Vs

__global__ __launch_bounds__(256) void attn_kernel(const int* __restrict__ seg,
                                                   float* __restrict__ out)
{
    extern __shared__ float dynsm[];
    float* Qs = dynsm;                 // [row][c]
    float* Ps = dynsm + 64 * TW;       // [row][j]
    float* Ks = dynsm + 2 * 64 * TW;   // [c][key]   (transposed)
    float* Vs = dynsm + 3 * 64 * TW;   // [key][c]
    __shared__ int seg_s[64];

    const int tid = threadIdx.x;
    const int tr  = tid >> 4;
    const int tc  = tid & 15;
    const int qt  = gridDim.x - 1 - blockIdx.x;
    const int h   = blockIdx.y;
    const int b   = blockIdx.z;

    const float sm_scale = 0.125f;

    {
        int r  = tid >> 2;
        int c0 = (tid & 3) * 16;
        const float* qp = &g_q[(size_t)(b * Nn + qt * 64 + r) * HC + h * Cc + c0];
#pragma unroll
        for (int u = 0; u < 4; u++)
            *(float4*)&Qs[r * TW + c0 + u * 4] = *(const float4*)&qp[u * 4];
    }

    // first kt whose tile can contain my segments (segs sorted ascending)
    const int* sb = seg + b * Nn;
    const int segA = sb[qt * 64];
    int kt_start = 0;
    while (kt_start < qt && sb[kt_start * 64 + 63] < segA) kt_start++;

    int   my_seg[4];
    float m_run[4], l_run[4];
    float O[4][4];
#pragma unroll
    for (int i = 0; i < 4; i++) {
        my_seg[i] = sb[qt * 64 + tr * 4 + i];
        m_run[i] = -INFINITY;
        l_run[i] = 0.f;
#pragma unroll
        for (int j = 0; j < 4; j++) O[i][j] = 0.f;
    }
    __syncthreads();   // Qs ready

    for (int kt = kt_start; kt <= qt; kt++) {
        // ---- load K (transposed) + V (direct) tiles ----
        const float* kbase = &g_k[(size_t)(b * Nn + kt * 64) * HC + h * Cc];
        const float* vbase = &g_v[(size_t)(b * Nn + kt * 64) * HC + h * Cc];
#pragma unroll
        for (int t = tid; t < 1024; t += 256) {
            int r  = t >> 4;
            int c4 = (t & 15) * 4;
            float4 kk = *(const float4*)&kbase[(size_t)r * HC + c4];
            Ks[(c4 + 0) * TW + r] = kk.x;
            Ks[(c4 + 1) * TW + r] = kk.y;
            Ks[(c4 + 2) * TW + r] = kk.z;
            Ks[(c4 + 3) * TW + r] = kk.w;
            *(float4*)&Vs[r * TW + c4] = *(const float4*)&vbase[(size_t)r * HC + c4];
        }
        if (tid < 64) seg_s[tid] = sb[kt * 64 + tid];
        __syncthreads();

        // ---- S = Q . K^T ----
        float S[4][4];
#pragma unroll
        for (int i = 0; i < 4; i++)
#pragma unroll
            for (int j = 0; j < 4; j++) S[i][j] = 0.f;

#pragma unroll 8
        for (int cc = 0; cc < 64; cc++) {
            float qf[4];
#pragma unroll
            for (int i = 0; i < 4; i++) qf[i] = Qs[(tr * 4 + i) * TW + cc];
            float4 kf4 = *(const float4*)&Ks[cc * TW + tc * 4];
            float kf[4] = { kf4.x, kf4.y, kf4.z, kf4.w };
#pragma unroll
            for (int i = 0; i < 4; i++)
#pragma unroll
                for (int j = 0; j < 4; j++)
                    S[i][j] = fmaf(qf[i], kf[j], S[i][j]);
        }

        // ---- bias (fp16) + mask + online softmax ----
        float mx[4];
#pragma unroll
        for (int i = 0; i < 4; i++) {
            int row = qt * 64 + tr * 4 + i;
            const __half2* bp = (const __half2*)&g_biash[
                ((size_t)(b * Hh + h) * Nn + row) * Nn + kt * 64 + tc * 4];
            float2 b01 = __half22float2(bp[0]);
            float2 b23 = __half22float2(bp[1]);
            float bb[4] = { b01.x, b01.y, b23.x, b23.y };
            mx[i] = -INFINITY;
#pragma unroll
            for (int j = 0; j < 4; j++) {
                int key = kt * 64 + tc * 4 + j;
                bool ok = (key <= row) && (seg_s[tc * 4 + j] == my_seg[i]);
                S[i][j] = ok ? fmaf(S[i][j], sm_scale, bb[j]) : -INFINITY;
                mx[i] = fmaxf(mx[i], S[i][j]);
            }
        }
#pragma unroll
        for (int s = 8; s >= 1; s >>= 1)
#pragma unroll
            for (int i = 0; i < 4; i++)
                mx[i] = fmaxf(mx[i], __shfl_xor_sync(0xffffffffu, mx[i], s, 16));

#pragma unroll
        for (int i = 0; i < 4; i++) {
            float m_new = fmaxf(m_run[i], mx[i]);
            bool  dead  = (m_new == -INFINITY);
            float m_use = dead ? 0.f : m_new;
            float alpha = __expf(m_run[i] - m_use);
            float ps = 0.f;
            float p[4];
#pragma unroll
            for (int j = 0; j < 4; j++) {
                p[j] = __expf(S[i][j] - m_use);
                ps += p[j];
            }
#pragma unroll
            for (int s = 8; s >= 1; s >>= 1)
                ps += __shfl_xor_sync(0xffffffffu, ps, s, 16);
            l_run[i] = l_run[i] * alpha + ps;
            m_run[i] = m_new;
#pragma unroll
            for (int j = 0; j < 4; j++) {
                O[i][j] *= alpha;
                Ps[(tr * 4 + i) * TW + tc * 4 + j] = p[j];
            }
        }
        __syncthreads();   // Ps visible

        // ---- O += P . V ----
#pragma unroll 8
        for (int jj = 0; jj < 64; jj++) {
            float pf[4];
#pragma unroll
            for (int i = 0; i < 4; i++) pf[i] = Ps[(tr * 4 + i) * TW + jj];
            float4 vf4 = *(const float4*)&Vs[jj * TW + tc * 4];
            float vf[4] = { vf4.x, vf4.y, vf4.z, vf4.w };
#pragma unroll
            for (int i = 0; i < 4; i++)
#pragma unroll
                for (int j = 0; j < 4; j++)
                    O[i][j] = fmaf(pf[i], vf[j], O[i][j]);
        }
        __syncthreads();   // tiles free for next kt
    }

#pragma unroll
    for (int i = 0; i < 4; i++) {
        int row = qt * 64 + tr * 4 + i;
        float inv = 1.f / l_run[i];
        float4 o4 = make_float4(O[i][0] * inv, O[i][1] * inv,
                                O[i][2] * inv, O[i][3] * inv);
        *(float4*)&out[(size_t)(b * Nn + row) * HC + h * Cc + tc * 4] = o4;
    }
}

// ---------------------------------------------------------------------------
extern "C" void kernel_launch(void* const* d_in, const int* in_sizes, int n_in,
                              void* d_out, int out_size)
{
    const float* s    = (const float*)d_in[0];
    const float* pair = (const float*)d_in[1];
    const int*   seg  = (const int*)d_in[2];
    const int*   pos  = (const int*)d_in[3];
    const float* Wq   = (const float*)d_in[4];
    const float* Wk   = (const float*)d_in[5];
    const float* Wv   = (const float*)d_in[6];
    const float* Wb   = (const float*)d_in[7];
    float* out = (float*)d_out;

    cudaFuncSetAttribute(attn_kernel,
                         cudaFuncAttributeMaxDynamicSharedMemorySize, ATTN_SMEM);

    conv_s_kernel<<<(Mrows * FS) / 256, 256>>>(s);
    conv_w_kernel<<<dim3(HC / 32, FS / 32, 3), dim3(32, 8)>>>(Wq, Wk, Wv);
    qkv_mma_kernel<<<dim3(HC / 128, Mrows / 128, 3), 256>>>();
    rope_kernel<<<(Bb * Nn * Hh * 32) / 256, 256>>>(pos);
    bias_kernel<<<dim3(Nn / 64, Nn / 4, Bb), 256>>>(pair, Wb, seg);
    attn_kernel<<<dim3(Nn / 64, Hh, Bb), 256, ATTN_SMEM>>>(seg, out);
}

// round 12
// speedup vs baseline: 5.3863x; 1.0280x over previous
#include <cuda_runtime.h>
#include <cuda_fp16.h>
#include <math.h>
#include <stdint.h>

#define Bb 2
#define Nn 1024
#define FS 1024
#define FZ 64
#define Hh 16
#define Cc 64
#define HC (Hh*Cc)          // 1024
#define Mrows (Bb*Nn)       // 2048

// ---------------- scratch (static device globals; no allocations) ----------
__device__ float g_q[Bb*Nn*HC];
__device__ float g_k[Bb*Nn*HC];
__device__ float g_v[Bb*Nn*HC];
__device__ __half g_biash[(size_t)Bb*Hh*Nn*Nn];  // 64MB fp16 bias

// fp16 copies for tensor-core GEMM
__device__ __half g_sh[(size_t)Mrows*FS];        // [m][k]
__device__ __half g_wh[(size_t)3*HC*FS];         // [mat][n][k]  (W transposed)

// ======================= helpers ===========================================
static __device__ __forceinline__ uint32_t smem_u32(const void* p) {
    uint32_t a;
    asm("{ .reg .u64 t; cvta.to.shared.u64 t, %1; cvt.u32.u64 %0, t; }"
        : "=r"(a) : "l"(p));
    return a;
}
static __device__ __forceinline__ void cp16(uint32_t dst, const void* src) {
    asm volatile("cp.async.cg.shared.global [%0], [%1], 16;"
                 :: "r"(dst), "l"(src) : "memory");
}
static __device__ __forceinline__ void cp_commit() {
    asm volatile("cp.async.commit_group;" ::: "memory");
}
static __device__ __forceinline__ void ldmx4(uint32_t* r, uint32_t addr) {
    asm volatile("ldmatrix.sync.aligned.m8n8.x4.shared.b16 {%0,%1,%2,%3}, [%4];"
                 : "=r"(r[0]), "=r"(r[1]), "=r"(r[2]), "=r"(r[3]) : "r"(addr));
}

#define MMA16816(d, a, b0v, b1v)                                              \
    asm volatile("mma.sync.aligned.m16n8k16.row.col.f32.f16.f16.f32 "         \
                 "{%0,%1,%2,%3}, {%4,%5,%6,%7}, {%8,%9}, {%0,%1,%2,%3};"      \
                 : "+f"((d)[0]), "+f"((d)[1]), "+f"((d)[2]), "+f"((d)[3])     \
                 : "r"((a)[0]), "r"((a)[1]), "r"((a)[2]), "r"((a)[3]),        \
                   "r"(b0v), "r"(b1v))

// ---------------- conversion kernels ---------------------------------------
__global__ void conv_s_kernel(const float* __restrict__ s) {
    int i = blockIdx.x * 256 + threadIdx.x;
    g_sh[i] = __float2half(s[i]);
}

// transpose + convert: g_wh[mat][n][k] = W_mat[k][n]
__global__ void conv_w_kernel(const float* __restrict__ Wq,
                              const float* __restrict__ Wk,
                              const float* __restrict__ Wv) {
    __shared__ float t[32][33];
    const float* W = (blockIdx.z == 0) ? Wq : (blockIdx.z == 1) ? Wk : Wv;
    int n0 = blockIdx.x * 32;
    int k0 = blockIdx.y * 32;
    int tx = threadIdx.x, ty = threadIdx.y;
#pragma unroll
    for (int i = 0; i < 32; i += 8)
        t[ty + i][tx] = W[(size_t)(k0 + ty + i) * HC + n0 + tx];
    __syncthreads();
#pragma unroll
    for (int i = 0; i < 32; i += 8) {
        size_t idx = ((size_t)(blockIdx.z * HC + n0 + ty + i)) * FS + k0 + tx;
        g_wh[idx] = __float2half(t[tx][ty + i]);
    }
}

// ---------------- QKV projection via mma.sync (HMMA) ------------------------
// 128x128 tile, BK=32, 3-stage cp.async pipeline, ldmatrix fragment loads.
// Swizzled smem: row r occupies 64B; 16B chunk c stored at c ^ ((r>>1)&3).
#define QSTG 3
#define STG_HALF (128 * 32)   // halves per matrix per stage (8KB)

__global__ __launch_bounds__(256) void qkv_mma_kernel()
{
    __shared__ __align__(16) __half As[QSTG][STG_HALF];
    __shared__ __align__(16) __half Bs[QSTG][STG_HALF];

    const int tid  = threadIdx.x;
    const int col0 = blockIdx.x * 128;
    const int row0 = blockIdx.y * 128;
    const int mat  = blockIdx.z;

    float* O = (mat == 0) ? g_q : (mat == 1) ? g_k : g_v;
    const __half* Ag = g_sh + (size_t)row0 * FS;
    const __half* Bg = g_wh + (size_t)(mat * HC + col0) * FS;

    const uint32_t aS = smem_u32(As);
    const uint32_t bS = smem_u32(Bs);

    // cp.async mapping: thread t -> row r = t>>1, chunks 2*(t&1), 2*(t&1)+1
    const int r   = tid >> 1;
    const int c20 = (tid & 1) * 2;
    const int rx  = (r >> 1) & 3;           // swizzle xor for stores

    const int w    = tid >> 5;
    const int lane = tid & 31;
    const int gid  = lane >> 2;
    const int tig  = lane & 3;
    const int wm   = w & 3;                 // rows wm*32
    const int wn   = w >> 2;                // cols wn*64
    const int lr   = lane & 15;
    const int lh   = lane >> 4;

    float acc[2][8][4];
#pragma unroll
    for (int mf = 0; mf < 2; mf++)
#pragma unroll
        for (int nf = 0; nf < 8; nf++)
#pragma unroll
            for (int i = 0; i < 4; i++) acc[mf][nf][i] = 0.f;

    auto issue = [&](int c, int stg) {
        const __half* as = Ag + (size_t)r * FS + c * 32 + c20 * 8;
        const __half* bs = Bg + (size_t)r * FS + c * 32 + c20 * 8;
        uint32_t arow = aS + (uint32_t)(stg * STG_HALF * 2 + r * 64);
        uint32_t brow = bS + (uint32_t)(stg * STG_HALF * 2 + r * 64);
        cp16(arow + (((c20 + 0) ^ rx) << 4), as);
        cp16(arow + (((c20 + 1) ^ rx) << 4), as + 8);
        cp16(brow + (((c20 + 0) ^ rx) << 4), bs);
        cp16(brow + (((c20 + 1) ^ rx) << 4), bs + 8);
    };

    issue(0, 0); cp_commit();
    issue(1, 1); cp_commit();

#pragma unroll 1
    for (int c = 0; c < 32; ++c) {
        if (c < 31) asm volatile("cp.async.wait_group 1;" ::: "memory");
        else        asm volatile("cp.async.wait_group 0;" ::: "memory");
        __syncthreads();

        if (c + 2 < 32) { issue(c + 2, (c + 2) % QSTG); cp_commit(); }

        const int stg = c % QSTG;
        const uint32_t sA = aS + (uint32_t)(stg * STG_HALF * 2);
        const uint32_t sB = bS + (uint32_t)(stg * STG_HALF * 2);

#pragma unroll
        for (int kk = 0; kk < 32; kk += 16) {
            const int cb = (kk >> 3) + lh;         // chunk index 0..3
            uint32_t a[2][4];
#pragma unroll
            for (int mf = 0; mf < 2; ++mf) {
                int R = wm * 32 + mf * 16 + lr;
                uint32_t addr = sA + (uint32_t)(R * 64 + ((cb ^ ((R >> 1) & 3)) << 4));
                ldmx4(a[mf], addr);
            }
            uint32_t bf[4][4];
#pragma unroll
            for (int np = 0; np < 4; ++np) {
                int R = wn * 64 + np * 16 + lr;
                uint32_t addr = sB + (uint32_t)(R * 64 + ((cb ^ ((R >> 1) & 3)) << 4));
                ldmx4(bf[np], addr);
            }
#pragma unroll
            for (int np = 0; np < 4; ++np) {
                MMA16816(acc[0][2 * np + 0], a[0], bf[np][0], bf[np][2]);
                MMA16816(acc[1][2 * np + 0], a[1], bf[np][0], bf[np][2]);
                MMA16816(acc[0][2 * np + 1], a[0], bf[np][1], bf[np][3]);
                MMA16816(acc[1][2 * np + 1], a[1], bf[np][1], bf[np][3]);
            }
        }
    }

    // epilogue
#pragma unroll
    for (int mf = 0; mf < 2; ++mf)
#pragma unroll
        for (int nf = 0; nf < 8; ++nf) {
            int row = row0 + wm * 32 + mf * 16 + gid;
            int col = col0 + wn * 64 + nf * 8 + 2 * tig;
            float* d0 = O + (size_t)row * HC + col;
            *(float2*)d0            = make_float2(acc[mf][nf][0], acc[mf][nf][1]);
            *(float2*)(d0 + 8 * HC) = make_float2(acc[mf][nf][2], acc[mf][nf][3]);
        }
}

// ---------------- RoPE on g_q and g_k, in place (fp32) ----------------------
__global__ void rope_kernel(const int* __restrict__ positions)
{
    int idx = blockIdx.x * blockDim.x + threadIdx.x;
    int i = idx & 31;
    int h = (idx >> 5) & 15;
    int n = (idx >> 9) & 1023;
    int b = idx >> 19;

    int pos = positions[b * Nn + n];
    float inv_ts = exp2f(-0.41524101186092029f * (float)i);
    float ang = (float)pos * inv_ts;
    float sn, cs;
    sincosf(ang, &sn, &cs);

    size_t base = (size_t)(b * Nn + n) * HC + h * Cc;
    float q1 = g_q[base + i], q2 = g_q[base + 32 + i];
    g_q[base + i]      = q1 * cs - q2 * sn;
    g_q[base + 32 + i] = q2 * cs + q1 * sn;
    float k1 = g_k[base + i], k2 = g_k[base + 32 + i];
    g_k[base + i]      = k1 * cs - k2 * sn;
    g_k[base + 32 + i] = k2 * cs + k1 * sn;
}

// ---------------- bias (fp16 out), masked-region skip -----------------------
__global__ __launch_bounds__(256) void bias_kernel(const float* __restrict__ pair,
                                                   const float* __restrict__ Wb,
                                                   const int* __restrict__ seg)
{
    const int kt = blockIdx.x;
    const int q0 = blockIdx.y * 4;
    const int b  = blockIdx.z;

    if (kt > (q0 >> 6)) return;
    const int* sb = seg + b * Nn;
    if (sb[kt * 64 + 63] < sb[q0] || sb[kt * 64] > sb[q0 + 3]) return;

    __shared__ float Wb_s[FZ][Hh];
    for (int i = threadIdx.x; i < FZ * Hh; i += 256)
        Wb_s[i >> 4][i & 15] = Wb[i];
    __syncthreads();

    const int q = q0 + (threadIdx.x >> 6);
    const int k = kt * 64 + (threadIdx.x & 63);

    const float4* pp = (const float4*)&pair[((size_t)(b * Nn + q) * Nn + k) * FZ];

    float acc[Hh];
#pragma unroll
    for (int h = 0; h < Hh; h++) acc[h] = 0.f;

#pragma unroll
    for (int f4 = 0; f4 < FZ / 4; f4++) {
        float4 p = pp[f4];
#pragma unroll
        for (int h = 0; h < Hh; h++) {
            acc[h] += p.x * Wb_s[4 * f4 + 0][h];
            acc[h] += p.y * Wb_s[4 * f4 + 1][h];
            acc[h] += p.z * Wb_s[4 * f4 + 2][h];
            acc[h] += p.w * Wb_s[4 * f4 + 3][h];
        }
    }
#pragma unroll
    for (int h = 0; h < Hh; h++)
        g_biash[((size_t)(b * Hh + h) * Nn + q) * Nn + k] = __float2half(acc[h]);
}

// ---------------- flash attention ------------------------------------------
#define TW 68
#define ATTN_SMEM (4 * 64 * TW * 4)   // Qs, Ps, Ks, Vs

__global__ __launch_bounds__(256) void attn_kernel(const int* __restrict__ seg,
                                                   float* __restrict__ out)
{
    extern __shared__ float dynsm[];
    float* Qs = dynsm;                 // [row][c]
    float* Ps = dynsm + 64 * TW;       // [row][j]
    float* Ks = dynsm + 2 * 64 * TW;   // [c][key]   (transposed)
    float* Vs = dynsm + 3 * 64 * TW;   // [key][c]
    __shared__ int seg_s[64];

    const int tid = threadIdx.x;
    const int tr  = tid >> 4;
    const int tc  = tid & 15;
    const int qt  = gridDim.x - 1 - blockIdx.x;
    const int h   = blockIdx.y;
    const int b   = blockIdx.z;

    const float sm_scale = 0.125f;

    {
        int r  = tid >> 2;
        int c0 = (tid & 3) * 16;
        const float* qp = &g_q[(size_t)(b * Nn + qt * 64 + r) * HC + h * Cc + c0];
#pragma unroll
        for (int u = 0; u < 4; u++)
            *(float4*)&Qs[r * TW + c0 + u * 4] = *(const float4*)&qp[u * 4];
    }

    const int* sb = seg + b * Nn;
    const int segA = sb[qt * 64];
    int kt_start = 0;
    while (kt_start < qt && sb[kt_start * 64 + 63] < segA) kt_start++;

    int   my_seg[4];
    float m_run[4], l_run[4];
    float O[4][4];
#pragma unroll
    for (int i = 0; i < 4; i++) {
        my_seg[i] = sb[qt * 64 + tr * 4 + i];
        m_run[i] = -INFINITY;
        l_run[i] = 0.f;
#pragma unroll
        for (int j = 0; j < 4; j++) O[i][j] = 0.f;
    }
    __syncthreads();   // Qs ready

    for (int kt = kt_start; kt <= qt; kt++) {
        const float* kbase = &g_k[(size_t)(b * Nn + kt * 64) * HC + h * Cc];
        const float* vbase = &g_v[(size_t)(b * Nn + kt * 64) * HC + h * Cc];
#pragma unroll
        for (int t = tid; t < 1024; t += 256) {
            int r  = t >> 4;
            int c4 = (t & 15) * 4;
            float4 kk = *(const float4*)&kbase[(size_t)r * HC + c4];
            Ks[(c4 + 0) * TW + r] = kk.x;
            Ks[(c4 + 1) * TW + r] = kk.y;
            Ks[(c4 + 2) * TW + r] = kk.z;
            Ks[(c4 + 3) * TW + r] = kk.w;
            *(float4*)&Vs[r * TW + c4] = *(const float4*)&vbase[(size_t)r * HC + c4];
        }
        if (tid < 64) seg_s[tid] = sb[kt * 64 + tid];
        __syncthreads();

        float S[4][4];
#pragma unroll
        for (int i = 0; i < 4; i++)
#pragma unroll
            for (int j = 0; j < 4; j++) S[i][j] = 0.f;

#pragma unroll 8
        for (int cc = 0; cc < 64; cc++) {
            float qf[4];
#pragma unroll
            for (int i = 0; i < 4; i++) qf[i] = Qs[(tr * 4 + i) * TW + cc];
            float4 kf4 = *(const float4*)&Ks[cc * TW + tc * 4];
            float kf[4] = { kf4.x, kf4.y, kf4.z, kf4.w };
#pragma unroll
            for (int i = 0; i < 4; i++)
#pragma unroll
                for (int j = 0; j < 4; j++)
                    S[i][j] = fmaf(qf[i], kf[j], S[i][j]);
        }

        float mx[4];
#pragma unroll
        for (int i = 0; i < 4; i++) {
            int row = qt * 64 + tr * 4 + i;
            const __half2* bp = (const __half2*)&g_biash[
                ((size_t)(b * Hh + h) * Nn + row) * Nn + kt * 64 + tc * 4];
            float2 b01 = __half22float2(bp[0]);
            float2 b23 = __half22float2(bp[1]);
            float bb[4] = { b01.x, b01.y, b23.x, b23.y };
            mx[i] = -INFINITY;
#pragma unroll
            for (int j = 0; j < 4; j++) {
                int key = kt * 64 + tc * 4 + j;
                bool ok = (key <= row) && (seg_s[tc * 4 + j] == my_seg[i]);
                S[i][j] = ok ? fmaf(S[i][j], sm_scale, bb[j]) : -INFINITY;
                mx[i] = fmaxf(mx[i], S[i][j]);
            }
        }
#pragma unroll
        for (int s = 8; s >= 1; s >>= 1)
#pragma unroll
            for (int i = 0; i < 4; i++)
                mx[i] = fmaxf(mx[i], __shfl_xor_sync(0xffffffffu, mx[i], s, 16));

#pragma unroll
        for (int i = 0; i < 4; i++) {
            float m_new = fmaxf(m_run[i], mx[i]);
            bool  dead  = (m_new == -INFINITY);
            float m_use = dead ? 0.f : m_new;
            float alpha = __expf(m_run[i] - m_use);
            float ps = 0.f;
            float p[4];
#pragma unroll
            for (int j = 0; j < 4; j++) {
                p[j] = __expf(S[i][j] - m_use);
                ps += p[j];
            }
#pragma unroll
            for (int s = 8; s >= 1; s >>= 1)
                ps += __shfl_xor_sync(0xffffffffu, ps, s, 16);
            l_run[i] = l_run[i] * alpha + ps;
            m_run[i] = m_new;
#pragma unroll
            for (int j = 0; j < 4; j++) {
                O[i][j] *= alpha;
                Ps[(tr * 4 + i) * TW + tc * 4 + j] = p[j];
            }
        }
        __syncthreads();   // Ps visible

#pragma unroll 8
        for (int jj = 0; jj < 64; jj++) {
            float pf[4];
#pragma unroll
            for (int i = 0; i < 4; i++) pf[i] = Ps[(tr * 4 + i) * TW + jj];
            float4 vf4 = *(const float4*)&Vs[jj * TW + tc * 4];
            float vf[4] = { vf4.x, vf4.y, vf4.z, vf4.w };
#pragma unroll
            for (int i = 0; i < 4; i++)
#pragma unroll
                for (int j = 0; j < 4; j++)
                    O[i][j] = fmaf(pf[i], vf[j], O[i][j]);
        }
        __syncthreads();   // tiles free for next kt
    }

#pragma unroll
    for (int i = 0; i < 4; i++) {
        int row = qt * 64 + tr * 4 + i;
        float inv = 1.f / l_run[i];
        float4 o4 = make_float4(O[i][0] * inv, O[i][1] * inv,
                                O[i][2] * inv, O[i][3] * inv);
        *(float4*)&out[(size_t)(b * Nn + row) * HC + h * Cc + tc * 4] = o4;
    }
}

// ---------------------------------------------------------------------------
extern "C" void kernel_launch(void* const* d_in, const int* in_sizes, int n_in,
                              void* d_out, int out_size)
{
    const float* s    = (const float*)d_in[0];
    const float* pair = (const float*)d_in[1];
    const int*   seg  = (const int*)d_in[2];
    const int*   pos  = (const int*)d_in[3];
    const float* Wq   = (const float*)d_in[4];
    const float* Wk   = (const float*)d_in[5];
    const float* Wv   = (const float*)d_in[6];
    const float* Wb   = (const float*)d_in[7];
    float* out = (float*)d_out;

    cudaFuncSetAttribute(attn_kernel,
                         cudaFuncAttributeMaxDynamicSharedMemorySize, ATTN_SMEM);

    conv_s_kernel<<<(Mrows * FS) / 256, 256>>>(s);
    conv_w_kernel<<<dim3(HC / 32, FS / 32, 3), dim3(32, 8)>>>(Wq, Wk, Wv);
    qkv_mma_kernel<<<dim3(HC / 128, Mrows / 128, 3), 256>>>();
    rope_kernel<<<(Bb * Nn * Hh * 32) / 256, 256>>>(pos);
    bias_kernel<<<dim3(Nn / 64, Nn / 4, Bb), 256>>>(pair, Wb, seg);
    attn_kernel<<<dim3(Nn / 64, Hh, Bb), 256, ATTN_SMEM>>>(seg, out);
}

// round 13
// speedup vs baseline: 7.5127x; 1.3948x over previous
#include <cuda_runtime.h>
#include <cuda_fp16.h>
#include <math.h>
#include <stdint.h>

#define Bb 2
#define Nn 1024
#define FS 1024
#define FZ 64
#define Hh 16
#define Cc 64
#define HC (Hh*Cc)          // 1024
#define Mrows (Bb*Nn)       // 2048

// ---------------- scratch (static device globals; no allocations) ----------
__device__ __half g_biash[(size_t)Bb*Hh*Nn*Nn];  // 64MB fp16 bias

// fp16 tensors
__device__ __half g_sh[(size_t)Mrows*FS];        // s  [m][k]
__device__ __half g_wh[(size_t)3*HC*FS];         // W^T [mat][n][k]
__device__ __half g_qh[(size_t)Mrows*HC];        // q  [b,n,h,c] (rope applied later)
__device__ __half g_kh[(size_t)Mrows*HC];        // k  [b,n,h,c]
__device__ __half g_vt[(size_t)Bb*Hh*Cc*Nn];     // v^T [b,h,c,n]

// ======================= helpers ===========================================
static __device__ __forceinline__ uint32_t smem_u32(const void* p) {
    uint32_t a;
    asm("{ .reg .u64 t; cvta.to.shared.u64 t, %1; cvt.u32.u64 %0, t; }"
        : "=r"(a) : "l"(p));
    return a;
}
static __device__ __forceinline__ void cp16(uint32_t dst, const void* src) {
    asm volatile("cp.async.cg.shared.global [%0], [%1], 16;"
                 :: "r"(dst), "l"(src) : "memory");
}
static __device__ __forceinline__ void cp_commit() {
    asm volatile("cp.async.commit_group;" ::: "memory");
}
static __device__ __forceinline__ void ldmx4(uint32_t* r, uint32_t addr) {
    asm volatile("ldmatrix.sync.aligned.m8n8.x4.shared.b16 {%0,%1,%2,%3}, [%4];"
                 : "=r"(r[0]), "=r"(r[1]), "=r"(r[2]), "=r"(r[3]) : "r"(addr));
}

#define MMA16816(d, a, b0v, b1v)                                              \
    asm volatile("mma.sync.aligned.m16n8k16.row.col.f32.f16.f16.f32 "         \
                 "{%0,%1,%2,%3}, {%4,%5,%6,%7}, {%8,%9}, {%0,%1,%2,%3};"      \
                 : "+f"((d)[0]), "+f"((d)[1]), "+f"((d)[2]), "+f"((d)[3])     \
                 : "r"((a)[0]), "r"((a)[1]), "r"((a)[2]), "r"((a)[3]),        \
                   "r"(b0v), "r"(b1v))

// ---------------- conversion kernels ---------------------------------------
__global__ void conv_s_kernel(const float* __restrict__ s) {
    int i = blockIdx.x * 256 + threadIdx.x;
    g_sh[i] = __float2half(s[i]);
}

__global__ void conv_w_kernel(const float* __restrict__ Wq,
                              const float* __restrict__ Wk,
                              const float* __restrict__ Wv) {
    __shared__ float t[32][33];
    const float* W = (blockIdx.z == 0) ? Wq : (blockIdx.z == 1) ? Wk : Wv;
    int n0 = blockIdx.x * 32;
    int k0 = blockIdx.y * 32;
    int tx = threadIdx.x, ty = threadIdx.y;
#pragma unroll
    for (int i = 0; i < 32; i += 8)
        t[ty + i][tx] = W[(size_t)(k0 + ty + i) * HC + n0 + tx];
    __syncthreads();
#pragma unroll
    for (int i = 0; i < 32; i += 8) {
        size_t idx = ((size_t)(blockIdx.z * HC + n0 + ty + i)) * FS + k0 + tx;
        g_wh[idx] = __float2half(t[tx][ty + i]);
    }
}

// ---------------- QKV projection via mma.sync (HMMA), fp16 outputs ----------
#define QSTG 3
#define STG_HALF (128 * 32)

__global__ __launch_bounds__(256) void qkv_mma_kernel()
{
    __shared__ __align__(16) __half As[QSTG][STG_HALF];
    __shared__ __align__(16) __half Bs[QSTG][STG_HALF];

    const int tid  = threadIdx.x;
    const int col0 = blockIdx.x * 128;
    const int row0 = blockIdx.y * 128;
    const int mat  = blockIdx.z;

    const __half* Ag = g_sh + (size_t)row0 * FS;
    const __half* Bg = g_wh + (size_t)(mat * HC + col0) * FS;

    const uint32_t aS = smem_u32(As);
    const uint32_t bS = smem_u32(Bs);

    const int r   = tid >> 1;
    const int c20 = (tid & 1) * 2;
    const int rx  = (r >> 1) & 3;

    const int w    = tid >> 5;
    const int lane = tid & 31;
    const int gid  = lane >> 2;
    const int tig  = lane & 3;
    const int wm   = w & 3;
    const int wn   = w >> 2;
    const int lr   = lane & 15;
    const int lh   = lane >> 4;

    float acc[2][8][4];
#pragma unroll
    for (int mf = 0; mf < 2; mf++)
#pragma unroll
        for (int nf = 0; nf < 8; nf++)
#pragma unroll
            for (int i = 0; i < 4; i++) acc[mf][nf][i] = 0.f;

    auto issue = [&](int c, int stg) {
        const __half* as = Ag + (size_t)r * FS + c * 32 + c20 * 8;
        const __half* bs = Bg + (size_t)r * FS + c * 32 + c20 * 8;
        uint32_t arow = aS + (uint32_t)(stg * STG_HALF * 2 + r * 64);
        uint32_t brow = bS + (uint32_t)(stg * STG_HALF * 2 + r * 64);
        cp16(arow + (((c20 + 0) ^ rx) << 4), as);
        cp16(arow + (((c20 + 1) ^ rx) << 4), as + 8);
        cp16(brow + (((c20 + 0) ^ rx) << 4), bs);
        cp16(brow + (((c20 + 1) ^ rx) << 4), bs + 8);
    };

    issue(0, 0); cp_commit();
    issue(1, 1); cp_commit();

#pragma unroll 1
    for (int c = 0; c < 32; ++c) {
        if (c < 31) asm volatile("cp.async.wait_group 1;" ::: "memory");
        else        asm volatile("cp.async.wait_group 0;" ::: "memory");
        __syncthreads();

        if (c + 2 < 32) { issue(c + 2, (c + 2) % QSTG); cp_commit(); }

        const int stg = c % QSTG;
        const uint32_t sA = aS + (uint32_t)(stg * STG_HALF * 2);
        const uint32_t sB = bS + (uint32_t)(stg * STG_HALF * 2);

#pragma unroll
        for (int kk = 0; kk < 32; kk += 16) {
            const int cb = (kk >> 3) + lh;
            uint32_t a[2][4];
#pragma unroll
            for (int mf = 0; mf < 2; ++mf) {
                int R = wm * 32 + mf * 16 + lr;
                ldmx4(a[mf], sA + (uint32_t)(R * 64 + ((cb ^ ((R >> 1) & 3)) << 4)));
            }
            uint32_t bf4[4][4];
#pragma unroll
            for (int np = 0; np < 4; ++np) {
                int R = wn * 64 + np * 16 + lr;
                ldmx4(bf4[np], sB + (uint32_t)(R * 64 + ((cb ^ ((R >> 1) & 3)) << 4)));
            }
#pragma unroll
            for (int np = 0; np < 4; ++np) {
                MMA16816(acc[0][2 * np + 0], a[0], bf4[np][0], bf4[np][2]);
                MMA16816(acc[1][2 * np + 0], a[1], bf4[np][0], bf4[np][2]);
                MMA16816(acc[0][2 * np + 1], a[0], bf4[np][1], bf4[np][3]);
                MMA16816(acc[1][2 * np + 1], a[1], bf4[np][1], bf4[np][3]);
            }
        }
    }

    // epilogue: fp16 outputs; v goes out transposed per (b,h)
    if (mat < 2) {
        __half* Oh = (mat == 0) ? g_qh : g_kh;
#pragma unroll
        for (int mf = 0; mf < 2; ++mf)
#pragma unroll
            for (int nf = 0; nf < 8; ++nf) {
                int row = row0 + wm * 32 + mf * 16 + gid;
                int col = col0 + wn * 64 + nf * 8 + 2 * tig;
                __half* d0 = Oh + (size_t)row * HC + col;
                *(__half2*)d0 = __floats2half2_rn(acc[mf][nf][0], acc[mf][nf][1]);
                *(__half2*)(d0 + 8 * HC) = __floats2half2_rn(acc[mf][nf][2], acc[mf][nf][3]);
            }
    } else {
#pragma unroll
        for (int mf = 0; mf < 2; ++mf)
#pragma unroll
            for (int nf = 0; nf < 8; ++nf) {
                int row = row0 + wm * 32 + mf * 16 + gid;
                int col = col0 + wn * 64 + nf * 8 + 2 * tig;
                int bz = row >> 10, n = row & 1023;
                int hh = col >> 6, cc = col & 63;
                __half* base = g_vt + ((size_t)(bz * Hh + hh) * Cc + cc) * Nn + n;
                base[0]      = __float2half(acc[mf][nf][0]);
                base[Nn]     = __float2half(acc[mf][nf][1]);
                base[8]      = __float2half(acc[mf][nf][2]);
                base[Nn + 8] = __float2half(acc[mf][nf][3]);
            }
    }
}

// ---------------- RoPE on g_qh and g_kh, in place (fp16 data, fp32 math) ----
__global__ void rope_kernel(const int* __restrict__ positions)
{
    int idx = blockIdx.x * blockDim.x + threadIdx.x;
    int i = idx & 31;
    int h = (idx >> 5) & 15;
    int n = (idx >> 9) & 1023;
    int b = idx >> 19;

    int pos = positions[b * Nn + n];
    float inv_ts = exp2f(-0.41524101186092029f * (float)i);
    float ang = (float)pos * inv_ts;
    float sn, cs;
    sincosf(ang, &sn, &cs);

    size_t base = (size_t)(b * Nn + n) * HC + h * Cc;
    float q1 = __half2float(g_qh[base + i]), q2 = __half2float(g_qh[base + 32 + i]);
    g_qh[base + i]      = __float2half(q1 * cs - q2 * sn);
    g_qh[base + 32 + i] = __float2half(q2 * cs + q1 * sn);
    float k1 = __half2float(g_kh[base + i]), k2 = __half2float(g_kh[base + 32 + i]);
    g_kh[base + i]      = __float2half(k1 * cs - k2 * sn);
    g_kh[base + 32 + i] = __float2half(k2 * cs + k1 * sn);
}

// ---------------- bias (fp16 out), masked-region skip -----------------------
__global__ __launch_bounds__(256) void bias_kernel(const float* __restrict__ pair,
                                                   const float* __restrict__ Wb,
                                                   const int* __restrict__ seg)
{
    const int kt = blockIdx.x;
    const int q0 = blockIdx.y * 4;
    const int b  = blockIdx.z;

    if (kt > (q0 >> 6)) return;
    const int* sb = seg + b * Nn;
    if (sb[kt * 64 + 63] < sb[q0] || sb[kt * 64] > sb[q0 + 3]) return;

    __shared__ float Wb_s[FZ][Hh];
    for (int i = threadIdx.x; i < FZ * Hh; i += 256)
        Wb_s[i >> 4][i & 15] = Wb[i];
    __syncthreads();

    const int q = q0 + (threadIdx.x >> 6);
    const int k = kt * 64 + (threadIdx.x & 63);

    const float4* pp = (const float4*)&pair[((size_t)(b * Nn + q) * Nn + k) * FZ];

    float acc[Hh];
#pragma unroll
    for (int h = 0; h < Hh; h++) acc[h] = 0.f;

#pragma unroll
    for (int f4 = 0; f4 < FZ / 4; f4++) {
        float4 p = pp[f4];
#pragma unroll
        for (int h = 0; h < Hh; h++) {
            acc[h] += p.x * Wb_s[4 * f4 + 0][h];
            acc[h] += p.y * Wb_s[4 * f4 + 1][h];
            acc[h] += p.z * Wb_s[4 * f4 + 2][h];
            acc[h] += p.w * Wb_s[4 * f4 + 3][h];
        }
    }
#pragma unroll
    for (int h = 0; h < Hh; h++)
        g_biash[((size_t)(b * Hh + h) * Nn + q) * Nn + k] = __float2half(acc[h]);
}

// ---------------- flash attention (HMMA) ------------------------------------
// 8 warps: wm = w&3 (rows wm*16..+15), wn = w>>2 (S cols wn*32..+31).
// Dynamic smem: Q[8KB] | buf{0,1}: K[8KB] + Vt[8KB] + bias[64x144B=9216B]
#define ATT_BUF  25600
#define ATT_SMEM (8192 + 2 * ATT_BUF)   // 59392

__global__ __launch_bounds__(256, 2) void attn_kernel(const int* __restrict__ seg,
                                                      float* __restrict__ out)
{
    extern __shared__ char sm[];
    __shared__ float smax[64][2];
    __shared__ float ssum[64][2];
    __shared__ int   seg_s[64];

    const int tid  = threadIdx.x;
    const int w    = tid >> 5, lane = tid & 31;
    const int gid  = lane >> 2, tig = lane & 3;
    const int wm   = w & 3, wn = w >> 2;
    const int lr   = lane & 15, lh = lane >> 4;
    const int qt   = gridDim.x - 1 - blockIdx.x;
    const int h    = blockIdx.y, b = blockIdx.z;
    const uint32_t smb = smem_u32(sm);

    const int* sb = seg + b * Nn;
    const int segA = sb[qt * 64];
    int kt_start = 0;
    while (kt_start < qt && sb[kt_start * 64 + 63] < segA) kt_start++;

    const int lrow = tid >> 2;
    const int cp0  = (tid & 3) * 2;

    // Q tile load (swizzled, once)
    {
        const __half* src = g_qh + (size_t)(b * Nn + qt * 64 + lrow) * HC + h * Cc + cp0 * 8;
        uint32_t qd = smb + (uint32_t)(lrow * 128);
        cp16(qd + (((cp0 + 0) ^ (lrow & 7)) << 4), src);
        cp16(qd + (((cp0 + 1) ^ (lrow & 7)) << 4), src + 8);
    }
    auto issue_tile = [&](int kt, int bf) {
        uint32_t base = smb + 8192u + (uint32_t)bf * ATT_BUF;
        const __half* ks = g_kh + (size_t)(b * Nn + kt * 64 + lrow) * HC + h * Cc + cp0 * 8;
        cp16(base + (uint32_t)(lrow * 128) + (((cp0 + 0) ^ (lrow & 7)) << 4), ks);
        cp16(base + (uint32_t)(lrow * 128) + (((cp0 + 1) ^ (lrow & 7)) << 4), ks + 8);
        const __half* vs = g_vt + ((size_t)(b * Hh + h) * Cc + lrow) * Nn + kt * 64 + cp0 * 8;
        cp16(base + 8192u + (uint32_t)(lrow * 128) + (((cp0 + 0) ^ (lrow & 7)) << 4), vs);
        cp16(base + 8192u + (uint32_t)(lrow * 128) + (((cp0 + 1) ^ (lrow & 7)) << 4), vs + 8);
        const __half* bs = g_biash + ((size_t)(b * Hh + h) * Nn + qt * 64 + lrow) * Nn + kt * 64 + cp0 * 8;
        cp16(base + 16384u + (uint32_t)(lrow * 144 + cp0 * 16), bs);
        cp16(base + 16384u + (uint32_t)(lrow * 144 + cp0 * 16 + 16), bs + 8);
    };

    issue_tile(kt_start, 0); cp_commit();
    if (kt_start + 1 <= qt) { issue_tile(kt_start + 1, 1); cp_commit(); }

    float Oacc[8][4];
#pragma unroll
    for (int nf = 0; nf < 8; nf++)
#pragma unroll
        for (int i = 0; i < 4; i++) Oacc[nf][i] = 0.f;

    const int r0l = wm * 16 + gid, r1l = r0l + 8;
    const int rowg0 = qt * 64 + r0l, rowg1 = qt * 64 + r1l;
    const int myseg0 = sb[rowg0], myseg1 = sb[rowg1];
    float m_run0 = -INFINITY, m_run1 = -INFINITY;
    float l_run0 = 0.f, l_run1 = 0.f;
    const float sc = 0.125f;

#pragma unroll 1
    for (int kt = kt_start; kt <= qt; kt++) {
        const int bf = (kt - kt_start) & 1;
        if (kt + 1 <= qt) asm volatile("cp.async.wait_group 1;" ::: "memory");
        else              asm volatile("cp.async.wait_group 0;" ::: "memory");
        if (tid < 64) seg_s[tid] = sb[kt * 64 + tid];
        __syncthreads();

        const uint32_t Kb = smb + 8192u + (uint32_t)bf * ATT_BUF;
        const uint32_t Vb = Kb + 8192u;
        const __half* biasb = (const __half*)(sm + 8192 + bf * ATT_BUF + 16384);

        // ---- S = Q K^T ----
        float Sa[4][4];
#pragma unroll
        for (int j = 0; j < 4; j++)
#pragma unroll
            for (int i = 0; i < 4; i++) Sa[j][i] = 0.f;

#pragma unroll
        for (int ks = 0; ks < 4; ks++) {
            uint32_t a[4];
            {
                int R = wm * 16 + lr, cb = 2 * ks + lh;
                ldmx4(a, smb + (uint32_t)(R * 128 + ((cb ^ (R & 7)) << 4)));
            }
#pragma unroll
            for (int np = 0; np < 2; np++) {
                uint32_t bk[4];
                int R = wn * 32 + np * 16 + lr, cb = 2 * ks + lh;
                ldmx4(bk, Kb + (uint32_t)(R * 128 + ((cb ^ (R & 7)) << 4)));
                MMA16816(Sa[2 * np + 0], a, bk[0], bk[2]);
                MMA16816(Sa[2 * np + 1], a, bk[1], bk[3]);
            }
        }

        // ---- bias + mask + scale, partial rowmax ----
        float mx0 = -INFINITY, mx1 = -INFINITY;
#pragma unroll
        for (int j = 0; j < 4; j++) {
            int keyl = wn * 32 + j * 8 + 2 * tig;
            int keyg = kt * 64 + keyl;
            float2 bf0 = __half22float2(*(const __half2*)&biasb[r0l * 72 + keyl]);
            float2 bf1 = __half22float2(*(const __half2*)&biasb[r1l * 72 + keyl]);
            int sg0 = seg_s[keyl], sg1 = seg_s[keyl + 1];
            bool ok00 = (keyg     <= rowg0) && (sg0 == myseg0);
            bool ok01 = (keyg + 1 <= rowg0) && (sg1 == myseg0);
            bool ok10 = (keyg     <= rowg1) && (sg0 == myseg1);
            bool ok11 = (keyg + 1 <= rowg1) && (sg1 == myseg1);
            Sa[j][0] = ok00 ? fmaf(Sa[j][0], sc, bf0.x) : -INFINITY;
            Sa[j][1] = ok01 ? fmaf(Sa[j][1], sc, bf0.y) : -INFINITY;
            Sa[j][2] = ok10 ? fmaf(Sa[j][2], sc, bf1.x) : -INFINITY;
            Sa[j][3] = ok11 ? fmaf(Sa[j][3], sc, bf1.y) : -INFINITY;
            mx0 = fmaxf(mx0, fmaxf(Sa[j][0], Sa[j][1]));
            mx1 = fmaxf(mx1, fmaxf(Sa[j][2], Sa[j][3]));
        }
        mx0 = fmaxf(mx0, __shfl_xor_sync(0xffffffffu, mx0, 1));
        mx0 = fmaxf(mx0, __shfl_xor_sync(0xffffffffu, mx0, 2));
        mx1 = fmaxf(mx1, __shfl_xor_sync(0xffffffffu, mx1, 1));
        mx1 = fmaxf(mx1, __shfl_xor_sync(0xffffffffu, mx1, 2));
        if (tig == 0) { smax[r0l][wn] = mx0; smax[r1l][wn] = mx1; }
        __syncthreads();

        float mt0 = fmaxf(smax[r0l][0], smax[r0l][1]);
        float mt1 = fmaxf(smax[r1l][0], smax[r1l][1]);
        float mn0 = fmaxf(m_run0, mt0), mn1 = fmaxf(m_run1, mt1);
        float mu0 = (mn0 == -INFINITY) ? 0.f : mn0;
        float mu1 = (mn1 == -INFINITY) ? 0.f : mn1;
        float al0 = __expf(m_run0 - mu0), al1 = __expf(m_run1 - mu1);

        float ps0 = 0.f, ps1 = 0.f;
        uint32_t pa[2][4];
#pragma unroll
        for (int jj = 0; jj < 2; jj++) {
            float p[2][4];
#pragma unroll
            for (int d = 0; d < 2; d++) {
                int j = 2 * jj + d;
                p[d][0] = __expf(Sa[j][0] - mu0);
                p[d][1] = __expf(Sa[j][1] - mu0);
                p[d][2] = __expf(Sa[j][2] - mu1);
                p[d][3] = __expf(Sa[j][3] - mu1);
                ps0 += p[d][0] + p[d][1];
                ps1 += p[d][2] + p[d][3];
            }
            pa[jj][0] = __half2_raw(__floats2half2_rn(p[0][0], p[0][1])).x |
                        ((uint32_t)__half2_raw(__floats2half2_rn(p[0][0], p[0][1])).y << 16);
            // (use direct reinterpret instead below)
            __half2 h0 = __floats2half2_rn(p[0][0], p[0][1]);
            __half2 h1 = __floats2half2_rn(p[0][2], p[0][3]);
            __half2 h2v = __floats2half2_rn(p[1][0], p[1][1]);
            __half2 h3 = __floats2half2_rn(p[1][2], p[1][3]);
            pa[jj][0] = *(uint32_t*)&h0;
            pa[jj][1] = *(uint32_t*)&h1;
            pa[jj][2] = *(uint32_t*)&h2v;
            pa[jj][3] = *(uint32_t*)&h3;
        }
        ps0 += __shfl_xor_sync(0xffffffffu, ps0, 1);
        ps0 += __shfl_xor_sync(0xffffffffu, ps0, 2);
        ps1 += __shfl_xor_sync(0xffffffffu, ps1, 1);
        ps1 += __shfl_xor_sync(0xffffffffu, ps1, 2);
        if (tig == 0) { ssum[r0l][wn] = ps0; ssum[r1l][wn] = ps1; }

#pragma unroll
        for (int nf = 0; nf < 8; nf++) {
            Oacc[nf][0] *= al0; Oacc[nf][1] *= al0;
            Oacc[nf][2] *= al1; Oacc[nf][3] *= al1;
        }
        __syncthreads();
        l_run0 = l_run0 * al0 + ssum[r0l][0] + ssum[r0l][1];
        l_run1 = l_run1 * al1 + ssum[r1l][0] + ssum[r1l][1];
        m_run0 = mn0; m_run1 = mn1;

        // ---- O += P V ----
#pragma unroll
        for (int ks2 = 0; ks2 < 2; ks2++) {
#pragma unroll
            for (int np2 = 0; np2 < 4; np2++) {
                uint32_t bv[4];
                int R = np2 * 16 + lr, cb = wn * 4 + ks2 * 2 + lh;
                ldmx4(bv, Vb + (uint32_t)(R * 128 + ((cb ^ (R & 7)) << 4)));
                MMA16816(Oacc[2 * np2 + 0], pa[ks2], bv[0], bv[2]);
                MMA16816(Oacc[2 * np2 + 1], pa[ks2], bv[1], bv[3]);
            }
        }

        __syncthreads();   // all reads of buffer bf done
        if (kt + 2 <= qt) { issue_tile(kt + 2, bf); cp_commit(); }
    }

    // ---- epilogue: combine wn partials via smem ----
    float inv0 = 1.f / l_run0, inv1 = 1.f / l_run1;
    float* Osm = (float*)sm;   // [64][68]
    if (wn == 1) {
#pragma unroll
        for (int nf = 0; nf < 8; nf++) {
            int c = nf * 8 + 2 * tig;
            *(float2*)&Osm[r0l * 68 + c] = make_float2(Oacc[nf][0], Oacc[nf][1]);
            *(float2*)&Osm[r1l * 68 + c] = make_float2(Oacc[nf][2], Oacc[nf][3]);
        }
    }
    __syncthreads();
    if (wn == 0) {
#pragma unroll
        for (int nf = 0; nf < 8; nf++) {
            int c = nf * 8 + 2 * tig;
            float2 o0 = *(float2*)&Osm[r0l * 68 + c];
            float2 o1 = *(float2*)&Osm[r1l * 68 + c];
            float* d0 = out + (size_t)(b * Nn + rowg0) * HC + h * Cc + c;
            float* d1 = out + (size_t)(b * Nn + rowg1) * HC + h * Cc + c;
            *(float2*)d0 = make_float2((Oacc[nf][0] + o0.x) * inv0,
                                       (Oacc[nf][1] + o0.y) * inv0);
            *(float2*)d1 = make_float2((Oacc[nf][2] + o1.x) * inv1,
                                       (Oacc[nf][3] + o1.y) * inv1);
        }
    }
}

// ---------------------------------------------------------------------------
extern "C" void kernel_launch(void* const* d_in, const int* in_sizes, int n_in,
                              void* d_out, int out_size)
{
    const float* s    = (const float*)d_in[0];
    const float* pair = (const float*)d_in[1];
    const int*   seg  = (const int*)d_in[2];
    const int*   pos  = (const int*)d_in[3];
    const float* Wq   = (const float*)d_in[4];
    const float* Wk   = (const float*)d_in[5];
    const float* Wv   = (const float*)d_in[6];
    const float* Wb   = (const float*)d_in[7];
    float* out = (float*)d_out;

    cudaFuncSetAttribute(attn_kernel,
                         cudaFuncAttributeMaxDynamicSharedMemorySize, ATT_SMEM);

    conv_s_kernel<<<(Mrows * FS) / 256, 256>>>(s);
    conv_w_kernel<<<dim3(HC / 32, FS / 32, 3), dim3(32, 8)>>>(Wq, Wk, Wv);
    qkv_mma_kernel<<<dim3(HC / 128, Mrows / 128, 3), 256>>>();
    rope_kernel<<<(Bb * Nn * Hh * 32) / 256, 256>>>(pos);
    bias_kernel<<<dim3(Nn / 64, Nn / 4, Bb), 256>>>(pair, Wb, seg);
    attn_kernel<<<dim3(Nn / 64, Hh, Bb), 256, ATT_SMEM>>>(seg, out);
}

// round 14
// speedup vs baseline: 7.6930x; 1.0240x over previous
#include <cuda_runtime.h>
#include <cuda_fp16.h>
#include <math.h>
#include <stdint.h>

#define Bb 2
#define Nn 1024
#define FS 1024
#define FZ 64
#define Hh 16
#define Cc 64
#define HC (Hh*Cc)          // 1024
#define Mrows (Bb*Nn)       // 2048

// ---------------- scratch (static device globals; no allocations) ----------
__device__ __half g_biash[(size_t)Bb*Hh*Nn*Nn];  // 64MB fp16 bias

// fp16 tensors
__device__ __half g_sh[(size_t)Mrows*FS];        // s  [m][k]
__device__ __half g_wh[(size_t)3*HC*FS];         // W^T [mat][n][k]
__device__ __half g_qh[(size_t)Mrows*HC];        // q (rope applied) [b,n,h,c]
__device__ __half g_kh[(size_t)Mrows*HC];        // k (rope applied) [b,n,h,c]
__device__ __half g_vt[(size_t)Bb*Hh*Cc*Nn];     // v^T [b,h,c,n]
__device__ float2 g_ropetab[(size_t)Mrows*32];   // (sin,cos) per (row, freq)

// ======================= helpers ===========================================
static __device__ __forceinline__ uint32_t smem_u32(const void* p) {
    uint32_t a;
    asm("{ .reg .u64 t; cvta.to.shared.u64 t, %1; cvt.u32.u64 %0, t; }"
        : "=r"(a) : "l"(p));
    return a;
}
static __device__ __forceinline__ void cp16(uint32_t dst, const void* src) {
    asm volatile("cp.async.cg.shared.global [%0], [%1], 16;"
                 :: "r"(dst), "l"(src) : "memory");
}
static __device__ __forceinline__ void cp_commit() {
    asm volatile("cp.async.commit_group;" ::: "memory");
}
static __device__ __forceinline__ void ldmx4(uint32_t* r, uint32_t addr) {
    asm volatile("ldmatrix.sync.aligned.m8n8.x4.shared.b16 {%0,%1,%2,%3}, [%4];"
                 : "=r"(r[0]), "=r"(r[1]), "=r"(r[2]), "=r"(r[3]) : "r"(addr));
}

#define MMA16816(d, a, b0v, b1v)                                              \
    asm volatile("mma.sync.aligned.m16n8k16.row.col.f32.f16.f16.f32 "         \
                 "{%0,%1,%2,%3}, {%4,%5,%6,%7}, {%8,%9}, {%0,%1,%2,%3};"      \
                 : "+f"((d)[0]), "+f"((d)[1]), "+f"((d)[2]), "+f"((d)[3])     \
                 : "r"((a)[0]), "r"((a)[1]), "r"((a)[2]), "r"((a)[3]),        \
                   "r"(b0v), "r"(b1v))

// ---------------- conversion / table kernels --------------------------------
__global__ void conv_s_kernel(const float* __restrict__ s) {
    int i = blockIdx.x * 256 + threadIdx.x;
    g_sh[i] = __float2half(s[i]);
}

__global__ void conv_w_kernel(const float* __restrict__ Wq,
                              const float* __restrict__ Wk,
                              const float* __restrict__ Wv) {
    __shared__ float t[32][33];
    const float* W = (blockIdx.z == 0) ? Wq : (blockIdx.z == 1) ? Wk : Wv;
    int n0 = blockIdx.x * 32;
    int k0 = blockIdx.y * 32;
    int tx = threadIdx.x, ty = threadIdx.y;
#pragma unroll
    for (int i = 0; i < 32; i += 8)
        t[ty + i][tx] = W[(size_t)(k0 + ty + i) * HC + n0 + tx];
    __syncthreads();
#pragma unroll
    for (int i = 0; i < 32; i += 8) {
        size_t idx = ((size_t)(blockIdx.z * HC + n0 + ty + i)) * FS + k0 + tx;
        g_wh[idx] = __float2half(t[tx][ty + i]);
    }
}

__global__ void ropetab_kernel(const int* __restrict__ positions) {
    int idx = blockIdx.x * 256 + threadIdx.x;   // Mrows*32 = 65536
    int i = idx & 31;
    int r = idx >> 5;
    int pos = positions[r];
    float inv_ts = exp2f(-0.41524101186092029f * (float)i);
    float sn, cs;
    sincosf((float)pos * inv_ts, &sn, &cs);
    g_ropetab[idx] = make_float2(sn, cs);
}

// ---------------- QKV projection via mma.sync (HMMA), rope fused ------------
#define QSTG 3
#define STG_HALF (128 * 32)

__global__ __launch_bounds__(256) void qkv_mma_kernel()
{
    __shared__ __align__(16) __half As[QSTG][STG_HALF];
    __shared__ __align__(16) __half Bs[QSTG][STG_HALF];

    const int tid  = threadIdx.x;
    const int col0 = blockIdx.x * 128;
    const int row0 = blockIdx.y * 128;
    const int mat  = blockIdx.z;

    const __half* Ag = g_sh + (size_t)row0 * FS;
    const __half* Bg = g_wh + (size_t)(mat * HC + col0) * FS;

    const uint32_t aS = smem_u32(As);
    const uint32_t bS = smem_u32(Bs);

    const int r   = tid >> 1;
    const int c20 = (tid & 1) * 2;
    const int rx  = (r >> 1) & 3;

    const int w    = tid >> 5;
    const int lane = tid & 31;
    const int gid  = lane >> 2;
    const int tig  = lane & 3;
    const int wm   = w & 3;
    const int wn   = w >> 2;
    const int lr   = lane & 15;
    const int lh   = lane >> 4;

    float acc[2][8][4];
#pragma unroll
    for (int mf = 0; mf < 2; mf++)
#pragma unroll
        for (int nf = 0; nf < 8; nf++)
#pragma unroll
            for (int i = 0; i < 4; i++) acc[mf][nf][i] = 0.f;

    auto issue = [&](int c, int stg) {
        const __half* as = Ag + (size_t)r * FS + c * 32 + c20 * 8;
        const __half* bs = Bg + (size_t)r * FS + c * 32 + c20 * 8;
        uint32_t arow = aS + (uint32_t)(stg * STG_HALF * 2 + r * 64);
        uint32_t brow = bS + (uint32_t)(stg * STG_HALF * 2 + r * 64);
        cp16(arow + (((c20 + 0) ^ rx) << 4), as);
        cp16(arow + (((c20 + 1) ^ rx) << 4), as + 8);
        cp16(brow + (((c20 + 0) ^ rx) << 4), bs);
        cp16(brow + (((c20 + 1) ^ rx) << 4), bs + 8);
    };

    issue(0, 0); cp_commit();
    issue(1, 1); cp_commit();

#pragma unroll 1
    for (int c = 0; c < 32; ++c) {
        if (c < 31) asm volatile("cp.async.wait_group 1;" ::: "memory");
        else        asm volatile("cp.async.wait_group 0;" ::: "memory");
        __syncthreads();

        if (c + 2 < 32) { issue(c + 2, (c + 2) % QSTG); cp_commit(); }

        const int stg = c % QSTG;
        const uint32_t sA = aS + (uint32_t)(stg * STG_HALF * 2);
        const uint32_t sB = bS + (uint32_t)(stg * STG_HALF * 2);

#pragma unroll
        for (int kk = 0; kk < 32; kk += 16) {
            const int cb = (kk >> 3) + lh;
            uint32_t a[2][4];
#pragma unroll
            for (int mf = 0; mf < 2; ++mf) {
                int R = wm * 32 + mf * 16 + lr;
                ldmx4(a[mf], sA + (uint32_t)(R * 64 + ((cb ^ ((R >> 1) & 3)) << 4)));
            }
            uint32_t bf4[4][4];
#pragma unroll
            for (int np = 0; np < 4; ++np) {
                int R = wn * 64 + np * 16 + lr;
                ldmx4(bf4[np], sB + (uint32_t)(R * 64 + ((cb ^ ((R >> 1) & 3)) << 4)));
            }
#pragma unroll
            for (int np = 0; np < 4; ++np) {
                MMA16816(acc[0][2 * np + 0], a[0], bf4[np][0], bf4[np][2]);
                MMA16816(acc[1][2 * np + 0], a[1], bf4[np][0], bf4[np][2]);
                MMA16816(acc[0][2 * np + 1], a[0], bf4[np][1], bf4[np][3]);
                MMA16816(acc[1][2 * np + 1], a[1], bf4[np][1], bf4[np][3]);
            }
        }
    }

    // ---- epilogue ----
    if (mat < 2) {
        // q/k: apply rope on fp32 accumulators, then emit fp16.
        // Pair structure: acc[mf][nf] holds head cols i (=nf*8+2*tig, +1),
        // acc[mf][nf+4] holds cols i+32 — same thread owns both halves.
        __half* Oh = (mat == 0) ? g_qh : g_kh;
#pragma unroll
        for (int mf = 0; mf < 2; ++mf) {
            int rA = row0 + wm * 32 + mf * 16 + gid;
            int rB = rA + 8;
            const float2* tA = g_ropetab + (size_t)rA * 32;
            const float2* tB = g_ropetab + (size_t)rB * 32;
#pragma unroll
            for (int nf = 0; nf < 4; ++nf) {
                int i0 = nf * 8 + 2 * tig;
                float2 sA0 = tA[i0], sA1 = tA[i0 + 1];
                float2 sB0 = tB[i0], sB1 = tB[i0 + 1];
                float x1A0 = acc[mf][nf][0],     x1A1 = acc[mf][nf][1];
                float x1B0 = acc[mf][nf][2],     x1B1 = acc[mf][nf][3];
                float x2A0 = acc[mf][nf + 4][0], x2A1 = acc[mf][nf + 4][1];
                float x2B0 = acc[mf][nf + 4][2], x2B1 = acc[mf][nf + 4][3];
                // out1 = x1*cos - x2*sin ; out2 = x2*cos + x1*sin
                float o1A0 = x1A0 * sA0.y - x2A0 * sA0.x;
                float o2A0 = x2A0 * sA0.y + x1A0 * sA0.x;
                float o1A1 = x1A1 * sA1.y - x2A1 * sA1.x;
                float o2A1 = x2A1 * sA1.y + x1A1 * sA1.x;
                float o1B0 = x1B0 * sB0.y - x2B0 * sB0.x;
                float o2B0 = x2B0 * sB0.y + x1B0 * sB0.x;
                float o1B1 = x1B1 * sB1.y - x2B1 * sB1.x;
                float o2B1 = x2B1 * sB1.y + x1B1 * sB1.x;
                int col = col0 + wn * 64 + i0;
                __half* dA = Oh + (size_t)rA * HC + col;
                __half* dB = Oh + (size_t)rB * HC + col;
                *(__half2*)dA        = __floats2half2_rn(o1A0, o1A1);
                *(__half2*)(dA + 32) = __floats2half2_rn(o2A0, o2A1);
                *(__half2*)dB        = __floats2half2_rn(o1B0, o1B1);
                *(__half2*)(dB + 32) = __floats2half2_rn(o2B0, o2B1);
            }
        }
    } else {
        // v: transposed per (b,h) -> g_vt[b,h,c,n]
#pragma unroll
        for (int mf = 0; mf < 2; ++mf)
#pragma unroll
            for (int nf = 0; nf < 8; ++nf) {
                int row = row0 + wm * 32 + mf * 16 + gid;
                int col = col0 + wn * 64 + nf * 8 + 2 * tig;
                int bz = row >> 10, n = row & 1023;
                int hh = col >> 6, cc = col & 63;
                __half* base = g_vt + ((size_t)(bz * Hh + hh) * Cc + cc) * Nn + n;
                base[0]      = __float2half(acc[mf][nf][0]);
                base[Nn]     = __float2half(acc[mf][nf][1]);
                base[8]      = __float2half(acc[mf][nf][2]);
                base[Nn + 8] = __float2half(acc[mf][nf][3]);
            }
    }
}

// ---------------- bias (fp16 out), masked-region skip -----------------------
__global__ __launch_bounds__(256) void bias_kernel(const float* __restrict__ pair,
                                                   const float* __restrict__ Wb,
                                                   const int* __restrict__ seg)
{
    const int kt = blockIdx.x;
    const int q0 = blockIdx.y * 4;
    const int b  = blockIdx.z;

    if (kt > (q0 >> 6)) return;
    const int* sb = seg + b * Nn;
    if (sb[kt * 64 + 63] < sb[q0] || sb[kt * 64] > sb[q0 + 3]) return;

    __shared__ float Wb_s[FZ][Hh];
    for (int i = threadIdx.x; i < FZ * Hh; i += 256)
        Wb_s[i >> 4][i & 15] = Wb[i];
    __syncthreads();

    const int q = q0 + (threadIdx.x >> 6);
    const int k = kt * 64 + (threadIdx.x & 63);

    const float4* pp = (const float4*)&pair[((size_t)(b * Nn + q) * Nn + k) * FZ];

    float acc[Hh];
#pragma unroll
    for (int h = 0; h < Hh; h++) acc[h] = 0.f;

#pragma unroll
    for (int f4 = 0; f4 < FZ / 4; f4++) {
        float4 p = pp[f4];
#pragma unroll
        for (int h = 0; h < Hh; h++) {
            acc[h] += p.x * Wb_s[4 * f4 + 0][h];
            acc[h] += p.y * Wb_s[4 * f4 + 1][h];
            acc[h] += p.z * Wb_s[4 * f4 + 2][h];
            acc[h] += p.w * Wb_s[4 * f4 + 3][h];
        }
    }
#pragma unroll
    for (int h = 0; h < Hh; h++)
        g_biash[((size_t)(b * Hh + h) * Nn + q) * Nn + k] = __float2half(acc[h]);
}

// ---------------- flash attention (HMMA) ------------------------------------
#define ATT_BUF  25600
#define ATT_SMEM (8192 + 2 * ATT_BUF)   // 59392

__global__ __launch_bounds__(256, 2) void attn_kernel(const int* __restrict__ seg,
                                                      float* __restrict__ out)
{
    extern __shared__ char sm[];
    __shared__ float smax[64][2];
    __shared__ float ssum[64][2];
    __shared__ int   seg_s[64];

    const int tid  = threadIdx.x;
    const int w    = tid >> 5, lane = tid & 31;
    const int gid  = lane >> 2, tig = lane & 3;
    const int wm   = w & 3, wn = w >> 2;
    const int lr   = lane & 15, lh = lane >> 4;
    const int qt   = gridDim.x - 1 - blockIdx.x;
    const int h    = blockIdx.y, b = blockIdx.z;
    const uint32_t smb = smem_u32(sm);

    const int* sb = seg + b * Nn;
    const int segA = sb[qt * 64];
    int kt_start = 0;
    while (kt_start < qt && sb[kt_start * 64 + 63] < segA) kt_start++;

    const int lrow = tid >> 2;
    const int cp0  = (tid & 3) * 2;

    {
        const __half* src = g_qh + (size_t)(b * Nn + qt * 64 + lrow) * HC + h * Cc + cp0 * 8;
        uint32_t qd = smb + (uint32_t)(lrow * 128);
        cp16(qd + (((cp0 + 0) ^ (lrow & 7)) << 4), src);
        cp16(qd + (((cp0 + 1) ^ (lrow & 7)) << 4), src + 8);
    }
    auto issue_tile = [&](int kt, int bf) {
        uint32_t base = smb + 8192u + (uint32_t)bf * ATT_BUF;
        const __half* ks = g_kh + (size_t)(b * Nn + kt * 64 + lrow) * HC + h * Cc + cp0 * 8;
        cp16(base + (uint32_t)(lrow * 128) + (((cp0 + 0) ^ (lrow & 7)) << 4), ks);
        cp16(base + (uint32_t)(lrow * 128) + (((cp0 + 1) ^ (lrow & 7)) << 4), ks + 8);
        const __half* vs = g_vt + ((size_t)(b * Hh + h) * Cc + lrow) * Nn + kt * 64 + cp0 * 8;
        cp16(base + 8192u + (uint32_t)(lrow * 128) + (((cp0 + 0) ^ (lrow & 7)) << 4), vs);
        cp16(base + 8192u + (uint32_t)(lrow * 128) + (((cp0 + 1) ^ (lrow & 7)) << 4), vs + 8);
        const __half* bs = g_biash + ((size_t)(b * Hh + h) * Nn + qt * 64 + lrow) * Nn + kt * 64 + cp0 * 8;
        cp16(base + 16384u + (uint32_t)(lrow * 144 + cp0 * 16), bs);
        cp16(base + 16384u + (uint32_t)(lrow * 144 + cp0 * 16 + 16), bs + 8);
    };

    issue_tile(kt_start, 0); cp_commit();
    if (kt_start + 1 <= qt) { issue_tile(kt_start + 1, 1); cp_commit(); }

    float Oacc[8][4];
#pragma unroll
    for (int nf = 0; nf < 8; nf++)
#pragma unroll
        for (int i = 0; i < 4; i++) Oacc[nf][i] = 0.f;

    const int r0l = wm * 16 + gid, r1l = r0l + 8;
    const int rowg0 = qt * 64 + r0l, rowg1 = qt * 64 + r1l;
    const int myseg0 = sb[rowg0], myseg1 = sb[rowg1];
    float m_run0 = -INFINITY, m_run1 = -INFINITY;
    float l_run0 = 0.f, l_run1 = 0.f;
    const float sc = 0.125f;

#pragma unroll 1
    for (int kt = kt_start; kt <= qt; kt++) {
        const int bf = (kt - kt_start) & 1;
        if (kt + 1 <= qt) asm volatile("cp.async.wait_group 1;" ::: "memory");
        else              asm volatile("cp.async.wait_group 0;" ::: "memory");
        if (tid < 64) seg_s[tid] = sb[kt * 64 + tid];
        __syncthreads();

        const uint32_t Kb = smb + 8192u + (uint32_t)bf * ATT_BUF;
        const uint32_t Vb = Kb + 8192u;
        const __half* biasb = (const __half*)(sm + 8192 + bf * ATT_BUF + 16384);

        // ---- S = Q K^T ----
        float Sa[4][4];
#pragma unroll
        for (int j = 0; j < 4; j++)
#pragma unroll
            for (int i = 0; i < 4; i++) Sa[j][i] = 0.f;

#pragma unroll
        for (int ks = 0; ks < 4; ks++) {
            uint32_t a[4];
            {
                int R = wm * 16 + lr, cb = 2 * ks + lh;
                ldmx4(a, smb + (uint32_t)(R * 128 + ((cb ^ (R & 7)) << 4)));
            }
#pragma unroll
            for (int np = 0; np < 2; np++) {
                uint32_t bk[4];
                int R = wn * 32 + np * 16 + lr, cb = 2 * ks + lh;
                ldmx4(bk, Kb + (uint32_t)(R * 128 + ((cb ^ (R & 7)) << 4)));
                MMA16816(Sa[2 * np + 0], a, bk[0], bk[2]);
                MMA16816(Sa[2 * np + 1], a, bk[1], bk[3]);
            }
        }

        // ---- bias + mask + scale, partial rowmax ----
        float mx0 = -INFINITY, mx1 = -INFINITY;
#pragma unroll
        for (int j = 0; j < 4; j++) {
            int keyl = wn * 32 + j * 8 + 2 * tig;
            int keyg = kt * 64 + keyl;
            float2 bf0 = __half22float2(*(const __half2*)&biasb[r0l * 72 + keyl]);
            float2 bf1 = __half22float2(*(const __half2*)&biasb[r1l * 72 + keyl]);
            int sg0 = seg_s[keyl], sg1 = seg_s[keyl + 1];
            bool ok00 = (keyg     <= rowg0) && (sg0 == myseg0);
            bool ok01 = (keyg + 1 <= rowg0) && (sg1 == myseg0);
            bool ok10 = (keyg     <= rowg1) && (sg0 == myseg1);
            bool ok11 = (keyg + 1 <= rowg1) && (sg1 == myseg1);
            Sa[j][0] = ok00 ? fmaf(Sa[j][0], sc, bf0.x) : -INFINITY;
            Sa[j][1] = ok01 ? fmaf(Sa[j][1], sc, bf0.y) : -INFINITY;
            Sa[j][2] = ok10 ? fmaf(Sa[j][2], sc, bf1.x) : -INFINITY;
            Sa[j][3] = ok11 ? fmaf(Sa[j][3], sc, bf1.y) : -INFINITY;
            mx0 = fmaxf(mx0, fmaxf(Sa[j][0], Sa[j][1]));
            mx1 = fmaxf(mx1, fmaxf(Sa[j][2], Sa[j][3]));
        }
        mx0 = fmaxf(mx0, __shfl_xor_sync(0xffffffffu, mx0, 1));
        mx0 = fmaxf(mx0, __shfl_xor_sync(0xffffffffu, mx0, 2));
        mx1 = fmaxf(mx1, __shfl_xor_sync(0xffffffffu, mx1, 1));
        mx1 = fmaxf(mx1, __shfl_xor_sync(0xffffffffu, mx1, 2));
        if (tig == 0) { smax[r0l][wn] = mx0; smax[r1l][wn] = mx1; }
        __syncthreads();

        float mt0 = fmaxf(smax[r0l][0], smax[r0l][1]);
        float mt1 = fmaxf(smax[r1l][0], smax[r1l][1]);
        float mn0 = fmaxf(m_run0, mt0), mn1 = fmaxf(m_run1, mt1);
        float mu0 = (mn0 == -INFINITY) ? 0.f : mn0;
        float mu1 = (mn1 == -INFINITY) ? 0.f : mn1;
        float al0 = __expf(m_run0 - mu0), al1 = __expf(m_run1 - mu1);

        float ps0 = 0.f, ps1 = 0.f;
        uint32_t pa[2][4];
#pragma unroll
        for (int jj = 0; jj < 2; jj++) {
            float p[2][4];
#pragma unroll
            for (int d = 0; d < 2; d++) {
                int j = 2 * jj + d;
                p[d][0] = __expf(Sa[j][0] - mu0);
                p[d][1] = __expf(Sa[j][1] - mu0);
                p[d][2] = __expf(Sa[j][2] - mu1);
                p[d][3] = __expf(Sa[j][3] - mu1);
                ps0 += p[d][0] + p[d][1];
                ps1 += p[d][2] + p[d][3];
            }
            __half2 h0  = __floats2half2_rn(p[0][0], p[0][1]);
            __half2 h1  = __floats2half2_rn(p[0][2], p[0][3]);
            __half2 h2v = __floats2half2_rn(p[1][0], p[1][1]);
            __half2 h3  = __floats2half2_rn(p[1][2], p[1][3]);
            pa[jj][0] = *(uint32_t*)&h0;
            pa[jj][1] = *(uint32_t*)&h1;
            pa[jj][2] = *(uint32_t*)&h2v;
            pa[jj][3] = *(uint32_t*)&h3;
        }
        ps0 += __shfl_xor_sync(0xffffffffu, ps0, 1);
        ps0 += __shfl_xor_sync(0xffffffffu, ps0, 2);
        ps1 += __shfl_xor_sync(0xffffffffu, ps1, 1);
        ps1 += __shfl_xor_sync(0xffffffffu, ps1, 2);
        if (tig == 0) { ssum[r0l][wn] = ps0; ssum[r1l][wn] = ps1; }

#pragma unroll
        for (int nf = 0; nf < 8; nf++) {
            Oacc[nf][0] *= al0; Oacc[nf][1] *= al0;
            Oacc[nf][2] *= al1; Oacc[nf][3] *= al1;
        }
        __syncthreads();
        l_run0 = l_run0 * al0 + ssum[r0l][0] + ssum[r0l][1];
        l_run1 = l_run1 * al1 + ssum[r1l][0] + ssum[r1l][1];
        m_run0 = mn0; m_run1 = mn1;

        // ---- O += P V ----
#pragma unroll
        for (int ks2 = 0; ks2 < 2; ks2++) {
#pragma unroll
            for (int np2 = 0; np2 < 4; np2++) {
                uint32_t bv[4];
                int R = np2 * 16 + lr, cb = wn * 4 + ks2 * 2 + lh;
                ldmx4(bv, Vb + (uint32_t)(R * 128 + ((cb ^ (R & 7)) << 4)));
                MMA16816(Oacc[2 * np2 + 0], pa[ks2], bv[0], bv[2]);
                MMA16816(Oacc[2 * np2 + 1], pa[ks2], bv[1], bv[3]);
            }
        }

        __syncthreads();
        if (kt + 2 <= qt) { issue_tile(kt + 2, bf); cp_commit(); }
    }

    // ---- epilogue: combine wn partials via smem ----
    float inv0 = 1.f / l_run0, inv1 = 1.f / l_run1;
    float* Osm = (float*)sm;   // [64][68]
    if (wn == 1) {
#pragma unroll
        for (int nf = 0; nf < 8; nf++) {
            int c = nf * 8 + 2 * tig;
            *(float2*)&Osm[r0l * 68 + c] = make_float2(Oacc[nf][0], Oacc[nf][1]);
            *(float2*)&Osm[r1l * 68 + c] = make_float2(Oacc[nf][2], Oacc[nf][3]);
        }
    }
    __syncthreads();
    if (wn == 0) {
#pragma unroll
        for (int nf = 0; nf < 8; nf++) {
            int c = nf * 8 + 2 * tig;
            float2 o0 = *(float2*)&Osm[r0l * 68 + c];
            float2 o1 = *(float2*)&Osm[r1l * 68 + c];
            float* d0 = out + (size_t)(b * Nn + rowg0) * HC + h * Cc + c;
            float* d1 = out + (size_t)(b * Nn + rowg1) * HC + h * Cc + c;
            *(float2*)d0 = make_float2((Oacc[nf][0] + o0.x) * inv0,
                                       (Oacc[nf][1] + o0.y) * inv0);
            *(float2*)d1 = make_float2((Oacc[nf][2] + o1.x) * inv1,
                                       (Oacc[nf][3] + o1.y) * inv1);
        }
    }
}

// ---------------------------------------------------------------------------
extern "C" void kernel_launch(void* const* d_in, const int* in_sizes, int n_in,
                              void* d_out, int out_size)
{
    const float* s    = (const float*)d_in[0];
    const float* pair = (const float*)d_in[1];
    const int*   seg  = (const int*)d_in[2];
    const int*   pos  = (const int*)d_in[3];
    const float* Wq   = (const float*)d_in[4];
    const float* Wk   = (const float*)d_in[5];
    const float* Wv   = (const float*)d_in[6];
    const float* Wb   = (const float*)d_in[7];
    float* out = (float*)d_out;

    cudaFuncSetAttribute(attn_kernel,
                         cudaFuncAttributeMaxDynamicSharedMemorySize, ATT_SMEM);

    ropetab_kernel<<<(Mrows * 32) / 256, 256>>>(pos);
    conv_s_kernel<<<(Mrows * FS) / 256, 256>>>(s);
    conv_w_kernel<<<dim3(HC / 32, FS / 32, 3), dim3(32, 8)>>>(Wq, Wk, Wv);
    qkv_mma_kernel<<<dim3(HC / 128, Mrows / 128, 3), 256>>>();
    bias_kernel<<<dim3(Nn / 64, Nn / 4, Bb), 256>>>(pair, Wb, seg);
    attn_kernel<<<dim3(Nn / 64, Hh, Bb), 256, ATT_SMEM>>>(seg, out);
}

// round 15
// speedup vs baseline: 7.8923x; 1.0259x over previous
#include <cuda_runtime.h>
#include <cuda_fp16.h>
#include <math.h>
#include <stdint.h>

#define Bb 2
#define Nn 1024
#define FS 1024
#define FZ 64
#define Hh 16
#define Cc 64
#define HC (Hh*Cc)          // 1024
#define Mrows (Bb*Nn)       // 2048

// ---------------- scratch (static device globals; no allocations) ----------
__device__ __half g_biash[(size_t)Bb*Hh*Nn*Nn];  // 64MB fp16 bias

__device__ __half g_sh[(size_t)Mrows*FS];        // s  [m][k]
__device__ __half g_wh[(size_t)3*HC*FS];         // W^T [mat][n][k]
__device__ __half g_qh[(size_t)Mrows*HC];        // q (rope applied) [b,n,h,c]
__device__ __half g_kh[(size_t)Mrows*HC];        // k (rope applied) [b,n,h,c]
__device__ __half g_vt[(size_t)Bb*Hh*Cc*Nn];     // v^T [b,h,c,n]
__device__ float2 g_ropetab[(size_t)Mrows*32];   // (sin,cos) per (row, freq)

// ======================= helpers ===========================================
static __device__ __forceinline__ uint32_t smem_u32(const void* p) {
    uint32_t a;
    asm("{ .reg .u64 t; cvta.to.shared.u64 t, %1; cvt.u32.u64 %0, t; }"
        : "=r"(a) : "l"(p));
    return a;
}
static __device__ __forceinline__ void cp16(uint32_t dst, const void* src) {
    asm volatile("cp.async.cg.shared.global [%0], [%1], 16;"
                 :: "r"(dst), "l"(src) : "memory");
}
static __device__ __forceinline__ void cp_commit() {
    asm volatile("cp.async.commit_group;" ::: "memory");
}
static __device__ __forceinline__ void ldmx4(uint32_t* r, uint32_t addr) {
    asm volatile("ldmatrix.sync.aligned.m8n8.x4.shared.b16 {%0,%1,%2,%3}, [%4];"
                 : "=r"(r[0]), "=r"(r[1]), "=r"(r[2]), "=r"(r[3]) : "r"(addr));
}

#define MMA16816(d, a, b0v, b1v)                                              \
    asm volatile("mma.sync.aligned.m16n8k16.row.col.f32.f16.f16.f32 "         \
                 "{%0,%1,%2,%3}, {%4,%5,%6,%7}, {%8,%9}, {%0,%1,%2,%3};"      \
                 : "+f"((d)[0]), "+f"((d)[1]), "+f"((d)[2]), "+f"((d)[3])     \
                 : "r"((a)[0]), "r"((a)[1]), "r"((a)[2]), "r"((a)[3]),        \
                   "r"(b0v), "r"(b1v))

// ---------------- conversion / table kernels --------------------------------
__global__ void conv_s_kernel(const float* __restrict__ s) {
    int i = blockIdx.x * 256 + threadIdx.x;
    g_sh[i] = __float2half(s[i]);
}

__global__ void conv_w_kernel(const float* __restrict__ Wq,
                              const float* __restrict__ Wk,
                              const float* __restrict__ Wv) {
    __shared__ float t[32][33];
    const float* W = (blockIdx.z == 0) ? Wq : (blockIdx.z == 1) ? Wk : Wv;
    int n0 = blockIdx.x * 32;
    int k0 = blockIdx.y * 32;
    int tx = threadIdx.x, ty = threadIdx.y;
#pragma unroll
    for (int i = 0; i < 32; i += 8)
        t[ty + i][tx] = W[(size_t)(k0 + ty + i) * HC + n0 + tx];
    __syncthreads();
#pragma unroll
    for (int i = 0; i < 32; i += 8) {
        size_t idx = ((size_t)(blockIdx.z * HC + n0 + ty + i)) * FS + k0 + tx;
        g_wh[idx] = __float2half(t[tx][ty + i]);
    }
}

__global__ void ropetab_kernel(const int* __restrict__ positions) {
    int idx = blockIdx.x * 256 + threadIdx.x;   // Mrows*32 = 65536
    int i = idx & 31;
    int r = idx >> 5;
    int pos = positions[r];
    float inv_ts = exp2f(-0.41524101186092029f * (float)i);
    float sn, cs;
    sincosf((float)pos * inv_ts, &sn, &cs);
    g_ropetab[idx] = make_float2(sn, cs);
}

// ---------------- QKV projection via mma.sync (HMMA), rope fused ------------
// 128(M) x 64(N) block tile, BK=32, 3-stage cp.async, 8 warps (4m x 2n).
// Warp wn covers n-cols {wn*16..+15} U {wn*16+32..+47} so RoPE pairs
// (i, i+32) stay within one thread.
#define QSTG 3
#define A_HALF (128 * 32)    // 8KB/stage
#define B_HALF (64 * 32)     // 4KB/stage

__global__ __launch_bounds__(256, 3) void qkv_mma_kernel()
{
    __shared__ __align__(16) __half As[QSTG][A_HALF];
    __shared__ __align__(16) __half Bs[QSTG][B_HALF];

    const int tid  = threadIdx.x;
    const int col0 = blockIdx.x * 64;
    const int row0 = blockIdx.y * 128;
    const int mat  = blockIdx.z;

    const __half* Ag = g_sh + (size_t)row0 * FS;
    const __half* Bg = g_wh + (size_t)(mat * HC + col0) * FS;

    const uint32_t aS = smem_u32(As);
    const uint32_t bS = smem_u32(Bs);

    // A cp.async mapping: row tid>>1, two 16B chunks
    const int ra  = tid >> 1;
    const int c20 = (tid & 1) * 2;
    const int rxa = (ra >> 1) & 3;
    // B cp.async mapping: row tid>>2, one 16B chunk
    const int rb  = tid >> 2;
    const int cb1 = tid & 3;
    const int rxb = (rb >> 1) & 3;

    const int w    = tid >> 5;
    const int lane = tid & 31;
    const int gid  = lane >> 2;
    const int tig  = lane & 3;
    const int wm   = w & 3;
    const int wn   = w >> 2;
    const int lr   = lane & 15;
    const int lh   = lane >> 4;

    float acc[2][4][4];
#pragma unroll
    for (int mf = 0; mf < 2; mf++)
#pragma unroll
        for (int nf = 0; nf < 4; nf++)
#pragma unroll
            for (int i = 0; i < 4; i++) acc[mf][nf][i] = 0.f;

    auto issue = [&](int c, int stg) {
        const __half* as = Ag + (size_t)ra * FS + c * 32 + c20 * 8;
        uint32_t arow = aS + (uint32_t)(stg * A_HALF * 2 + ra * 64);
        cp16(arow + (((c20 + 0) ^ rxa) << 4), as);
        cp16(arow + (((c20 + 1) ^ rxa) << 4), as + 8);
        const __half* bs = Bg + (size_t)rb * FS + c * 32 + cb1 * 8;
        uint32_t brow = bS + (uint32_t)(stg * B_HALF * 2 + rb * 64);
        cp16(brow + ((cb1 ^ rxb) << 4), bs);
    };

    issue(0, 0); cp_commit();
    issue(1, 1); cp_commit();

#pragma unroll 1
    for (int c = 0; c < 32; ++c) {
        if (c < 31) asm volatile("cp.async.wait_group 1;" ::: "memory");
        else        asm volatile("cp.async.wait_group 0;" ::: "memory");
        __syncthreads();

        if (c + 2 < 32) { issue(c + 2, (c + 2) % QSTG); cp_commit(); }

        const int stg = c % QSTG;
        const uint32_t sA = aS + (uint32_t)(stg * A_HALF * 2);
        const uint32_t sB = bS + (uint32_t)(stg * B_HALF * 2);

#pragma unroll
        for (int kk = 0; kk < 32; kk += 16) {
            const int cb = (kk >> 3) + lh;
            uint32_t a[2][4];
#pragma unroll
            for (int mf = 0; mf < 2; ++mf) {
                int R = wm * 32 + mf * 16 + lr;
                ldmx4(a[mf], sA + (uint32_t)(R * 64 + ((cb ^ ((R >> 1) & 3)) << 4)));
            }
            uint32_t bf4[2][4];
#pragma unroll
            for (int g = 0; g < 2; ++g) {
                int R = wn * 16 + g * 32 + lr;
                ldmx4(bf4[g], sB + (uint32_t)(R * 64 + ((cb ^ ((R >> 1) & 3)) << 4)));
            }
#pragma unroll
            for (int g = 0; g < 2; ++g) {
                MMA16816(acc[0][2 * g + 0], a[0], bf4[g][0], bf4[g][2]);
                MMA16816(acc[1][2 * g + 0], a[1], bf4[g][0], bf4[g][2]);
                MMA16816(acc[0][2 * g + 1], a[0], bf4[g][1], bf4[g][3]);
                MMA16816(acc[1][2 * g + 1], a[1], bf4[g][1], bf4[g][3]);
            }
        }
    }

    // ---- epilogue ----
    // acc[mf][nf]: cols col0 + wn*16 + (nf>>1)*32 + (nf&1)*8 + 2*tig (+1)
    // rows: row0 + wm*32 + mf*16 + gid (regs 0,1) and +8 (regs 2,3)
    if (mat < 2) {
        __half* Oh = (mat == 0) ? g_qh : g_kh;
#pragma unroll
        for (int mf = 0; mf < 2; ++mf) {
            int rA = row0 + wm * 32 + mf * 16 + gid;
            int rB = rA + 8;
            const float2* tA = g_ropetab + (size_t)rA * 32;
            const float2* tB = g_ropetab + (size_t)rB * 32;
#pragma unroll
            for (int nf = 0; nf < 2; ++nf) {
                int i0 = wn * 16 + nf * 8 + 2 * tig;   // head-local col in [0,32)
                float2 sA0 = tA[i0], sA1 = tA[i0 + 1];
                float2 sB0 = tB[i0], sB1 = tB[i0 + 1];
                float x1A0 = acc[mf][nf][0],     x1A1 = acc[mf][nf][1];
                float x1B0 = acc[mf][nf][2],     x1B1 = acc[mf][nf][3];
                float x2A0 = acc[mf][nf + 2][0], x2A1 = acc[mf][nf + 2][1];
                float x2B0 = acc[mf][nf + 2][2], x2B1 = acc[mf][nf + 2][3];
                float o1A0 = x1A0 * sA0.y - x2A0 * sA0.x;
                float o2A0 = x2A0 * sA0.y + x1A0 * sA0.x;
                float o1A1 = x1A1 * sA1.y - x2A1 * sA1.x;
                float o2A1 = x2A1 * sA1.y + x1A1 * sA1.x;
                float o1B0 = x1B0 * sB0.y - x2B0 * sB0.x;
                float o2B0 = x2B0 * sB0.y + x1B0 * sB0.x;
                float o1B1 = x1B1 * sB1.y - x2B1 * sB1.x;
                float o2B1 = x2B1 * sB1.y + x1B1 * sB1.x;
                int col = col0 + i0;
                __half* dA = Oh + (size_t)rA * HC + col;
                __half* dB = Oh + (size_t)rB * HC + col;
                *(__half2*)dA        = __floats2half2_rn(o1A0, o1A1);
                *(__half2*)(dA + 32) = __floats2half2_rn(o2A0, o2A1);
                *(__half2*)dB        = __floats2half2_rn(o1B0, o1B1);
                *(__half2*)(dB + 32) = __floats2half2_rn(o2B0, o2B1);
            }
        }
    } else {
#pragma unroll
        for (int mf = 0; mf < 2; ++mf)
#pragma unroll
            for (int nf = 0; nf < 4; ++nf) {
                int row = row0 + wm * 32 + mf * 16 + gid;
                int col = col0 + wn * 16 + (nf >> 1) * 32 + (nf & 1) * 8 + 2 * tig;
                int bz = row >> 10, n = row & 1023;
                int hh = col >> 6, cc = col & 63;
                __half* base = g_vt + ((size_t)(bz * Hh + hh) * Cc + cc) * Nn + n;
                base[0]      = __float2half(acc[mf][nf][0]);
                base[Nn]     = __float2half(acc[mf][nf][1]);
                base[8]      = __float2half(acc[mf][nf][2]);
                base[Nn + 8] = __float2half(acc[mf][nf][3]);
            }
    }
}

// ---------------- bias (fp16 out), masked-region skip -----------------------
__global__ __launch_bounds__(256) void bias_kernel(const float* __restrict__ pair,
                                                   const float* __restrict__ Wb,
                                                   const int* __restrict__ seg)
{
    const int kt = blockIdx.x;
    const int q0 = blockIdx.y * 4;
    const int b  = blockIdx.z;

    if (kt > (q0 >> 6)) return;
    const int* sb = seg + b * Nn;
    if (sb[kt * 64 + 63] < sb[q0] || sb[kt * 64] > sb[q0 + 3]) return;

    __shared__ float Wb_s[FZ][Hh];
    for (int i = threadIdx.x; i < FZ * Hh; i += 256)
        Wb_s[i >> 4][i & 15] = Wb[i];
    __syncthreads();

    const int q = q0 + (threadIdx.x >> 6);
    const int k = kt * 64 + (threadIdx.x & 63);

    const float4* pp = (const float4*)&pair[((size_t)(b * Nn + q) * Nn + k) * FZ];

    float acc[Hh];
#pragma unroll
    for (int h = 0; h < Hh; h++) acc[h] = 0.f;

#pragma unroll
    for (int f4 = 0; f4 < FZ / 4; f4++) {
        float4 p = pp[f4];
#pragma unroll
        for (int h = 0; h < Hh; h++) {
            acc[h] += p.x * Wb_s[4 * f4 + 0][h];
            acc[h] += p.y * Wb_s[4 * f4 + 1][h];
            acc[h] += p.z * Wb_s[4 * f4 + 2][h];
            acc[h] += p.w * Wb_s[4 * f4 + 3][h];
        }
    }
#pragma unroll
    for (int h = 0; h < Hh; h++)
        g_biash[((size_t)(b * Hh + h) * Nn + q) * Nn + k] = __float2half(acc[h]);
}

// ---------------- flash attention (HMMA) ------------------------------------
#define ATT_BUF  25600
#define ATT_SMEM (8192 + 2 * ATT_BUF)   // 59392

__global__ __launch_bounds__(256, 2) void attn_kernel(const int* __restrict__ seg,
                                                      float* __restrict__ out)
{
    extern __shared__ char sm[];
    __shared__ float smax[64][2];
    __shared__ float ssum[64][2];
    __shared__ int   seg_s[64];

    const int tid  = threadIdx.x;
    const int w    = tid >> 5, lane = tid & 31;
    const int gid  = lane >> 2, tig = lane & 3;
    const int wm   = w & 3, wn = w >> 2;
    const int lr   = lane & 15, lh = lane >> 4;
    const int qt   = gridDim.x - 1 - blockIdx.x;
    const int h    = blockIdx.y, b = blockIdx.z;
    const uint32_t smb = smem_u32(sm);

    const int* sb = seg + b * Nn;
    const int segA = sb[qt * 64];
    int kt_start = 0;
    while (kt_start < qt && sb[kt_start * 64 + 63] < segA) kt_start++;

    const int lrow = tid >> 2;
    const int cp0  = (tid & 3) * 2;

    {
        const __half* src = g_qh + (size_t)(b * Nn + qt * 64 + lrow) * HC + h * Cc + cp0 * 8;
        uint32_t qd = smb + (uint32_t)(lrow * 128);
        cp16(qd + (((cp0 + 0) ^ (lrow & 7)) << 4), src);
        cp16(qd + (((cp0 + 1) ^ (lrow & 7)) << 4), src + 8);
    }
    auto issue_tile = [&](int kt, int bf) {
        uint32_t base = smb + 8192u + (uint32_t)bf * ATT_BUF;
        const __half* ks = g_kh + (size_t)(b * Nn + kt * 64 + lrow) * HC + h * Cc + cp0 * 8;
        cp16(base + (uint32_t)(lrow * 128) + (((cp0 + 0) ^ (lrow & 7)) << 4), ks);
        cp16(base + (uint32_t)(lrow * 128) + (((cp0 + 1) ^ (lrow & 7)) << 4), ks + 8);
        const __half* vs = g_vt + ((size_t)(b * Hh + h) * Cc + lrow) * Nn + kt * 64 + cp0 * 8;
        cp16(base + 8192u + (uint32_t)(lrow * 128) + (((cp0 + 0) ^ (lrow & 7)) << 4), vs);
        cp16(base + 8192u + (uint32_t)(lrow * 128) + (((cp0 + 1) ^ (lrow & 7)) << 4), vs + 8);
        const __half* bs = g_biash + ((size_t)(b * Hh + h) * Nn + qt * 64 + lrow) * Nn + kt * 64 + cp0 * 8;
        cp16(base + 16384u + (uint32_t)(lrow * 144 + cp0 * 16), bs);
        cp16(base + 16384u + (uint32_t)(lrow * 144 + cp0 * 16 + 16), bs + 8);
    };

    issue_tile(kt_start, 0); cp_commit();
    if (kt_start + 1 <= qt) { issue_tile(kt_start + 1, 1); cp_commit(); }

    float Oacc[8][4];
#pragma unroll
    for (int nf = 0; nf < 8; nf++)
#pragma unroll
        for (int i = 0; i < 4; i++) Oacc[nf][i] = 0.f;

    const int r0l = wm * 16 + gid, r1l = r0l + 8;
    const int rowg0 = qt * 64 + r0l, rowg1 = qt * 64 + r1l;
    const int myseg0 = sb[rowg0], myseg1 = sb[rowg1];
    float m_run0 = -INFINITY, m_run1 = -INFINITY;
    float l_run0 = 0.f, l_run1 = 0.f;
    const float sc = 0.125f;

#pragma unroll 1
    for (int kt = kt_start; kt <= qt; kt++) {
        const int bf = (kt - kt_start) & 1;
        if (kt + 1 <= qt) asm volatile("cp.async.wait_group 1;" ::: "memory");
        else              asm volatile("cp.async.wait_group 0;" ::: "memory");
        if (tid < 64) seg_s[tid] = sb[kt * 64 + tid];
        __syncthreads();

        const uint32_t Kb = smb + 8192u + (uint32_t)bf * ATT_BUF;
        const uint32_t Vb = Kb + 8192u;
        const __half* biasb = (const __half*)(sm + 8192 + bf * ATT_BUF + 16384);

        // ---- S = Q K^T ----
        float Sa[4][4];
#pragma unroll
        for (int j = 0; j < 4; j++)
#pragma unroll
            for (int i = 0; i < 4; i++) Sa[j][i] = 0.f;

#pragma unroll
        for (int ks = 0; ks < 4; ks++) {
            uint32_t a[4];
            {
                int R = wm * 16 + lr, cb = 2 * ks + lh;
                ldmx4(a, smb + (uint32_t)(R * 128 + ((cb ^ (R & 7)) << 4)));
            }
#pragma unroll
            for (int np = 0; np < 2; np++) {
                uint32_t bk[4];
                int R = wn * 32 + np * 16 + lr, cb = 2 * ks + lh;
                ldmx4(bk, Kb + (uint32_t)(R * 128 + ((cb ^ (R & 7)) << 4)));
                MMA16816(Sa[2 * np + 0], a, bk[0], bk[2]);
                MMA16816(Sa[2 * np + 1], a, bk[1], bk[3]);
            }
        }

        // ---- bias + mask + scale, partial rowmax ----
        float mx0 = -INFINITY, mx1 = -INFINITY;
#pragma unroll
        for (int j = 0; j < 4; j++) {
            int keyl = wn * 32 + j * 8 + 2 * tig;
            int keyg = kt * 64 + keyl;
            float2 bf0 = __half22float2(*(const __half2*)&biasb[r0l * 72 + keyl]);
            float2 bf1 = __half22float2(*(const __half2*)&biasb[r1l * 72 + keyl]);
            int sg0 = seg_s[keyl], sg1 = seg_s[keyl + 1];
            bool ok00 = (keyg     <= rowg0) && (sg0 == myseg0);
            bool ok01 = (keyg + 1 <= rowg0) && (sg1 == myseg0);
            bool ok10 = (keyg     <= rowg1) && (sg0 == myseg1);
            bool ok11 = (keyg + 1 <= rowg1) && (sg1 == myseg1);
            Sa[j][0] = ok00 ? fmaf(Sa[j][0], sc, bf0.x) : -INFINITY;
            Sa[j][1] = ok01 ? fmaf(Sa[j][1], sc, bf0.y) : -INFINITY;
            Sa[j][2] = ok10 ? fmaf(Sa[j][2], sc, bf1.x) : -INFINITY;
            Sa[j][3] = ok11 ? fmaf(Sa[j][3], sc, bf1.y) : -INFINITY;
            mx0 = fmaxf(mx0, fmaxf(Sa[j][0], Sa[j][1]));
            mx1 = fmaxf(mx1, fmaxf(Sa[j][2], Sa[j][3]));
        }
        mx0 = fmaxf(mx0, __shfl_xor_sync(0xffffffffu, mx0, 1));
        mx0 = fmaxf(mx0, __shfl_xor_sync(0xffffffffu, mx0, 2));
        mx1 = fmaxf(mx1, __shfl_xor_sync(0xffffffffu, mx1, 1));
        mx1 = fmaxf(mx1, __shfl_xor_sync(0xffffffffu, mx1, 2));
        if (tig == 0) { smax[r0l][wn] = mx0; smax[r1l][wn] = mx1; }
        __syncthreads();

        float mt0 = fmaxf(smax[r0l][0], smax[r0l][1]);
        float mt1 = fmaxf(smax[r1l][0], smax[r1l][1]);
        float mn0 = fmaxf(m_run0, mt0), mn1 = fmaxf(m_run1, mt1);
        float mu0 = (mn0 == -INFINITY) ? 0.f : mn0;
        float mu1 = (mn1 == -INFINITY) ? 0.f : mn1;
        float al0 = __expf(m_run0 - mu0), al1 = __expf(m_run1 - mu1);

        float ps0 = 0.f, ps1 = 0.f;
        uint32_t pa[2][4];
#pragma unroll
        for (int jj = 0; jj < 2; jj++) {
            float p[2][4];
#pragma unroll
            for (int d = 0; d < 2; d++) {
                int j = 2 * jj + d;
                p[d][0] = __expf(Sa[j][0] - mu0);
                p[d][1] = __expf(Sa[j][1] - mu0);
                p[d][2] = __expf(Sa[j][2] - mu1);
                p[d][3] = __expf(Sa[j][3] - mu1);
                ps0 += p[d][0] + p[d][1];
                ps1 += p[d][2] + p[d][3];
            }
            __half2 h0  = __floats2half2_rn(p[0][0], p[0][1]);
            __half2 h1  = __floats2half2_rn(p[0][2], p[0][3]);
            __half2 h2v = __floats2half2_rn(p[1][0], p[1][1]);
            __half2 h3  = __floats2half2_rn(p[1][2], p[1][3]);
            pa[jj][0] = *(uint32_t*)&h0;
            pa[jj][1] = *(uint32_t*)&h1;
            pa[jj][2] = *(uint32_t*)&h2v;
            pa[jj][3] = *(uint32_t*)&h3;
        }
        ps0 += __shfl_xor_sync(0xffffffffu, ps0, 1);
        ps0 += __shfl_xor_sync(0xffffffffu, ps0, 2);
        ps1 += __shfl_xor_sync(0xffffffffu, ps1, 1);
        ps1 += __shfl_xor_sync(0xffffffffu, ps1, 2);
        if (tig == 0) { ssum[r0l][wn] = ps0; ssum[r1l][wn] = ps1; }

#pragma unroll
        for (int nf = 0; nf < 8; nf++) {
            Oacc[nf][0] *= al0; Oacc[nf][1] *= al0;
            Oacc[nf][2] *= al1; Oacc[nf][3] *= al1;
        }
        __syncthreads();
        l_run0 = l_run0 * al0 + ssum[r0l][0] + ssum[r0l][1];
        l_run1 = l_run1 * al1 + ssum[r1l][0] + ssum[r1l][1];
        m_run0 = mn0; m_run1 = mn1;

        // ---- O += P V ----
#pragma unroll
        for (int ks2 = 0; ks2 < 2; ks2++) {
#pragma unroll
            for (int np2 = 0; np2 < 4; np2++) {
                uint32_t bv[4];
                int R = np2 * 16 + lr, cb = wn * 4 + ks2 * 2 + lh;
                ldmx4(bv, Vb + (uint32_t)(R * 128 + ((cb ^ (R & 7)) << 4)));
                MMA16816(Oacc[2 * np2 + 0], pa[ks2], bv[0], bv[2]);
                MMA16816(Oacc[2 * np2 + 1], pa[ks2], bv[1], bv[3]);
            }
        }

        __syncthreads();
        if (kt + 2 <= qt) { issue_tile(kt + 2, bf); cp_commit(); }
    }

    // ---- epilogue: combine wn partials via smem ----
    float inv0 = 1.f / l_run0, inv1 = 1.f / l_run1;
    float* Osm = (float*)sm;   // [64][68]
    if (wn == 1) {
#pragma unroll
        for (int nf = 0; nf < 8; nf++) {
            int c = nf * 8 + 2 * tig;
            *(float2*)&Osm[r0l * 68 + c] = make_float2(Oacc[nf][0], Oacc[nf][1]);
            *(float2*)&Osm[r1l * 68 + c] = make_float2(Oacc[nf][2], Oacc[nf][3]);
        }
    }
    __syncthreads();
    if (wn == 0) {
#pragma unroll
        for (int nf = 0; nf < 8; nf++) {
            int c = nf * 8 + 2 * tig;
            float2 o0 = *(float2*)&Osm[r0l * 68 + c];
            float2 o1 = *(float2*)&Osm[r1l * 68 + c];
            float* d0 = out + (size_t)(b * Nn + rowg0) * HC + h * Cc + c;
            float* d1 = out + (size_t)(b * Nn + rowg1) * HC + h * Cc + c;
            *(float2*)d0 = make_float2((Oacc[nf][0] + o0.x) * inv0,
                                       (Oacc[nf][1] + o0.y) * inv0);
            *(float2*)d1 = make_float2((Oacc[nf][2] + o1.x) * inv1,
                                       (Oacc[nf][3] + o1.y) * inv1);
        }
    }
}

// ---------------------------------------------------------------------------
extern "C" void kernel_launch(void* const* d_in, const int* in_sizes, int n_in,
                              void* d_out, int out_size)
{
    const float* s    = (const float*)d_in[0];
    const float* pair = (const float*)d_in[1];
    const int*   seg  = (const int*)d_in[2];
    const int*   pos  = (const int*)d_in[3];
    const float* Wq   = (const float*)d_in[4];
    const float* Wk   = (const float*)d_in[5];
    const float* Wv   = (const float*)d_in[6];
    const float* Wb   = (const float*)d_in[7];
    float* out = (float*)d_out;

    cudaFuncSetAttribute(attn_kernel,
                         cudaFuncAttributeMaxDynamicSharedMemorySize, ATT_SMEM);

    ropetab_kernel<<<(Mrows * 32) / 256, 256>>>(pos);
    conv_s_kernel<<<(Mrows * FS) / 256, 256>>>(s);
    conv_w_kernel<<<dim3(HC / 32, FS / 32, 3), dim3(32, 8)>>>(Wq, Wk, Wv);
    qkv_mma_kernel<<<dim3(HC / 64, Mrows / 128, 3), 256>>>();
    bias_kernel<<<dim3(Nn / 64, Nn / 4, Bb), 256>>>(pair, Wb, seg);
    attn_kernel<<<dim3(Nn / 64, Hh, Bb), 256, ATT_SMEM>>>(seg, out);
}

// round 17
// speedup vs baseline: 8.1455x; 1.0321x over previous
#include <cuda_runtime.h>
#include <cuda_fp16.h>
#include <math.h>
#include <stdint.h>

#define Bb 2
#define Nn 1024
#define FS 1024
#define FZ 64
#define Hh 16
#define Cc 64
#define HC (Hh*Cc)          // 1024
#define Mrows (Bb*Nn)       // 2048

// ---------------- scratch (static device globals; no allocations) ----------
__device__ __half g_biash[(size_t)Bb*Hh*Nn*Nn];  // 64MB fp16 bias

__device__ __half g_sh[(size_t)Mrows*FS];        // s  [m][k]
__device__ __half g_wh[(size_t)3*HC*FS];         // W^T [mat][n][k]
__device__ __half g_qh[(size_t)Mrows*HC];        // q (rope applied) [b,n,h,c]
__device__ __half g_kh[(size_t)Mrows*HC];        // k (rope applied) [b,n,h,c]
__device__ __half g_vt[(size_t)Bb*Hh*Cc*Nn];     // v^T [b,h,c,n]
__device__ float2 g_ropetab[(size_t)Mrows*32];   // (sin,cos) per (row, freq)

// ======================= helpers ===========================================
static __device__ __forceinline__ uint32_t smem_u32(const void* p) {
    uint32_t a;
    asm("{ .reg .u64 t; cvta.to.shared.u64 t, %1; cvt.u32.u64 %0, t; }"
        : "=r"(a) : "l"(p));
    return a;
}
static __device__ __forceinline__ void cp16(uint32_t dst, const void* src) {
    asm volatile("cp.async.cg.shared.global [%0], [%1], 16;"
                 :: "r"(dst), "l"(src) : "memory");
}
static __device__ __forceinline__ void cp_commit() {
    asm volatile("cp.async.commit_group;" ::: "memory");
}
static __device__ __forceinline__ void ldmx4(uint32_t* r, uint32_t addr) {
    asm volatile("ldmatrix.sync.aligned.m8n8.x4.shared.b16 {%0,%1,%2,%3}, [%4];"
                 : "=r"(r[0]), "=r"(r[1]), "=r"(r[2]), "=r"(r[3]) : "r"(addr));
}

#define MMA16816(d, a, b0v, b1v)                                              \
    asm volatile("mma.sync.aligned.m16n8k16.row.col.f32.f16.f16.f32 "         \
                 "{%0,%1,%2,%3}, {%4,%5,%6,%7}, {%8,%9}, {%0,%1,%2,%3};"      \
                 : "+f"((d)[0]), "+f"((d)[1]), "+f"((d)[2]), "+f"((d)[3])     \
                 : "r"((a)[0]), "r"((a)[1]), "r"((a)[2]), "r"((a)[3]),        \
                   "r"(b0v), "r"(b1v))

// ---------------- conversion / table kernels --------------------------------
__global__ void conv_s_kernel(const float* __restrict__ s) {
    int i = blockIdx.x * 256 + threadIdx.x;
    g_sh[i] = __float2half(s[i]);
}

__global__ void conv_w_kernel(const float* __restrict__ Wq,
                              const float* __restrict__ Wk,
                              const float* __restrict__ Wv) {
    __shared__ float t[32][33];
    const float* W = (blockIdx.z == 0) ? Wq : (blockIdx.z == 1) ? Wk : Wv;
    int n0 = blockIdx.x * 32;
    int k0 = blockIdx.y * 32;
    int tx = threadIdx.x, ty = threadIdx.y;
#pragma unroll
    for (int i = 0; i < 32; i += 8)
        t[ty + i][tx] = W[(size_t)(k0 + ty + i) * HC + n0 + tx];
    __syncthreads();
#pragma unroll
    for (int i = 0; i < 32; i += 8) {
        size_t idx = ((size_t)(blockIdx.z * HC + n0 + ty + i)) * FS + k0 + tx;
        g_wh[idx] = __float2half(t[tx][ty + i]);
    }
}

__global__ void ropetab_kernel(const int* __restrict__ positions) {
    int idx = blockIdx.x * 256 + threadIdx.x;   // Mrows*32 = 65536
    int i = idx & 31;
    int r = idx >> 5;
    int pos = positions[r];
    float inv_ts = exp2f(-0.41524101186092029f * (float)i);
    float sn, cs;
    sincosf((float)pos * inv_ts, &sn, &cs);
    g_ropetab[idx] = make_float2(sn, cs);
}

// ---------------- fused QKV GEMM + bias kernel ------------------------------
// Blocks [0, 768): qkv HMMA GEMM (128x64 tile, BK=32, 3-stage, rope fused).
// Blocks [768, 8960): bias einsum with masked-region skip.
// The two roles are data-independent; fusing them lets DRAM-bound bias
// blocks overlap with tensor-bound qkv blocks across the chip.
#define QSTG 3
#define A_HALF (128 * 32)    // 8KB/stage
#define B_HALF (64 * 32)     // 4KB/stage
#define QKV_BLOCKS 768

__global__ __launch_bounds__(256, 3) void qkv_bias_kernel(
    const float* __restrict__ pair,
    const float* __restrict__ Wb,
    const int* __restrict__ seg)
{
    __shared__ __align__(16) __half As[QSTG][A_HALF];
    __shared__ __align__(16) __half Bs[QSTG][B_HALF];
    __shared__ float Wb_s[FZ][Hh];

    const int tid = threadIdx.x;
    const int bid = blockIdx.x;

    if (bid >= QKV_BLOCKS) {
        // =============== bias role ===============
        const int bid2 = bid - QKV_BLOCKS;
        const int kt = bid2 & 15;
        const int q0 = ((bid2 >> 4) & 255) * 4;
        const int b  = bid2 >> 12;

        if (kt > (q0 >> 6)) return;
        const int* sb = seg + b * Nn;
        if (sb[kt * 64 + 63] < sb[q0] || sb[kt * 64] > sb[q0 + 3]) return;

        for (int i = tid; i < FZ * Hh; i += 256)
            Wb_s[i >> 4][i & 15] = Wb[i];
        __syncthreads();

        const int q = q0 + (tid >> 6);
        const int k = kt * 64 + (tid & 63);

        const float4* pp = (const float4*)&pair[((size_t)(b * Nn + q) * Nn + k) * FZ];

        float acc[Hh];
#pragma unroll
        for (int h = 0; h < Hh; h++) acc[h] = 0.f;

#pragma unroll
        for (int f4 = 0; f4 < FZ / 4; f4++) {
            float4 p = pp[f4];
#pragma unroll
            for (int h = 0; h < Hh; h++) {
                acc[h] += p.x * Wb_s[4 * f4 + 0][h];
                acc[h] += p.y * Wb_s[4 * f4 + 1][h];
                acc[h] += p.z * Wb_s[4 * f4 + 2][h];
                acc[h] += p.w * Wb_s[4 * f4 + 3][h];
            }
        }
#pragma unroll
        for (int h = 0; h < Hh; h++)
            g_biash[((size_t)(b * Hh + h) * Nn + q) * Nn + k] = __float2half(acc[h]);
        return;
    }

    // =============== qkv role ===============
    const int col0 = (bid & 15) * 64;
    const int row0 = ((bid >> 4) & 15) * 128;
    const int mat  = bid >> 8;

    const __half* Ag = g_sh + (size_t)row0 * FS;
    const __half* Bg = g_wh + (size_t)(mat * HC + col0) * FS;

    const uint32_t aS = smem_u32(As);
    const uint32_t bS = smem_u32(Bs);

    const int ra  = tid >> 1;
    const int c20 = (tid & 1) * 2;
    const int rxa = (ra >> 1) & 3;
    const int rb  = tid >> 2;
    const int cb1 = tid & 3;
    const int rxb = (rb >> 1) & 3;

    const int w    = tid >> 5;
    const int lane = tid & 31;
    const int gid  = lane >> 2;
    const int tig  = lane & 3;
    const int wm   = w & 3;
    const int wn   = w >> 2;
    const int lr   = lane & 15;
    const int lh   = lane >> 4;

    float acc[2][4][4];
#pragma unroll
    for (int mf = 0; mf < 2; mf++)
#pragma unroll
        for (int nf = 0; nf < 4; nf++)
#pragma unroll
            for (int i = 0; i < 4; i++) acc[mf][nf][i] = 0.f;

    auto issue = [&](int c, int stg) {
        const __half* as = Ag + (size_t)ra * FS + c * 32 + c20 * 8;
        uint32_t arow = aS + (uint32_t)(stg * A_HALF * 2 + ra * 64);
        cp16(arow + (((c20 + 0) ^ rxa) << 4), as);
        cp16(arow + (((c20 + 1) ^ rxa) << 4), as + 8);
        const __half* bs = Bg + (size_t)rb * FS + c * 32 + cb1 * 8;
        uint32_t brow = bS + (uint32_t)(stg * B_HALF * 2 + rb * 64);
        cp16(brow + ((cb1 ^ rxb) << 4), bs);
    };

    issue(0, 0); cp_commit();
    issue(1, 1); cp_commit();

#pragma unroll 1
    for (int c = 0; c < 32; ++c) {
        if (c < 31) asm volatile("cp.async.wait_group 1;" ::: "memory");
        else        asm volatile("cp.async.wait_group 0;" ::: "memory");
        __syncthreads();

        if (c + 2 < 32) { issue(c + 2, (c + 2) % QSTG); cp_commit(); }

        const int stg = c % QSTG;
        const uint32_t sA = aS + (uint32_t)(stg * A_HALF * 2);
        const uint32_t sB = bS + (uint32_t)(stg * B_HALF * 2);

#pragma unroll
        for (int kk = 0; kk < 32; kk += 16) {
            const int cb = (kk >> 3) + lh;
            uint32_t a[2][4];
#pragma unroll
            for (int mf = 0; mf < 2; ++mf) {
                int R = wm * 32 + mf * 16 + lr;
                ldmx4(a[mf], sA + (uint32_t)(R * 64 + ((cb ^ ((R >> 1) & 3)) << 4)));
            }
            uint32_t bf4[2][4];
#pragma unroll
            for (int g = 0; g < 2; ++g) {
                int R = wn * 16 + g * 32 + lr;
                ldmx4(bf4[g], sB + (uint32_t)(R * 64 + ((cb ^ ((R >> 1) & 3)) << 4)));
            }
#pragma unroll
            for (int g = 0; g < 2; ++g) {
                MMA16816(acc[0][2 * g + 0], a[0], bf4[g][0], bf4[g][2]);
                MMA16816(acc[1][2 * g + 0], a[1], bf4[g][0], bf4[g][2]);
                MMA16816(acc[0][2 * g + 1], a[0], bf4[g][1], bf4[g][3]);
                MMA16816(acc[1][2 * g + 1], a[1], bf4[g][1], bf4[g][3]);
            }
        }
    }

    // ---- epilogue ----
    if (mat < 2) {
        __half* Oh = (mat == 0) ? g_qh : g_kh;
#pragma unroll
        for (int mf = 0; mf < 2; ++mf) {
            int rA = row0 + wm * 32 + mf * 16 + gid;
            int rB = rA + 8;
            const float2* tA = g_ropetab + (size_t)rA * 32;
            const float2* tB = g_ropetab + (size_t)rB * 32;
#pragma unroll
            for (int nf = 0; nf < 2; ++nf) {
                int i0 = wn * 16 + nf * 8 + 2 * tig;
                float2 sA0 = tA[i0], sA1 = tA[i0 + 1];
                float2 sB0 = tB[i0], sB1 = tB[i0 + 1];
                float x1A0 = acc[mf][nf][0],     x1A1 = acc[mf][nf][1];
                float x1B0 = acc[mf][nf][2],     x1B1 = acc[mf][nf][3];
                float x2A0 = acc[mf][nf + 2][0], x2A1 = acc[mf][nf + 2][1];
                float x2B0 = acc[mf][nf + 2][2], x2B1 = acc[mf][nf + 2][3];
                float o1A0 = x1A0 * sA0.y - x2A0 * sA0.x;
                float o2A0 = x2A0 * sA0.y + x1A0 * sA0.x;
                float o1A1 = x1A1 * sA1.y - x2A1 * sA1.x;
                float o2A1 = x2A1 * sA1.y + x1A1 * sA1.x;
                float o1B0 = x1B0 * sB0.y - x2B0 * sB0.x;
                float o2B0 = x2B0 * sB0.y + x1B0 * sB0.x;
                float o1B1 = x1B1 * sB1.y - x2B1 * sB1.x;
                float o2B1 = x2B1 * sB1.y + x1B1 * sB1.x;
                int col = col0 + i0;
                __half* dA = Oh + (size_t)rA * HC + col;
                __half* dB = Oh + (size_t)rB * HC + col;
                *(__half2*)dA        = __floats2half2_rn(o1A0, o1A1);
                *(__half2*)(dA + 32) = __floats2half2_rn(o2A0, o2A1);
                *(__half2*)dB        = __floats2half2_rn(o1B0, o1B1);
                *(__half2*)(dB + 32) = __floats2half2_rn(o2B0, o2B1);
            }
        }
    } else {
#pragma unroll
        for (int mf = 0; mf < 2; ++mf)
#pragma unroll
            for (int nf = 0; nf < 4; ++nf) {
                int row = row0 + wm * 32 + mf * 16 + gid;
                int col = col0 + wn * 16 + (nf >> 1) * 32 + (nf & 1) * 8 + 2 * tig;
                int bz = row >> 10, n = row & 1023;
                int hh = col >> 6, cc = col & 63;
                __half* base = g_vt + ((size_t)(bz * Hh + hh) * Cc + cc) * Nn + n;
                base[0]      = __float2half(acc[mf][nf][0]);
                base[Nn]     = __float2half(acc[mf][nf][1]);
                base[8]      = __float2half(acc[mf][nf][2]);
                base[Nn + 8] = __float2half(acc[mf][nf][3]);
            }
    }
}

// ---------------- flash attention (HMMA) ------------------------------------
#define ATT_BUF  25600
#define ATT_SMEM (8192 + 2 * ATT_BUF)   // 59392

__global__ __launch_bounds__(256, 2) void attn_kernel(const int* __restrict__ seg,
                                                      float* __restrict__ out)
{
    extern __shared__ char sm[];
    __shared__ float smax[64][2];
    __shared__ float ssum[64][2];
    __shared__ int   seg_s[64];

    const int tid  = threadIdx.x;
    const int w    = tid >> 5, lane = tid & 31;
    const int gid  = lane >> 2, tig = lane & 3;
    const int wm   = w & 3, wn = w >> 2;
    const int lr   = lane & 15, lh = lane >> 4;
    const int qt   = gridDim.x - 1 - blockIdx.x;
    const int h    = blockIdx.y, b = blockIdx.z;
    const uint32_t smb = smem_u32(sm);

    const int* sb = seg + b * Nn;
    const int segA = sb[qt * 64];
    int kt_start = 0;
    while (kt_start < qt && sb[kt_start * 64 + 63] < segA) kt_start++;

    const int lrow = tid >> 2;
    const int cp0  = (tid & 3) * 2;

    {
        const __half* src = g_qh + (size_t)(b * Nn + qt * 64 + lrow) * HC + h * Cc + cp0 * 8;
        uint32_t qd = smb + (uint32_t)(lrow * 128);
        cp16(qd + (((cp0 + 0) ^ (lrow & 7)) << 4), src);
        cp16(qd + (((cp0 + 1) ^ (lrow & 7)) << 4), src + 8);
    }
    auto issue_tile = [&](int kt, int bf) {
        uint32_t base = smb + 8192u + (uint32_t)bf * ATT_BUF;
        const __half* ks = g_kh + (size_t)(b * Nn + kt * 64 + lrow) * HC + h * Cc + cp0 * 8;
        cp16(base + (uint32_t)(lrow * 128) + (((cp0 + 0) ^ (lrow & 7)) << 4), ks);
        cp16(base + (uint32_t)(lrow * 128) + (((cp0 + 1) ^ (lrow & 7)) << 4), ks + 8);
        const __half* vs = g_vt + ((size_t)(b * Hh + h) * Cc + lrow) * Nn + kt * 64 + cp0 * 8;
        cp16(base + 8192u + (uint32_t)(lrow * 128) + (((cp0 + 0) ^ (lrow & 7)) << 4), vs);
        cp16(base + 8192u + (uint32_t)(lrow * 128) + (((cp0 + 1) ^ (lrow & 7)) << 4), vs + 8);
        const __half* bs = g_biash + ((size_t)(b * Hh + h) * Nn + qt * 64 + lrow) * Nn + kt * 64 + cp0 * 8;
        cp16(base + 16384u + (uint32_t)(lrow * 144 + cp0 * 16), bs);
        cp16(base + 16384u + (uint32_t)(lrow * 144 + cp0 * 16 + 16), bs + 8);
    };

    issue_tile(kt_start, 0); cp_commit();
    if (kt_start + 1 <= qt) { issue_tile(kt_start + 1, 1); cp_commit(); }

    float Oacc[8][4];
#pragma unroll
    for (int nf = 0; nf < 8; nf++)
#pragma unroll
        for (int i = 0; i < 4; i++) Oacc[nf][i] = 0.f;

    const int r0l = wm * 16 + gid, r1l = r0l + 8;
    const int rowg0 = qt * 64 + r0l, rowg1 = qt * 64 + r1l;
    const int myseg0 = sb[rowg0], myseg1 = sb[rowg1];
    float m_run0 = -INFINITY, m_run1 = -INFINITY;
    float l_run0 = 0.f, l_run1 = 0.f;
    const float sc = 0.125f;

#pragma unroll 1
    for (int kt = kt_start; kt <= qt; kt++) {
        const int bf = (kt - kt_start) & 1;
        if (kt + 1 <= qt) asm volatile("cp.async.wait_group 1;" ::: "memory");
        else              asm volatile("cp.async.wait_group 0;" ::: "memory");
        if (tid < 64) seg_s[tid] = sb[kt * 64 + tid];
        __syncthreads();

        const uint32_t Kb = smb + 8192u + (uint32_t)bf * ATT_BUF;
        const uint32_t Vb = Kb + 8192u;
        const __half* biasb = (const __half*)(sm + 8192 + bf * ATT_BUF + 16384);

        // ---- S = Q K^T ----
        float Sa[4][4];
#pragma unroll
        for (int j = 0; j < 4; j++)
#pragma unroll
            for (int i = 0; i < 4; i++) Sa[j][i] = 0.f;

#pragma unroll
        for (int ks = 0; ks < 4; ks++) {
            uint32_t a[4];
            {
                int R = wm * 16 + lr, cb = 2 * ks + lh;
                ldmx4(a, smb + (uint32_t)(R * 128 + ((cb ^ (R & 7)) << 4)));
            }
#pragma unroll
            for (int np = 0; np < 2; np++) {
                uint32_t bk[4];
                int R = wn * 32 + np * 16 + lr, cb = 2 * ks + lh;
                ldmx4(bk, Kb + (uint32_t)(R * 128 + ((cb ^ (R & 7)) << 4)));
                MMA16816(Sa[2 * np + 0], a, bk[0], bk[2]);
                MMA16816(Sa[2 * np + 1], a, bk[1], bk[3]);
            }
        }

        // ---- bias + mask + scale, partial rowmax ----
        float mx0 = -INFINITY, mx1 = -INFINITY;
#pragma unroll
        for (int j = 0; j < 4; j++) {
            int keyl = wn * 32 + j * 8 + 2 * tig;
            int keyg = kt * 64 + keyl;
            float2 bf0 = __half22float2(*(const __half2*)&biasb[r0l * 72 + keyl]);
            float2 bf1 = __half22float2(*(const __half2*)&biasb[r1l * 72 + keyl]);
            int sg0 = seg_s[keyl], sg1 = seg_s[keyl + 1];
            bool ok00 = (keyg     <= rowg0) && (sg0 == myseg0);
            bool ok01 = (keyg + 1 <= rowg0) && (sg1 == myseg0);
            bool ok10 = (keyg     <= rowg1) && (sg0 == myseg1);
            bool ok11 = (keyg + 1 <= rowg1) && (sg1 == myseg1);
            Sa[j][0] = ok00 ? fmaf(Sa[j][0], sc, bf0.x) : -INFINITY;
            Sa[j][1] = ok01 ? fmaf(Sa[j][1], sc, bf0.y) : -INFINITY;
            Sa[j][2] = ok10 ? fmaf(Sa[j][2], sc, bf1.x) : -INFINITY;
            Sa[j][3] = ok11 ? fmaf(Sa[j][3], sc, bf1.y) : -INFINITY;
            mx0 = fmaxf(mx0, fmaxf(Sa[j][0], Sa[j][1]));
            mx1 = fmaxf(mx1, fmaxf(Sa[j][2], Sa[j][3]));
        }
        mx0 = fmaxf(mx0, __shfl_xor_sync(0xffffffffu, mx0, 1));
        mx0 = fmaxf(mx0, __shfl_xor_sync(0xffffffffu, mx0, 2));
        mx1 = fmaxf(mx1, __shfl_xor_sync(0xffffffffu, mx1, 1));
        mx1 = fmaxf(mx1, __shfl_xor_sync(0xffffffffu, mx1, 2));
        if (tig == 0) { smax[r0l][wn] = mx0; smax[r1l][wn] = mx1; }
        __syncthreads();

        float mt0 = fmaxf(smax[r0l][0], smax[r0l][1]);
        float mt1 = fmaxf(smax[r1l][0], smax[r1l][1]);
        float mn0 = fmaxf(m_run0, mt0), mn1 = fmaxf(m_run1, mt1);
        float mu0 = (mn0 == -INFINITY) ? 0.f : mn0;
        float mu1 = (mn1 == -INFINITY) ? 0.f : mn1;
        float al0 = __expf(m_run0 - mu0), al1 = __expf(m_run1 - mu1);

        float ps0 = 0.f, ps1 = 0.f;
        uint32_t pa[2][4];
#pragma unroll
        for (int jj = 0; jj < 2; jj++) {
            float p[2][4];
#pragma unroll
            for (int d = 0; d < 2; d++) {
                int j = 2 * jj + d;
                p[d][0] = __expf(Sa[j][0] - mu0);
                p[d][1] = __expf(Sa[j][1] - mu0);
                p[d][2] = __expf(Sa[j][2] - mu1);
                p[d][3] = __expf(Sa[j][3] - mu1);
                ps0 += p[d][0] + p[d][1];
                ps1 += p[d][2] + p[d][3];
            }
            __half2 h0  = __floats2half2_rn(p[0][0], p[0][1]);
            __half2 h1  = __floats2half2_rn(p[0][2], p[0][3]);
            __half2 h2v = __floats2half2_rn(p[1][0], p[1][1]);
            __half2 h3  = __floats2half2_rn(p[1][2], p[1][3]);
            pa[jj][0] = *(uint32_t*)&h0;
            pa[jj][1] = *(uint32_t*)&h1;
            pa[jj][2] = *(uint32_t*)&h2v;
            pa[jj][3] = *(uint32_t*)&h3;
        }
        ps0 += __shfl_xor_sync(0xffffffffu, ps0, 1);
        ps0 += __shfl_xor_sync(0xffffffffu, ps0, 2);
        ps1 += __shfl_xor_sync(0xffffffffu, ps1, 1);
        ps1 += __shfl_xor_sync(0xffffffffu, ps1, 2);
        if (tig == 0) { ssum[r0l][wn] = ps0; ssum[r1l][wn] = ps1; }

#pragma unroll
        for (int nf = 0; nf < 8; nf++) {
            Oacc[nf][0] *= al0; Oacc[nf][1] *= al0;
            Oacc[nf][2] *= al1; Oacc[nf][3] *= al1;
        }
        __syncthreads();
        l_run0 = l_run0 * al0 + ssum[r0l][0] + ssum[r0l][1];
        l_run1 = l_run1 * al1 + ssum[r1l][0] + ssum[r1l][1];
        m_run0 = mn0; m_run1 = mn1;

        // ---- O += P V ----
#pragma unroll
        for (int ks2 = 0; ks2 < 2; ks2++) {
#pragma unroll
            for (int np2 = 0; np2 < 4; np2++) {
                uint32_t bv[4];
                int R = np2 * 16 + lr, cb = wn * 4 + ks2 * 2 + lh;
                ldmx4(bv, Vb + (uint32_t)(R * 128 + ((cb ^ (R & 7)) << 4)));
                MMA16816(Oacc[2 * np2 + 0], pa[ks2], bv[0], bv[2]);
                MMA16816(Oacc[2 * np2 + 1], pa[ks2], bv[1], bv[3]);
            }
        }

        __syncthreads();
        if (kt + 2 <= qt) { issue_tile(kt + 2, bf); cp_commit(); }
    }

    // ---- epilogue: combine wn partials via smem ----
    float inv0 = 1.f / l_run0, inv1 = 1.f / l_run1;
    float* Osm = (float*)sm;   // [64][68]
    if (wn == 1) {
#pragma unroll
        for (int nf = 0; nf < 8; nf++) {
            int c = nf * 8 + 2 * tig;
            *(float2*)&Osm[r0l * 68 + c] = make_float2(Oacc[nf][0], Oacc[nf][1]);
            *(float2*)&Osm[r1l * 68 + c] = make_float2(Oacc[nf][2], Oacc[nf][3]);
        }
    }
    __syncthreads();
    if (wn == 0) {
#pragma unroll
        for (int nf = 0; nf < 8; nf++) {
            int c = nf * 8 + 2 * tig;
            float2 o0 = *(float2*)&Osm[r0l * 68 + c];
            float2 o1 = *(float2*)&Osm[r1l * 68 + c];
            float* d0 = out + (size_t)(b * Nn + rowg0) * HC + h * Cc + c;
            float* d1 = out + (size_t)(b * Nn + rowg1) * HC + h * Cc + c;
            *(float2*)d0 = make_float2((Oacc[nf][0] + o0.x) * inv0,
                                       (Oacc[nf][1] + o0.y) * inv0);
            *(float2*)d1 = make_float2((Oacc[nf][2] + o1.x) * inv1,
                                       (Oacc[nf][3] + o1.y) * inv1);
        }
    }
}

// ---------------------------------------------------------------------------
extern "C" void kernel_launch(void* const* d_in, const int* in_sizes, int n_in,
                              void* d_out, int out_size)
{
    const float* s    = (const float*)d_in[0];
    const float* pair = (const float*)d_in[1];
    const int*   seg  = (const int*)d_in[2];
    const int*   pos  = (const int*)d_in[3];
    const float* Wq   = (const float*)d_in[4];
    const float* Wk   = (const float*)d_in[5];
    const float* Wv   = (const float*)d_in[6];
    const float* Wb   = (const float*)d_in[7];
    float* out = (float*)d_out;

    cudaFuncSetAttribute(attn_kernel,
                         cudaFuncAttributeMaxDynamicSharedMemorySize, ATT_SMEM);

    ropetab_kernel<<<(Mrows * 32) / 256, 256>>>(pos);
    conv_s_kernel<<<(Mrows * FS) / 256, 256>>>(s);
    conv_w_kernel<<<dim3(HC / 32, FS / 32, 3), dim3(32, 8)>>>(Wq, Wk, Wv);
    // fused: qkv GEMM blocks + bias blocks in one launch (overlap)
    qkv_bias_kernel<<<QKV_BLOCKS + 16 * 256 * Bb, 256>>>(pair, Wb, seg);
    attn_kernel<<<dim3(Nn / 64, Hh, Bb), 256, ATT_SMEM>>>(seg, out);
}